// round 1
// baseline (speedup 1.0000x reference)
#include <cuda_runtime.h>
#include <math.h>

namespace {
constexpr int B  = 2;
constexpr int L  = 2048;
constexpr int D  = 2048;
constexpr int H  = 16;
constexpr int HD = 128;
constexpr int LD = 32;
constexpr int BL = B * L;                 // 4096
constexpr long long BLD = (long long)B * L * D;   // 8388608
constexpr int BHLLD = B * H * L * LD;     // 2097152
}

// ---------------- scratch (static device memory, no allocation) -------------
__device__ float g_q[B * L * D];     // (b,l,h,hd); reused for decompressed attn
__device__ float g_k[B * L * D];
__device__ float g_v[B * L * D];
__device__ float g_qc[BHLLD];        // (b,h,l,e)
__device__ float g_kc[BHLLD];
__device__ float g_vc[BHLLD];
__device__ float g_attn[BHLLD];      // (b,l,h,e)

// ---------------- big GEMM: C[M,N] = A[M,K] @ W[K,N] + bias[N] --------------
// 128x128 block tile, K-tile 16, 256 threads, 8x8 register micro-tile.
// Requires M%128==0, N%128==0, K%16==0 (holds: 4096/2048/2048).
__global__ void __launch_bounds__(256) gemm_bias_kernel(
    const float* __restrict__ A, const float* __restrict__ W,
    const float* __restrict__ bias, float* __restrict__ C,
    int M, int N, int K)
{
    __shared__ float As[16][128];   // k-major (transposed) -> float4 inner loads
    __shared__ float Bs[16][128];

    const int tid  = threadIdx.x;
    const int trow = (tid / 16) * 8;
    const int tcol = (tid % 16) * 8;
    const int m0   = blockIdx.y * 128;
    const int n0   = blockIdx.x * 128;

    const int ar = tid >> 2;          // 0..63   (A row within tile)
    const int ak = (tid & 3) * 4;     // 0,4,8,12
    const int br = tid >> 5;          // 0..7    (B k-row within tile)
    const int bc = (tid & 31) * 4;    // 0..124

    const float* Ap = A + (long long)m0 * K;
    const float* Wp = W + n0;

    float acc[8][8];
    #pragma unroll
    for (int i = 0; i < 8; i++)
        #pragma unroll
        for (int j = 0; j < 8; j++) acc[i][j] = 0.f;

    for (int k0 = 0; k0 < K; k0 += 16) {
        float4 a0 = *(const float4*)(Ap + (long long)ar * K + k0 + ak);
        float4 a1 = *(const float4*)(Ap + (long long)(ar + 64) * K + k0 + ak);
        float4 b0 = *(const float4*)(Wp + (long long)(k0 + br) * N + bc);
        float4 b1 = *(const float4*)(Wp + (long long)(k0 + br + 8) * N + bc);
        __syncthreads();
        As[ak + 0][ar]      = a0.x; As[ak + 1][ar]      = a0.y;
        As[ak + 2][ar]      = a0.z; As[ak + 3][ar]      = a0.w;
        As[ak + 0][ar + 64] = a1.x; As[ak + 1][ar + 64] = a1.y;
        As[ak + 2][ar + 64] = a1.z; As[ak + 3][ar + 64] = a1.w;
        *(float4*)&Bs[br][bc]     = b0;
        *(float4*)&Bs[br + 8][bc] = b1;
        __syncthreads();
        #pragma unroll
        for (int kk = 0; kk < 16; kk++) {
            float a[8], bb[8];
            *(float4*)&a[0]  = *(const float4*)&As[kk][trow];
            *(float4*)&a[4]  = *(const float4*)&As[kk][trow + 4];
            *(float4*)&bb[0] = *(const float4*)&Bs[kk][tcol];
            *(float4*)&bb[4] = *(const float4*)&Bs[kk][tcol + 4];
            #pragma unroll
            for (int i = 0; i < 8; i++)
                #pragma unroll
                for (int j = 0; j < 8; j++)
                    acc[i][j] += a[i] * bb[j];
        }
    }
    #pragma unroll
    for (int j = 0; j < 8; j++) {
        float bv = bias[n0 + tcol + j];
        #pragma unroll
        for (int i = 0; i < 8; i++) acc[i][j] += bv;
    }
    #pragma unroll
    for (int i = 0; i < 8; i++) {
        float* cp = C + (long long)(m0 + trow + i) * N + n0 + tcol;
        *(float4*)cp       = *(float4*)&acc[i][0];
        *(float4*)(cp + 4) = *(float4*)&acc[i][4];
    }
}

// ---------------- RoPE over q and k, layout (b,l,h,hd), interleaved pairs ---
__global__ void rope_kernel(float* __restrict__ q, float* __restrict__ k,
                            const float* __restrict__ cosT,
                            const float* __restrict__ sinT)
{
    constexpr int NP = B * L * H * (HD / 2);   // pair index
    int idx = blockIdx.x * blockDim.x + threadIdx.x;
    if (idx >= NP) return;
    // idx = ((b*L + l)*H + h)*64 + p  -> element offset = 2*idx
    int p = idx & 63;
    int l = ((idx >> 6) / H) % L;
    float c = cosT[l * 64 + p];
    float s = sinT[l * 64 + p];
    float2 qv = *(float2*)(q + 2 * (long long)idx);
    float2 kv = *(float2*)(k + 2 * (long long)idx);
    float2 qr = make_float2(qv.x * c - qv.y * s, qv.x * s + qv.y * c);
    float2 kr = make_float2(kv.x * c - kv.y * s, kv.x * s + kv.y * c);
    *(float2*)(q + 2 * (long long)idx) = qr;
    *(float2*)(k + 2 * (long long)idx) = kr;
}

// ---------------- compress: (b,l,h,:HD) @ Wc(HD,LD) + bc -> (b,h,l,:LD) -----
// block = 256 threads = 8 l-rows x 32 e; grid = (L/8, B*H)
__global__ void __launch_bounds__(256) compress_kernel(
    const float* __restrict__ X, const float* __restrict__ Wc,
    const float* __restrict__ bc, float* __restrict__ Xc)
{
    __shared__ float Ws[HD][LD];   // 16KB
    __shared__ float xs[8][HD];    // 4KB
    const int bh = blockIdx.y;
    const int b = bh / H, h = bh % H;
    const int l0 = blockIdx.x * 8;
    const int tid = threadIdx.x;
    for (int i = tid; i < HD * LD; i += 256) Ws[i / LD][i % LD] = Wc[i];
    for (int i = tid; i < 8 * HD; i += 256) {
        int li = i >> 7, d = i & 127;
        xs[li][d] = X[((long long)((b * L + l0 + li) * H + h)) * HD + d];
    }
    __syncthreads();
    const int li = tid >> 5, e = tid & 31;
    float acc = bc[e];
    #pragma unroll
    for (int d = 0; d < HD; d++) acc += xs[li][d] * Ws[d][e];
    Xc[((long long)bh * L + l0 + li) * LD + e] = acc;
}

// ---------------- causal flash attention in compressed space ----------------
// qc/kc/vc: (b,h,l,32). One warp per query row; block = 4 warps sharing key
// tiles in shared. Output attn: (b,l,h,32).
__global__ void __launch_bounds__(128) attn_kernel(
    const float* __restrict__ qc, const float* __restrict__ kc,
    const float* __restrict__ vc, float* __restrict__ attn)
{
    __shared__ float ks[32][33];
    __shared__ float vs[32][33];
    __shared__ float qs[4][32];
    constexpr float SCALE = 0.17677669529663687f;  // 1/sqrt(32)

    const int bh  = blockIdx.y;
    const int q0  = blockIdx.x * 4;
    const int tid = threadIdx.x;
    const int w = tid >> 5, lane = tid & 31;
    const int q = q0 + w;

    const float* bk = kc + (long long)bh * L * LD;
    const float* bv = vc + (long long)bh * L * LD;

    qs[w][lane] = qc[((long long)bh * L + q) * LD + lane];

    float m = -INFINITY, lsum = 0.f, acc = 0.f;
    const int ntiles = (q0 + 3) / 32 + 1;   // uniform for all 4 warps (4 | 32)

    for (int t = 0; t < ntiles; t++) {
        __syncthreads();   // protect prev-iter reads (and initial qs store)
        for (int i = tid; i < 32 * 32; i += 128) {
            int r = i >> 5, c = i & 31;
            ks[r][c] = bk[((long long)(t * 32 + r)) * LD + c];
            vs[r][c] = bv[((long long)(t * 32 + r)) * LD + c];
        }
        __syncthreads();

        const int key = t * 32 + lane;
        float s = 0.f;
        #pragma unroll
        for (int e = 0; e < 32; e++) s += qs[w][e] * ks[lane][e];
        s = (key <= q) ? s * SCALE : -INFINITY;

        float tm = s;
        #pragma unroll
        for (int off = 16; off; off >>= 1)
            tm = fmaxf(tm, __shfl_xor_sync(0xffffffffu, tm, off));
        const float mnew  = fmaxf(m, tm);
        const float alpha = __expf(m - mnew);     // m=-inf -> 0; masked tile -> 1
        const float p     = __expf(s - mnew);     // masked lane -> 0

        float psum = p;
        #pragma unroll
        for (int off = 16; off; off >>= 1)
            psum += __shfl_xor_sync(0xffffffffu, psum, off);
        lsum = lsum * alpha + psum;

        acc *= alpha;
        #pragma unroll
        for (int j = 0; j < 32; j++) {
            float pj = __shfl_sync(0xffffffffu, p, j);
            acc += pj * vs[j][lane];
        }
        m = mnew;
    }

    const int b = bh / H, h = bh % H;
    attn[((long long)(b * L + q) * H + h) * LD + lane] = acc / lsum;
}

// ---------------- decompress: rows(b,l,h) x LD @ Wd(LD,HD) + bd -> (b,l,D) --
// block = 256 threads, 8 rows x 128 cols; grid = (B*L*H)/8
__global__ void __launch_bounds__(256) decompress_kernel(
    const float* __restrict__ Ac, const float* __restrict__ Wd,
    const float* __restrict__ bd, float* __restrict__ Out)
{
    __shared__ float Ws[LD][HD];   // 16KB
    __shared__ float as[8][LD];
    const int r0 = blockIdx.x * 8;
    const int tid = threadIdx.x;
    for (int i = tid; i < LD * HD; i += 256) Ws[i / HD][i % HD] = Wd[i];
    for (int i = tid; i < 8 * LD; i += 256)
        as[i >> 5][i & 31] = Ac[(long long)(r0 + (i >> 5)) * LD + (i & 31)];
    __syncthreads();
    const int c  = tid & 127;
    const int rb = tid >> 7;
    const float bvv = bd[c];
    #pragma unroll
    for (int rr = rb; rr < 8; rr += 2) {
        float acc = bvv;
        #pragma unroll
        for (int e = 0; e < LD; e++) acc += as[rr][e] * Ws[e][c];
        Out[(long long)(r0 + rr) * HD + c] = acc;
    }
}

// ---------------------------------------------------------------------------
extern "C" void kernel_launch(void* const* d_in, const int* in_sizes, int n_in,
                              void* d_out, int out_size)
{
    const float* x    = (const float*)d_in[0];
    const float* cosT = (const float*)d_in[1];
    const float* sinT = (const float*)d_in[2];
    const float* Wq   = (const float*)d_in[3];
    const float* bq   = (const float*)d_in[4];
    const float* Wk   = (const float*)d_in[5];
    const float* bk   = (const float*)d_in[6];
    const float* Wv   = (const float*)d_in[7];
    const float* bv   = (const float*)d_in[8];
    const float* Wqc  = (const float*)d_in[9];
    const float* bqc  = (const float*)d_in[10];
    const float* Wkc  = (const float*)d_in[11];
    const float* bkc  = (const float*)d_in[12];
    const float* Wvc  = (const float*)d_in[13];
    const float* bvc  = (const float*)d_in[14];
    const float* Wd   = (const float*)d_in[15];
    const float* bd   = (const float*)d_in[16];
    const float* Wo   = (const float*)d_in[17];
    const float* bo   = (const float*)d_in[18];
    float* out = (float*)d_out;

    float *q, *k, *v, *qc, *kc, *vc, *attn;
    cudaGetSymbolAddress((void**)&q,    g_q);
    cudaGetSymbolAddress((void**)&k,    g_k);
    cudaGetSymbolAddress((void**)&v,    g_v);
    cudaGetSymbolAddress((void**)&qc,   g_qc);
    cudaGetSymbolAddress((void**)&kc,   g_kc);
    cudaGetSymbolAddress((void**)&vc,   g_vc);
    cudaGetSymbolAddress((void**)&attn, g_attn);

    dim3 ggrid(D / 128, BL / 128);   // (16, 32)
    gemm_bias_kernel<<<ggrid, 256>>>(x, Wq, bq, q, BL, D, D);
    gemm_bias_kernel<<<ggrid, 256>>>(x, Wk, bk, k, BL, D, D);
    gemm_bias_kernel<<<ggrid, 256>>>(x, Wv, bv, v, BL, D, D);

    const int npairs = B * L * H * (HD / 2);
    rope_kernel<<<(npairs + 255) / 256, 256>>>(q, k, cosT, sinT);

    dim3 cgrid(L / 8, B * H);
    compress_kernel<<<cgrid, 256>>>(q, Wqc, bqc, qc);
    compress_kernel<<<cgrid, 256>>>(k, Wkc, bkc, kc);
    compress_kernel<<<cgrid, 256>>>(v, Wvc, bvc, vc);

    dim3 agrid(L / 4, B * H);
    attn_kernel<<<agrid, 128>>>(qc, kc, vc, attn);

    decompress_kernel<<<(B * L * H) / 8, 256>>>(attn, Wd, bd, q /* reuse */);

    gemm_bias_kernel<<<ggrid, 256>>>(q, Wo, bo, out, BL, D, D);
}

// round 4
// speedup vs baseline: 1.6880x; 1.6880x over previous
#include <cuda_runtime.h>
#include <cuda_bf16.h>
#include <math.h>
#include <cstdint>

namespace {
constexpr int B  = 2;
constexpr int L  = 2048;
constexpr int D  = 2048;
constexpr int H  = 16;
constexpr int HD = 128;
constexpr int LD = 32;
constexpr int BL = B * L;                 // 4096
constexpr int BHLLD = B * H * L * LD;     // 2097152

constexpr int GM = BL;    // 4096
constexpr int GN = D;     // 2048
constexpr int GK = D;     // 2048

// HMMA GEMM tiling
constexpr int BK     = 32;                 // k elements per stage
constexpr int STAGES = 3;
constexpr int NIT    = GK / BK;            // 64
constexpr int ROWB   = 80;                 // smem row stride bytes (32*2 + 16 pad)
constexpr int TILEB  = 128 * ROWB;         // 10240 per operand tile
constexpr int OFF_AH = 0;
constexpr int OFF_AL = TILEB;
constexpr int OFF_BH = 2 * TILEB;
constexpr int OFF_BL = 3 * TILEB;
constexpr int STAGEB = 4 * TILEB;          // 40960
constexpr int SMEMB  = STAGES * STAGEB;    // 122880
}

// ---------------- scratch (static device memory, no allocation) -------------
__device__ float g_q[B * L * D];
__device__ float g_k[B * L * D];
__device__ float g_v[B * L * D];
__device__ float g_qc[BHLLD];
__device__ float g_kc[BHLLD];
__device__ float g_vc[BHLLD];
__device__ float g_attn[BHLLD];
__device__ __nv_bfloat16 g_ahi[GM * GK];   // A split, [M,K]
__device__ __nv_bfloat16 g_alo[GM * GK];
__device__ __nv_bfloat16 g_whi[GK * GN];   // W split, TRANSPOSED [N,K]
__device__ __nv_bfloat16 g_wlo[GK * GN];

// ================= PTX helpers (base sm_10x target: HMMA path) ==============
__device__ __forceinline__ uint32_t smem_u32(const void* p) {
    uint32_t a;
    asm("{ .reg .u64 t; cvta.to.shared.u64 t, %1; cvt.u32.u64 %0, t; }"
        : "=r"(a) : "l"(p));
    return a;
}
__device__ __forceinline__ void cp_async16(uint32_t dst, const void* src) {
    asm volatile("cp.async.cg.shared.global [%0], [%1], 16;"
                 :: "r"(dst), "l"(src) : "memory");
}
__device__ __forceinline__ void cp_commit() {
    asm volatile("cp.async.commit_group;" ::: "memory");
}
template <int N>
__device__ __forceinline__ void cp_wait() {
    asm volatile("cp.async.wait_group %0;" :: "n"(N) : "memory");
}
__device__ __forceinline__ void ldsm4(uint32_t* r, uint32_t addr) {
    asm volatile("ldmatrix.sync.aligned.m8n8.x4.shared.b16 {%0,%1,%2,%3}, [%4];"
                 : "=r"(r[0]), "=r"(r[1]), "=r"(r[2]), "=r"(r[3]) : "r"(addr));
}
__device__ __forceinline__ void mma16816(float* d, const uint32_t* a,
                                         uint32_t b0, uint32_t b1) {
    asm volatile(
        "mma.sync.aligned.m16n8k16.row.col.f32.bf16.bf16.f32 "
        "{%0,%1,%2,%3}, {%4,%5,%6,%7}, {%8,%9}, {%0,%1,%2,%3};"
        : "+f"(d[0]), "+f"(d[1]), "+f"(d[2]), "+f"(d[3])
        : "r"(a[0]), "r"(a[1]), "r"(a[2]), "r"(a[3]), "r"(b0), "r"(b1));
}

// ================= conversion kernels =======================================
__global__ void __launch_bounds__(256) convert_a_kernel(
    const float* __restrict__ X, __nv_bfloat16* __restrict__ hi,
    __nv_bfloat16* __restrict__ lo)
{
    long long i = ((long long)blockIdx.x * 256 + threadIdx.x) * 4;
    float4 v = *(const float4*)(X + i);
    __nv_bfloat16 h0 = __float2bfloat16(v.x);
    __nv_bfloat16 h1 = __float2bfloat16(v.y);
    __nv_bfloat16 h2 = __float2bfloat16(v.z);
    __nv_bfloat16 h3 = __float2bfloat16(v.w);
    __nv_bfloat16 l0 = __float2bfloat16(v.x - __bfloat162float(h0));
    __nv_bfloat16 l1 = __float2bfloat16(v.y - __bfloat162float(h1));
    __nv_bfloat16 l2 = __float2bfloat16(v.z - __bfloat162float(h2));
    __nv_bfloat16 l3 = __float2bfloat16(v.w - __bfloat162float(h3));
    *(__nv_bfloat162*)(hi + i)     = __nv_bfloat162(h0, h1);
    *(__nv_bfloat162*)(hi + i + 2) = __nv_bfloat162(h2, h3);
    *(__nv_bfloat162*)(lo + i)     = __nv_bfloat162(l0, l1);
    *(__nv_bfloat162*)(lo + i + 2) = __nv_bfloat162(l2, l3);
}

// W [K,N] fp32 -> transposed [N,K] bf16 hi/lo. block (32,8), grid (N/32, K/32)
__global__ void __launch_bounds__(256) convert_wT_kernel(
    const float* __restrict__ W, __nv_bfloat16* __restrict__ hi,
    __nv_bfloat16* __restrict__ lo)
{
    __shared__ float t[32][33];
    const int n0 = blockIdx.x * 32, k0 = blockIdx.y * 32;
    const int tx = threadIdx.x, ty = threadIdx.y;
    #pragma unroll
    for (int r = ty; r < 32; r += 8)
        t[r][tx] = W[(size_t)(k0 + r) * GN + n0 + tx];
    __syncthreads();
    #pragma unroll
    for (int r = ty; r < 32; r += 8) {
        float v = t[tx][r];            // = W[k0+tx][n0+r]
        __nv_bfloat16 h = __float2bfloat16(v);
        __nv_bfloat16 l = __float2bfloat16(v - __bfloat162float(h));
        hi[(size_t)(n0 + r) * GK + k0 + tx] = h;
        lo[(size_t)(n0 + r) * GK + k0 + tx] = l;
    }
}

// ================= HMMA bf16x3 GEMM =========================================
// C[GM,GN] = (Ahi+Alo)[M,K] @ (Bhi+Blo)[N,K]^T + bias.
// 128x128 CTA tile, 8 warps of 32x64, BK=32, 3-stage cp.async pipeline.
__device__ __forceinline__ void load_stage(
    uint32_t sbase, const __nv_bfloat16* pAh, const __nv_bfloat16* pAl,
    const __nv_bfloat16* pBh, const __nv_bfloat16* pBl, int kc, int tid)
{
    #pragma unroll
    for (int j = 0; j < 2; j++) {
        const int idx = tid + j * 256;
        const int row = idx >> 2, seg = idx & 3;
        const size_t go = (size_t)row * GK + kc + seg * 8;
        const uint32_t so = row * ROWB + seg * 16;
        cp_async16(sbase + OFF_AH + so, pAh + go);
        cp_async16(sbase + OFF_AL + so, pAl + go);
        cp_async16(sbase + OFF_BH + so, pBh + go);
        cp_async16(sbase + OFF_BL + so, pBl + go);
    }
}

__global__ void __launch_bounds__(256) hmma_gemm_kernel(
    const __nv_bfloat16* __restrict__ Ahi, const __nv_bfloat16* __restrict__ Alo,
    const __nv_bfloat16* __restrict__ Bhi, const __nv_bfloat16* __restrict__ Blo,
    const float* __restrict__ bias, float* __restrict__ C)
{
    extern __shared__ char smem[];
    const uint32_t sb0 = smem_u32(smem);
    const int tid = threadIdx.x, wid = tid >> 5, lane = tid & 31;
    const int warp_m = (wid & 3) * 32;      // 4 warps along M
    const int warp_n = (wid >> 2) * 64;     // 2 warps along N
    const int m0 = blockIdx.y * 128, n0 = blockIdx.x * 128;

    const __nv_bfloat16* pAh = Ahi + (size_t)m0 * GK;
    const __nv_bfloat16* pAl = Alo + (size_t)m0 * GK;
    const __nv_bfloat16* pBh = Bhi + (size_t)n0 * GK;
    const __nv_bfloat16* pBl = Blo + (size_t)n0 * GK;

    float acc[2][8][4];
    #pragma unroll
    for (int i = 0; i < 2; i++)
        #pragma unroll
        for (int j = 0; j < 8; j++)
            #pragma unroll
            for (int t = 0; t < 4; t++) acc[i][j][t] = 0.f;

    // ldmatrix per-lane offsets
    const int arow = ((lane >> 3) & 1) * 8 + (lane & 7);
    const int acol = (lane >> 4) * 16;
    const int brow = (lane >> 4) * 8 + (lane & 7);
    const int bcol = ((lane >> 3) & 1) * 16;

    load_stage(sb0, pAh, pAl, pBh, pBl, 0, tid);
    cp_commit();
    load_stage(sb0 + STAGEB, pAh, pAl, pBh, pBl, BK, tid);
    cp_commit();

    #pragma unroll 1
    for (int kt = 0; kt < NIT; kt++) {
        cp_wait<1>();
        __syncthreads();
        if (kt + 2 < NIT)
            load_stage(sb0 + ((kt + 2) % STAGES) * STAGEB,
                       pAh, pAl, pBh, pBl, (kt + 2) * BK, tid);
        cp_commit();

        const uint32_t sb = sb0 + (kt % STAGES) * STAGEB;
        #pragma unroll
        for (int ks = 0; ks < 2; ks++) {
            uint32_t ah[2][4], al[2][4];
            #pragma unroll
            for (int mt = 0; mt < 2; mt++) {
                uint32_t addr = sb + OFF_AH +
                    (warp_m + mt * 16 + arow) * ROWB + ks * 32 + acol;
                ldsm4(ah[mt], addr);
                ldsm4(al[mt], addr + TILEB);   // OFF_AL
            }
            uint32_t bh[4][4], bl[4][4];
            #pragma unroll
            for (int np = 0; np < 4; np++) {
                uint32_t addr = sb + OFF_BH +
                    (warp_n + np * 16 + brow) * ROWB + ks * 32 + bcol;
                ldsm4(bh[np], addr);
                ldsm4(bl[np], addr + TILEB);   // OFF_BL
            }
            #pragma unroll
            for (int mt = 0; mt < 2; mt++)
                #pragma unroll
                for (int nt = 0; nt < 8; nt++) {
                    const int np = nt >> 1, pp = (nt & 1) * 2;
                    mma16816(acc[mt][nt], ah[mt], bh[np][pp], bh[np][pp + 1]);
                    mma16816(acc[mt][nt], ah[mt], bl[np][pp], bl[np][pp + 1]);
                    mma16816(acc[mt][nt], al[mt], bh[np][pp], bh[np][pp + 1]);
                }
        }
    }

    // epilogue: d0,d1 at (r, c..c+1), d2,d3 at (r+8, c..c+1)
    #pragma unroll
    for (int mt = 0; mt < 2; mt++) {
        const int row = m0 + warp_m + mt * 16 + (lane >> 2);
        #pragma unroll
        for (int nt = 0; nt < 8; nt++) {
            const int col = n0 + warp_n + nt * 8 + (lane & 3) * 2;
            const float b0 = bias[col], b1 = bias[col + 1];
            float2 lo = make_float2(acc[mt][nt][0] + b0, acc[mt][nt][1] + b1);
            float2 hi = make_float2(acc[mt][nt][2] + b0, acc[mt][nt][3] + b1);
            *(float2*)(C + (size_t)row * GN + col)       = lo;
            *(float2*)(C + (size_t)(row + 8) * GN + col) = hi;
        }
    }
}

// ---------------- RoPE over q and k, layout (b,l,h,hd), interleaved pairs ---
__global__ void rope_kernel(float* __restrict__ q, float* __restrict__ k,
                            const float* __restrict__ cosT,
                            const float* __restrict__ sinT)
{
    constexpr int NP = B * L * H * (HD / 2);
    int idx = blockIdx.x * blockDim.x + threadIdx.x;
    if (idx >= NP) return;
    int p = idx & 63;
    int l = ((idx >> 6) / H) % L;
    float c = cosT[l * 64 + p];
    float s = sinT[l * 64 + p];
    float2 qv = *(float2*)(q + 2 * (long long)idx);
    float2 kv = *(float2*)(k + 2 * (long long)idx);
    float2 qr = make_float2(qv.x * c - qv.y * s, qv.x * s + qv.y * c);
    float2 kr = make_float2(kv.x * c - kv.y * s, kv.x * s + kv.y * c);
    *(float2*)(q + 2 * (long long)idx) = qr;
    *(float2*)(k + 2 * (long long)idx) = kr;
}

// ---------------- compress: (b,l,h,:HD) @ Wc(HD,LD) + bc -> (b,h,l,:LD) -----
__global__ void __launch_bounds__(256) compress_kernel(
    const float* __restrict__ X, const float* __restrict__ Wc,
    const float* __restrict__ bc, float* __restrict__ Xc)
{
    __shared__ float Ws[HD][LD];
    __shared__ float xs[8][HD];
    const int bh = blockIdx.y;
    const int b = bh / H, h = bh % H;
    const int l0 = blockIdx.x * 8;
    const int tid = threadIdx.x;
    for (int i = tid; i < HD * LD; i += 256) Ws[i / LD][i % LD] = Wc[i];
    for (int i = tid; i < 8 * HD; i += 256) {
        int li = i >> 7, d = i & 127;
        xs[li][d] = X[((long long)((b * L + l0 + li) * H + h)) * HD + d];
    }
    __syncthreads();
    const int li = tid >> 5, e = tid & 31;
    float acc = bc[e];
    #pragma unroll
    for (int d = 0; d < HD; d++) acc += xs[li][d] * Ws[d][e];
    Xc[((long long)bh * L + l0 + li) * LD + e] = acc;
}

// ---------------- causal flash attention in compressed space ----------------
__global__ void __launch_bounds__(128) attn_kernel(
    const float* __restrict__ qc, const float* __restrict__ kc,
    const float* __restrict__ vc, float* __restrict__ attn)
{
    __shared__ float ks[32][33];
    __shared__ float vs[32][33];
    __shared__ float qs[4][32];
    constexpr float SCALE = 0.17677669529663687f;  // 1/sqrt(32)

    const int bh  = blockIdx.y;
    const int q0  = blockIdx.x * 4;
    const int tid = threadIdx.x;
    const int w = tid >> 5, lane = tid & 31;
    const int q = q0 + w;

    const float* bk = kc + (long long)bh * L * LD;
    const float* bv = vc + (long long)bh * L * LD;

    qs[w][lane] = qc[((long long)bh * L + q) * LD + lane];

    float m = -INFINITY, lsum = 0.f, acc = 0.f;
    const int ntiles = (q0 + 3) / 32 + 1;

    for (int t = 0; t < ntiles; t++) {
        __syncthreads();
        for (int i = tid; i < 32 * 32; i += 128) {
            int r = i >> 5, c = i & 31;
            ks[r][c] = bk[((long long)(t * 32 + r)) * LD + c];
            vs[r][c] = bv[((long long)(t * 32 + r)) * LD + c];
        }
        __syncthreads();

        const int key = t * 32 + lane;
        float s = 0.f;
        #pragma unroll
        for (int e = 0; e < 32; e++) s += qs[w][e] * ks[lane][e];
        s = (key <= q) ? s * SCALE : -INFINITY;

        float tm = s;
        #pragma unroll
        for (int off = 16; off; off >>= 1)
            tm = fmaxf(tm, __shfl_xor_sync(0xffffffffu, tm, off));
        const float mnew  = fmaxf(m, tm);
        const float alpha = __expf(m - mnew);
        const float p     = __expf(s - mnew);

        float psum = p;
        #pragma unroll
        for (int off = 16; off; off >>= 1)
            psum += __shfl_xor_sync(0xffffffffu, psum, off);
        lsum = lsum * alpha + psum;

        acc *= alpha;
        #pragma unroll
        for (int j = 0; j < 32; j++) {
            float pj = __shfl_sync(0xffffffffu, p, j);
            acc += pj * vs[j][lane];
        }
        m = mnew;
    }

    const int b = bh / H, h = bh % H;
    attn[((long long)(b * L + q) * H + h) * LD + lane] = acc / lsum;
}

// ---------------- decompress: rows(b,l,h) x LD @ Wd(LD,HD) + bd -> (b,l,D) --
__global__ void __launch_bounds__(256) decompress_kernel(
    const float* __restrict__ Ac, const float* __restrict__ Wd,
    const float* __restrict__ bd, float* __restrict__ Out)
{
    __shared__ float Ws[LD][HD];
    __shared__ float as[8][LD];
    const int r0 = blockIdx.x * 8;
    const int tid = threadIdx.x;
    for (int i = tid; i < LD * HD; i += 256) Ws[i / HD][i % HD] = Wd[i];
    for (int i = tid; i < 8 * LD; i += 256)
        as[i >> 5][i & 31] = Ac[(long long)(r0 + (i >> 5)) * LD + (i & 31)];
    __syncthreads();
    const int c  = tid & 127;
    const int rb = tid >> 7;
    const float bvv = bd[c];
    #pragma unroll
    for (int rr = rb; rr < 8; rr += 2) {
        float acc = bvv;
        #pragma unroll
        for (int e = 0; e < LD; e++) acc += as[rr][e] * Ws[e][c];
        Out[(long long)(r0 + rr) * HD + c] = acc;
    }
}

// ---------------------------------------------------------------------------
extern "C" void kernel_launch(void* const* d_in, const int* in_sizes, int n_in,
                              void* d_out, int out_size)
{
    const float* x    = (const float*)d_in[0];
    const float* cosT = (const float*)d_in[1];
    const float* sinT = (const float*)d_in[2];
    const float* Wq   = (const float*)d_in[3];
    const float* bq   = (const float*)d_in[4];
    const float* Wk   = (const float*)d_in[5];
    const float* bk   = (const float*)d_in[6];
    const float* Wv   = (const float*)d_in[7];
    const float* bv   = (const float*)d_in[8];
    const float* Wqc  = (const float*)d_in[9];
    const float* bqc  = (const float*)d_in[10];
    const float* Wkc  = (const float*)d_in[11];
    const float* bkc  = (const float*)d_in[12];
    const float* Wvc  = (const float*)d_in[13];
    const float* bvc  = (const float*)d_in[14];
    const float* Wd   = (const float*)d_in[15];
    const float* bd   = (const float*)d_in[16];
    const float* Wo   = (const float*)d_in[17];
    const float* bo   = (const float*)d_in[18];
    float* out = (float*)d_out;

    float *q, *k, *v, *qc, *kc, *vc, *attn;
    __nv_bfloat16 *ahi, *alo, *whi, *wlo;
    cudaGetSymbolAddress((void**)&q,    g_q);
    cudaGetSymbolAddress((void**)&k,    g_k);
    cudaGetSymbolAddress((void**)&v,    g_v);
    cudaGetSymbolAddress((void**)&qc,   g_qc);
    cudaGetSymbolAddress((void**)&kc,   g_kc);
    cudaGetSymbolAddress((void**)&vc,   g_vc);
    cudaGetSymbolAddress((void**)&attn, g_attn);
    cudaGetSymbolAddress((void**)&ahi,  g_ahi);
    cudaGetSymbolAddress((void**)&alo,  g_alo);
    cudaGetSymbolAddress((void**)&whi,  g_whi);
    cudaGetSymbolAddress((void**)&wlo,  g_wlo);

    cudaFuncSetAttribute(hmma_gemm_kernel,
                         cudaFuncAttributeMaxDynamicSharedMemorySize, SMEMB);

    const int conv_a_blocks = (GM * GK / 4) / 256;       // 8192
    dim3 wgrid(GN / 32, GK / 32);                        // (64,64)
    dim3 wblk(32, 8);
    dim3 ggrid(GN / 128, GM / 128);                      // (16, 32)

    // --- Q/K/V projections on tensor cores (bf16x3 HMMA) ---
    convert_a_kernel<<<conv_a_blocks, 256>>>(x, ahi, alo);
    convert_wT_kernel<<<wgrid, wblk>>>(Wq, whi, wlo);
    hmma_gemm_kernel<<<ggrid, 256, SMEMB>>>(ahi, alo, whi, wlo, bq, q);
    convert_wT_kernel<<<wgrid, wblk>>>(Wk, whi, wlo);
    hmma_gemm_kernel<<<ggrid, 256, SMEMB>>>(ahi, alo, whi, wlo, bk, k);
    convert_wT_kernel<<<wgrid, wblk>>>(Wv, whi, wlo);
    hmma_gemm_kernel<<<ggrid, 256, SMEMB>>>(ahi, alo, whi, wlo, bv, v);

    const int npairs = B * L * H * (HD / 2);
    rope_kernel<<<(npairs + 255) / 256, 256>>>(q, k, cosT, sinT);

    dim3 cgrid(L / 8, B * H);
    compress_kernel<<<cgrid, 256>>>(q, Wqc, bqc, qc);
    compress_kernel<<<cgrid, 256>>>(k, Wkc, bkc, kc);
    compress_kernel<<<cgrid, 256>>>(v, Wvc, bvc, vc);

    dim3 agrid(L / 4, B * H);
    attn_kernel<<<agrid, 128>>>(qc, kc, vc, attn);

    decompress_kernel<<<(B * L * H) / 8, 256>>>(attn, Wd, bd, q /* reuse */);

    // --- output projection ---
    convert_a_kernel<<<conv_a_blocks, 256>>>(q, ahi, alo);
    convert_wT_kernel<<<wgrid, wblk>>>(Wo, whi, wlo);
    hmma_gemm_kernel<<<ggrid, 256, SMEMB>>>(ahi, alo, whi, wlo, bo, out);
}

// round 5
// speedup vs baseline: 1.9708x; 1.1675x over previous
#include <cuda_runtime.h>
#include <cuda_bf16.h>
#include <math.h>
#include <cstdint>

namespace {
constexpr int B  = 2;
constexpr int L  = 2048;
constexpr int D  = 2048;
constexpr int H  = 16;
constexpr int HD = 128;
constexpr int LD = 32;
constexpr int BL = B * L;                 // 4096
constexpr int BHLLD = B * H * L * LD;     // 2097152

constexpr int GM = BL;    // 4096
constexpr int GN = D;     // 2048
constexpr int GK = D;     // 2048

// HMMA GEMM tiling: CTA 256x128, 8 warps of 64x64, BK=32, 3 stages
constexpr int BK     = 32;
constexpr int STAGES = 3;
constexpr int NIT    = GK / BK;            // 64
constexpr int ROWB   = 80;                 // smem row stride bytes (64B + 16 pad)
constexpr int OFF_B  = 512 * ROWB;         // B rows start after 512 A rows
constexpr int STAGEB = 768 * ROWB;         // 61440 per stage
constexpr int SMEMB  = STAGES * STAGEB;    // 184320
}

// ---------------- scratch (static device memory, no allocation) -------------
__device__ float g_q[B * L * D];
__device__ float g_k[B * L * D];
__device__ float g_v[B * L * D];
__device__ float g_qc[BHLLD];
__device__ float g_kc[BHLLD];
__device__ float g_vc[BHLLD];
__device__ float g_attn[BHLLD];
__device__ __nv_bfloat16 g_ahi[GM * GK];   // A split, [M,K]
__device__ __nv_bfloat16 g_alo[GM * GK];
__device__ __nv_bfloat16 g_whi[GK * GN];   // W split, TRANSPOSED [N,K]
__device__ __nv_bfloat16 g_wlo[GK * GN];

// ================= PTX helpers ==============================================
__device__ __forceinline__ uint32_t smem_u32(const void* p) {
    uint32_t a;
    asm("{ .reg .u64 t; cvta.to.shared.u64 t, %1; cvt.u32.u64 %0, t; }"
        : "=r"(a) : "l"(p));
    return a;
}
__device__ __forceinline__ void cp_async16(uint32_t dst, const void* src) {
    asm volatile("cp.async.cg.shared.global [%0], [%1], 16;"
                 :: "r"(dst), "l"(src) : "memory");
}
__device__ __forceinline__ void cp_commit() {
    asm volatile("cp.async.commit_group;" ::: "memory");
}
template <int N>
__device__ __forceinline__ void cp_wait() {
    asm volatile("cp.async.wait_group %0;" :: "n"(N) : "memory");
}
__device__ __forceinline__ void ldsm4(uint32_t* r, uint32_t addr) {
    asm volatile("ldmatrix.sync.aligned.m8n8.x4.shared.b16 {%0,%1,%2,%3}, [%4];"
                 : "=r"(r[0]), "=r"(r[1]), "=r"(r[2]), "=r"(r[3]) : "r"(addr));
}
__device__ __forceinline__ void mma16816(float* d, const uint32_t* a,
                                         uint32_t b0, uint32_t b1) {
    asm volatile(
        "mma.sync.aligned.m16n8k16.row.col.f32.bf16.bf16.f32 "
        "{%0,%1,%2,%3}, {%4,%5,%6,%7}, {%8,%9}, {%0,%1,%2,%3};"
        : "+f"(d[0]), "+f"(d[1]), "+f"(d[2]), "+f"(d[3])
        : "r"(a[0]), "r"(a[1]), "r"(a[2]), "r"(a[3]), "r"(b0), "r"(b1));
}

// ================= conversion kernels =======================================
__global__ void __launch_bounds__(256) convert_a_kernel(
    const float* __restrict__ X, __nv_bfloat16* __restrict__ hi,
    __nv_bfloat16* __restrict__ lo)
{
    long long i = ((long long)blockIdx.x * 256 + threadIdx.x) * 4;
    float4 v = *(const float4*)(X + i);
    __nv_bfloat16 h0 = __float2bfloat16(v.x);
    __nv_bfloat16 h1 = __float2bfloat16(v.y);
    __nv_bfloat16 h2 = __float2bfloat16(v.z);
    __nv_bfloat16 h3 = __float2bfloat16(v.w);
    __nv_bfloat16 l0 = __float2bfloat16(v.x - __bfloat162float(h0));
    __nv_bfloat16 l1 = __float2bfloat16(v.y - __bfloat162float(h1));
    __nv_bfloat16 l2 = __float2bfloat16(v.z - __bfloat162float(h2));
    __nv_bfloat16 l3 = __float2bfloat16(v.w - __bfloat162float(h3));
    *(__nv_bfloat162*)(hi + i)     = __nv_bfloat162(h0, h1);
    *(__nv_bfloat162*)(hi + i + 2) = __nv_bfloat162(h2, h3);
    *(__nv_bfloat162*)(lo + i)     = __nv_bfloat162(l0, l1);
    *(__nv_bfloat162*)(lo + i + 2) = __nv_bfloat162(l2, l3);
}

// W [K,N] fp32 -> transposed [N,K] bf16 hi/lo. block (32,8), grid (N/32, K/32)
__global__ void __launch_bounds__(256) convert_wT_kernel(
    const float* __restrict__ W, __nv_bfloat16* __restrict__ hi,
    __nv_bfloat16* __restrict__ lo)
{
    __shared__ float t[32][33];
    const int n0 = blockIdx.x * 32, k0 = blockIdx.y * 32;
    const int tx = threadIdx.x, ty = threadIdx.y;
    #pragma unroll
    for (int r = ty; r < 32; r += 8)
        t[r][tx] = W[(size_t)(k0 + r) * GN + n0 + tx];
    __syncthreads();
    #pragma unroll
    for (int r = ty; r < 32; r += 8) {
        float v = t[tx][r];            // = W[k0+tx][n0+r]
        __nv_bfloat16 h = __float2bfloat16(v);
        __nv_bfloat16 l = __float2bfloat16(v - __bfloat162float(h));
        hi[(size_t)(n0 + r) * GK + k0 + tx] = h;
        lo[(size_t)(n0 + r) * GK + k0 + tx] = l;
    }
}

// ================= HMMA bf16x3 GEMM =========================================
// C = (Ahi+Alo)[M,K] @ (Bhi+Blo)[N,K]^T + bias.  CTA 256x128, warp 64x64.
// smem stage layout (row stride 80B): rows 0-255 Ahi, 256-511 Alo,
// 512-639 Bhi, 640-767 Blo.
__device__ __forceinline__ void load_stage(
    uint32_t sbase, const __nv_bfloat16* pAh, const __nv_bfloat16* pAl,
    const __nv_bfloat16* pBh, const __nv_bfloat16* pBl, int kc, int tid)
{
    const int r0  = tid >> 2;                 // 0..63
    const int seg = tid & 3;
    const uint32_t so = sbase + r0 * ROWB + seg * 16;
    const size_t   go = (size_t)r0 * GK + kc + seg * 8;
    #pragma unroll
    for (int j = 0; j < 4; j++)
        cp_async16(so + j * 64 * ROWB, pAh + go + (size_t)j * 64 * GK);
    #pragma unroll
    for (int j = 0; j < 4; j++)
        cp_async16(so + (256 + j * 64) * ROWB, pAl + go + (size_t)j * 64 * GK);
    #pragma unroll
    for (int j = 0; j < 2; j++)
        cp_async16(so + (512 + j * 64) * ROWB, pBh + go + (size_t)j * 64 * GK);
    #pragma unroll
    for (int j = 0; j < 2; j++)
        cp_async16(so + (640 + j * 64) * ROWB, pBl + go + (size_t)j * 64 * GK);
}

__global__ void __launch_bounds__(256) hmma_gemm_kernel(
    const __nv_bfloat16* __restrict__ Ahi, const __nv_bfloat16* __restrict__ Alo,
    const __nv_bfloat16* __restrict__ Bhi, const __nv_bfloat16* __restrict__ Blo,
    const float* __restrict__ bias, float* __restrict__ C)
{
    extern __shared__ char smem[];
    const uint32_t sb0 = smem_u32(smem);
    const int tid = threadIdx.x, wid = tid >> 5, lane = tid & 31;
    const int warp_m = (wid & 3) * 64;      // 4 warps along M (256)
    const int warp_n = (wid >> 2) * 64;     // 2 warps along N (128)
    const int m0 = blockIdx.y * 256, n0 = blockIdx.x * 128;

    const __nv_bfloat16* pAh = Ahi + (size_t)m0 * GK;
    const __nv_bfloat16* pAl = Alo + (size_t)m0 * GK;
    const __nv_bfloat16* pBh = Bhi + (size_t)n0 * GK;
    const __nv_bfloat16* pBl = Blo + (size_t)n0 * GK;

    float acc[4][8][4];
    #pragma unroll
    for (int i = 0; i < 4; i++)
        #pragma unroll
        for (int j = 0; j < 8; j++)
            #pragma unroll
            for (int t = 0; t < 4; t++) acc[i][j][t] = 0.f;

    const int arow = ((lane >> 3) & 1) * 8 + (lane & 7);
    const int acol = (lane >> 4) * 16;
    const int brow = (lane >> 4) * 8 + (lane & 7);
    const int bcol = ((lane >> 3) & 1) * 16;

    load_stage(sb0, pAh, pAl, pBh, pBl, 0, tid);
    cp_commit();
    load_stage(sb0 + STAGEB, pAh, pAl, pBh, pBl, BK, tid);
    cp_commit();

    #pragma unroll 1
    for (int kt = 0; kt < NIT; kt++) {
        cp_wait<1>();
        __syncthreads();
        if (kt + 2 < NIT)
            load_stage(sb0 + ((kt + 2) % STAGES) * STAGEB,
                       pAh, pAl, pBh, pBl, (kt + 2) * BK, tid);
        cp_commit();

        const uint32_t sb = sb0 + (kt % STAGES) * STAGEB;
        #pragma unroll
        for (int ks = 0; ks < 2; ks++) {
            uint32_t ah[4][4], al[4][4];
            #pragma unroll
            for (int mt = 0; mt < 4; mt++) {
                uint32_t addr = sb + (warp_m + mt * 16 + arow) * ROWB
                              + ks * 32 + acol;
                ldsm4(ah[mt], addr);
                ldsm4(al[mt], addr + 256 * ROWB);
            }
            uint32_t bh[4][4], bl[4][4];
            #pragma unroll
            for (int np = 0; np < 4; np++) {
                uint32_t addr = sb + OFF_B + (warp_n + np * 16 + brow) * ROWB
                              + ks * 32 + bcol;
                ldsm4(bh[np], addr);
                ldsm4(bl[np], addr + 128 * ROWB);
            }
            #pragma unroll
            for (int mt = 0; mt < 4; mt++)
                #pragma unroll
                for (int nt = 0; nt < 8; nt++) {
                    const int np = nt >> 1, pp = (nt & 1) * 2;
                    mma16816(acc[mt][nt], ah[mt], bh[np][pp], bh[np][pp + 1]);
                    mma16816(acc[mt][nt], ah[mt], bl[np][pp], bl[np][pp + 1]);
                    mma16816(acc[mt][nt], al[mt], bh[np][pp], bh[np][pp + 1]);
                }
        }
    }

    #pragma unroll
    for (int mt = 0; mt < 4; mt++) {
        const int row = m0 + warp_m + mt * 16 + (lane >> 2);
        #pragma unroll
        for (int nt = 0; nt < 8; nt++) {
            const int col = n0 + warp_n + nt * 8 + (lane & 3) * 2;
            const float b0 = bias[col], b1 = bias[col + 1];
            float2 lo = make_float2(acc[mt][nt][0] + b0, acc[mt][nt][1] + b1);
            float2 hi = make_float2(acc[mt][nt][2] + b0, acc[mt][nt][3] + b1);
            *(float2*)(C + (size_t)row * GN + col)       = lo;
            *(float2*)(C + (size_t)(row + 8) * GN + col) = hi;
        }
    }
}

// ---------------- RoPE over q and k, layout (b,l,h,hd), interleaved pairs ---
__global__ void rope_kernel(float* __restrict__ q, float* __restrict__ k,
                            const float* __restrict__ cosT,
                            const float* __restrict__ sinT)
{
    constexpr int NP = B * L * H * (HD / 2);
    int idx = blockIdx.x * blockDim.x + threadIdx.x;
    if (idx >= NP) return;
    int p = idx & 63;
    int l = ((idx >> 6) / H) % L;
    float c = cosT[l * 64 + p];
    float s = sinT[l * 64 + p];
    float2 qv = *(float2*)(q + 2 * (long long)idx);
    float2 kv = *(float2*)(k + 2 * (long long)idx);
    float2 qr = make_float2(qv.x * c - qv.y * s, qv.x * s + qv.y * c);
    float2 kr = make_float2(kv.x * c - kv.y * s, kv.x * s + kv.y * c);
    *(float2*)(q + 2 * (long long)idx) = qr;
    *(float2*)(k + 2 * (long long)idx) = kr;
}

// ---------------- compress: (b,l,h,:HD) @ Wc(HD,LD) + bc -> (b,h,l,:LD) -----
// 32 l-rows per block, 256 threads; grid (L/32, B*H)
__global__ void __launch_bounds__(256) compress_kernel(
    const float* __restrict__ X, const float* __restrict__ Wc,
    const float* __restrict__ bc, float* __restrict__ Xc)
{
    __shared__ float Ws[HD][LD];    // 16KB
    __shared__ float xs[32][HD];    // 16KB
    const int bh = blockIdx.y;
    const int b = bh / H, h = bh % H;
    const int l0 = blockIdx.x * 32;
    const int tid = threadIdx.x;
    for (int i = tid; i < HD * LD; i += 256) Ws[i / LD][i % LD] = Wc[i];
    for (int i = tid; i < 32 * HD; i += 256) {
        int li = i >> 7, d = i & 127;
        xs[li][d] = X[((long long)((b * L + l0 + li) * H + h)) * HD + d];
    }
    __syncthreads();
    const int e = tid & 31;
    const float bias = bc[e];
    #pragma unroll
    for (int p = 0; p < 4; p++) {
        const int li = p * 8 + (tid >> 5);
        float acc = bias;
        #pragma unroll
        for (int d = 0; d < HD; d++) acc += xs[li][d] * Ws[d][e];
        Xc[((long long)bh * L + l0 + li) * LD + e] = acc;
    }
}

// ---------------- causal flash attention in compressed space ----------------
// 64 queries / block (8 warps x 8 queries), shared 32-key K/V tiles.
__global__ void __launch_bounds__(256) attn_kernel(
    const float* __restrict__ qc, const float* __restrict__ kc,
    const float* __restrict__ vc, float* __restrict__ attn)
{
    __shared__ float ks[32][33];
    __shared__ float vs[32][33];
    __shared__ float qs[64][33];
    constexpr float SCALE = 0.17677669529663687f;  // 1/sqrt(32)

    const int bh  = blockIdx.y;
    const int q0  = (gridDim.x - 1 - blockIdx.x) * 64;   // long blocks first
    const int tid = threadIdx.x;
    const int w = tid >> 5, lane = tid & 31;

    const float* bq_ = qc + ((long long)bh * L + q0) * LD;
    const float* bk  = kc + (long long)bh * L * LD;
    const float* bv  = vc + (long long)bh * L * LD;

    for (int i = tid; i < 64 * 32; i += 256)
        qs[i >> 5][i & 31] = bq_[i];

    float m[8], lsum[8], acc[8];
    #pragma unroll
    for (int r = 0; r < 8; r++) { m[r] = -INFINITY; lsum[r] = 0.f; acc[r] = 0.f; }

    const int ntiles = q0 / 32 + 2;

    for (int t = 0; t < ntiles; t++) {
        __syncthreads();
        #pragma unroll
        for (int i = tid; i < 32 * 32; i += 256) {
            int r = i >> 5, c = i & 31;
            ks[r][c] = bk[((long long)(t * 32 + r)) * LD + c];
            vs[r][c] = bv[((long long)(t * 32 + r)) * LD + c];
        }
        __syncthreads();

        const int key = t * 32 + lane;
        #pragma unroll
        for (int r = 0; r < 8; r++) {
            const int qrow = w * 8 + r;
            const int q = q0 + qrow;
            float s = 0.f;
            #pragma unroll
            for (int e = 0; e < 32; e++) s += qs[qrow][e] * ks[lane][e];
            s = (key <= q) ? s * SCALE : -INFINITY;

            float tm = s;
            #pragma unroll
            for (int off = 16; off; off >>= 1)
                tm = fmaxf(tm, __shfl_xor_sync(0xffffffffu, tm, off));
            const float mnew  = fmaxf(m[r], tm);
            const float alpha = __expf(m[r] - mnew);
            const float p     = __expf(s - mnew);

            float psum = p;
            #pragma unroll
            for (int off = 16; off; off >>= 1)
                psum += __shfl_xor_sync(0xffffffffu, psum, off);
            lsum[r] = lsum[r] * alpha + psum;

            acc[r] *= alpha;
            #pragma unroll
            for (int j = 0; j < 32; j++) {
                float pj = __shfl_sync(0xffffffffu, p, j);
                acc[r] += pj * vs[j][lane];
            }
            m[r] = mnew;
        }
    }

    const int b = bh / H, h = bh % H;
    #pragma unroll
    for (int r = 0; r < 8; r++) {
        const int q = q0 + w * 8 + r;
        attn[((long long)(b * L + q) * H + h) * LD + lane] = acc[r] / lsum[r];
    }
}

// ---------------- decompress: rows(b,l,h) x LD @ Wd(LD,HD) + bd -> (b,l,D) --
// 32 rows per block, 256 threads; grid (B*L*H/32)
__global__ void __launch_bounds__(256) decompress_kernel(
    const float* __restrict__ Ac, const float* __restrict__ Wd,
    const float* __restrict__ bd, float* __restrict__ Out)
{
    __shared__ float Ws[LD][HD];    // 16KB
    __shared__ float as[32][LD];    // 4KB
    const int r0 = blockIdx.x * 32;
    const int tid = threadIdx.x;
    for (int i = tid; i < LD * HD; i += 256) Ws[i / HD][i % HD] = Wd[i];
    for (int i = tid; i < 32 * LD; i += 256)
        as[i >> 5][i & 31] = Ac[(long long)r0 * LD + i];
    __syncthreads();
    const int c  = tid & 127;
    const int rb = tid >> 7;
    const float bvv = bd[c];
    #pragma unroll
    for (int rr = rb; rr < 32; rr += 2) {
        float acc = bvv;
        #pragma unroll
        for (int e = 0; e < LD; e++) acc += as[rr][e] * Ws[e][c];
        Out[(long long)(r0 + rr) * HD + c] = acc;
    }
}

// ---------------------------------------------------------------------------
extern "C" void kernel_launch(void* const* d_in, const int* in_sizes, int n_in,
                              void* d_out, int out_size)
{
    const float* x    = (const float*)d_in[0];
    const float* cosT = (const float*)d_in[1];
    const float* sinT = (const float*)d_in[2];
    const float* Wq   = (const float*)d_in[3];
    const float* bq   = (const float*)d_in[4];
    const float* Wk   = (const float*)d_in[5];
    const float* bk   = (const float*)d_in[6];
    const float* Wv   = (const float*)d_in[7];
    const float* bv   = (const float*)d_in[8];
    const float* Wqc  = (const float*)d_in[9];
    const float* bqc  = (const float*)d_in[10];
    const float* Wkc  = (const float*)d_in[11];
    const float* bkc  = (const float*)d_in[12];
    const float* Wvc  = (const float*)d_in[13];
    const float* bvc  = (const float*)d_in[14];
    const float* Wd   = (const float*)d_in[15];
    const float* bd   = (const float*)d_in[16];
    const float* Wo   = (const float*)d_in[17];
    const float* bo   = (const float*)d_in[18];
    float* out = (float*)d_out;

    float *q, *k, *v, *qc, *kc, *vc, *attn;
    __nv_bfloat16 *ahi, *alo, *whi, *wlo;
    cudaGetSymbolAddress((void**)&q,    g_q);
    cudaGetSymbolAddress((void**)&k,    g_k);
    cudaGetSymbolAddress((void**)&v,    g_v);
    cudaGetSymbolAddress((void**)&qc,   g_qc);
    cudaGetSymbolAddress((void**)&kc,   g_kc);
    cudaGetSymbolAddress((void**)&vc,   g_vc);
    cudaGetSymbolAddress((void**)&attn, g_attn);
    cudaGetSymbolAddress((void**)&ahi,  g_ahi);
    cudaGetSymbolAddress((void**)&alo,  g_alo);
    cudaGetSymbolAddress((void**)&whi,  g_whi);
    cudaGetSymbolAddress((void**)&wlo,  g_wlo);

    cudaFuncSetAttribute(hmma_gemm_kernel,
                         cudaFuncAttributeMaxDynamicSharedMemorySize, SMEMB);

    const int conv_a_blocks = (GM * GK / 4) / 256;       // 8192
    dim3 wgrid(GN / 32, GK / 32);                        // (64,64)
    dim3 wblk(32, 8);
    dim3 ggrid(GN / 128, GM / 256);                      // (16, 16)

    // --- Q/K/V projections on tensor cores (bf16x3 HMMA) ---
    convert_a_kernel<<<conv_a_blocks, 256>>>(x, ahi, alo);
    convert_wT_kernel<<<wgrid, wblk>>>(Wq, whi, wlo);
    hmma_gemm_kernel<<<ggrid, 256, SMEMB>>>(ahi, alo, whi, wlo, bq, q);
    convert_wT_kernel<<<wgrid, wblk>>>(Wk, whi, wlo);
    hmma_gemm_kernel<<<ggrid, 256, SMEMB>>>(ahi, alo, whi, wlo, bk, k);
    convert_wT_kernel<<<wgrid, wblk>>>(Wv, whi, wlo);
    hmma_gemm_kernel<<<ggrid, 256, SMEMB>>>(ahi, alo, whi, wlo, bv, v);

    const int npairs = B * L * H * (HD / 2);
    rope_kernel<<<(npairs + 255) / 256, 256>>>(q, k, cosT, sinT);

    dim3 cgrid(L / 32, B * H);
    compress_kernel<<<cgrid, 256>>>(q, Wqc, bqc, qc);
    compress_kernel<<<cgrid, 256>>>(k, Wkc, bkc, kc);
    compress_kernel<<<cgrid, 256>>>(v, Wvc, bvc, vc);

    dim3 agrid(L / 64, B * H);
    attn_kernel<<<agrid, 256>>>(qc, kc, vc, attn);

    decompress_kernel<<<(B * L * H) / 32, 256>>>(attn, Wd, bd, q /* reuse */);

    // --- output projection ---
    convert_a_kernel<<<conv_a_blocks, 256>>>(q, ahi, alo);
    convert_wT_kernel<<<wgrid, wblk>>>(Wo, whi, wlo);
    hmma_gemm_kernel<<<ggrid, 256, SMEMB>>>(ahi, alo, whi, wlo, bo, out);
}

// round 6
// speedup vs baseline: 2.4389x; 1.2375x over previous
#include <cuda_runtime.h>
#include <cuda_fp16.h>
#include <math.h>
#include <cstdint>

namespace {
constexpr int B  = 2;
constexpr int L  = 2048;
constexpr int D  = 2048;
constexpr int H  = 16;
constexpr int HD = 128;
constexpr int LD = 32;
constexpr int BL = B * L;                 // 4096
constexpr int BHLLD = B * H * L * LD;     // 2097152

constexpr int GM = BL;    // 4096
constexpr int GN = D;     // 2048
constexpr int GK = D;     // 2048

// HMMA GEMM tiling: CTA 256x128, 8 warps of 64x64, BK=32, 3 stages
constexpr int BK     = 32;
constexpr int STAGES = 3;
constexpr int NIT    = GK / BK;            // 64
constexpr int ROWB   = 80;                 // smem row stride bytes (64B + 16 pad)
constexpr int OFF_B  = 512 * ROWB;         // B rows after 512 A rows (hi+lo)
constexpr int STAGEB = 640 * ROWB;         // 51200 per stage
constexpr int SMEMB  = STAGES * STAGEB;    // 153600
}

// ---------------- scratch (static device memory, no allocation) -------------
__device__ float g_q[B * L * D];
__device__ float g_k[B * L * D];
__device__ float g_v[B * L * D];
__device__ float g_qc[BHLLD];
__device__ float g_kc[BHLLD];
__device__ float g_vc[BHLLD];
__device__ float g_attn[BHLLD];
__device__ __half g_ahi[GM * GK];   // A fp16 split, [M,K]
__device__ __half g_alo[GM * GK];
__device__ __half g_w16[GK * GN];   // W fp16, TRANSPOSED [N,K]

// ================= PTX helpers ==============================================
__device__ __forceinline__ uint32_t smem_u32(const void* p) {
    uint32_t a;
    asm("{ .reg .u64 t; cvta.to.shared.u64 t, %1; cvt.u32.u64 %0, t; }"
        : "=r"(a) : "l"(p));
    return a;
}
__device__ __forceinline__ void cp_async16(uint32_t dst, const void* src) {
    asm volatile("cp.async.cg.shared.global [%0], [%1], 16;"
                 :: "r"(dst), "l"(src) : "memory");
}
__device__ __forceinline__ void cp_commit() {
    asm volatile("cp.async.commit_group;" ::: "memory");
}
template <int N>
__device__ __forceinline__ void cp_wait() {
    asm volatile("cp.async.wait_group %0;" :: "n"(N) : "memory");
}
__device__ __forceinline__ void ldsm4(uint32_t* r, uint32_t addr) {
    asm volatile("ldmatrix.sync.aligned.m8n8.x4.shared.b16 {%0,%1,%2,%3}, [%4];"
                 : "=r"(r[0]), "=r"(r[1]), "=r"(r[2]), "=r"(r[3]) : "r"(addr));
}
__device__ __forceinline__ void mma16816(float* d, const uint32_t* a,
                                         uint32_t b0, uint32_t b1) {
    asm volatile(
        "mma.sync.aligned.m16n8k16.row.col.f32.f16.f16.f32 "
        "{%0,%1,%2,%3}, {%4,%5,%6,%7}, {%8,%9}, {%0,%1,%2,%3};"
        : "+f"(d[0]), "+f"(d[1]), "+f"(d[2]), "+f"(d[3])
        : "r"(a[0]), "r"(a[1]), "r"(a[2]), "r"(a[3]), "r"(b0), "r"(b1));
}

// ================= conversion kernels =======================================
// X [rows,K] fp32 -> fp16 hi/lo split
__global__ void __launch_bounds__(256) convert_a_kernel(
    const float* __restrict__ X, __half* __restrict__ hi,
    __half* __restrict__ lo)
{
    long long i = ((long long)blockIdx.x * 256 + threadIdx.x) * 4;
    float4 v = *(const float4*)(X + i);
    __half h0 = __float2half_rn(v.x);
    __half h1 = __float2half_rn(v.y);
    __half h2 = __float2half_rn(v.z);
    __half h3 = __float2half_rn(v.w);
    __half l0 = __float2half_rn(v.x - __half2float(h0));
    __half l1 = __float2half_rn(v.y - __half2float(h1));
    __half l2 = __float2half_rn(v.z - __half2float(h2));
    __half l3 = __float2half_rn(v.w - __half2float(h3));
    *(__half2*)(hi + i)     = __halves2half2(h0, h1);
    *(__half2*)(hi + i + 2) = __halves2half2(h2, h3);
    *(__half2*)(lo + i)     = __halves2half2(l0, l1);
    *(__half2*)(lo + i + 2) = __halves2half2(l2, l3);
}

// W [K,N] fp32 -> transposed [N,K] fp16. block (32,8), grid (N/32, K/32)
__global__ void __launch_bounds__(256) convert_wT_kernel(
    const float* __restrict__ W, __half* __restrict__ w16)
{
    __shared__ float t[32][33];
    const int n0 = blockIdx.x * 32, k0 = blockIdx.y * 32;
    const int tx = threadIdx.x, ty = threadIdx.y;
    #pragma unroll
    for (int r = ty; r < 32; r += 8)
        t[r][tx] = W[(size_t)(k0 + r) * GN + n0 + tx];
    __syncthreads();
    #pragma unroll
    for (int r = ty; r < 32; r += 8)
        w16[(size_t)(n0 + r) * GK + k0 + tx] = __float2half_rn(t[tx][r]);
}

// ================= HMMA fp16 2-term GEMM ====================================
// C = (Ahi+Alo)[M,K] @ W[N,K]^T + bias.  CTA 256x128, warp 64x64.
// smem stage (row stride 80B): rows 0-255 Ahi, 256-511 Alo, 512-639 W.
__device__ __forceinline__ void load_stage(
    uint32_t sbase, const __half* pAh, const __half* pAl,
    const __half* pB, int kc, int tid)
{
    const int r0  = tid >> 2;                 // 0..63
    const int seg = tid & 3;
    const uint32_t so = sbase + r0 * ROWB + seg * 16;
    const size_t   go = (size_t)r0 * GK + kc + seg * 8;
    #pragma unroll
    for (int j = 0; j < 4; j++)
        cp_async16(so + j * 64 * ROWB, pAh + go + (size_t)j * 64 * GK);
    #pragma unroll
    for (int j = 0; j < 4; j++)
        cp_async16(so + (256 + j * 64) * ROWB, pAl + go + (size_t)j * 64 * GK);
    #pragma unroll
    for (int j = 0; j < 2; j++)
        cp_async16(so + (512 + j * 64) * ROWB, pB + go + (size_t)j * 64 * GK);
}

__global__ void __launch_bounds__(256) hmma_gemm_kernel(
    const __half* __restrict__ Ahi, const __half* __restrict__ Alo,
    const __half* __restrict__ Bw,
    const float* __restrict__ bias, float* __restrict__ C)
{
    extern __shared__ char smem[];
    const uint32_t sb0 = smem_u32(smem);
    const int tid = threadIdx.x, wid = tid >> 5, lane = tid & 31;
    const int warp_m = (wid & 3) * 64;      // 4 warps along M (256)
    const int warp_n = (wid >> 2) * 64;     // 2 warps along N (128)
    const int m0 = blockIdx.y * 256, n0 = blockIdx.x * 128;

    const __half* pAh = Ahi + (size_t)m0 * GK;
    const __half* pAl = Alo + (size_t)m0 * GK;
    const __half* pB  = Bw  + (size_t)n0 * GK;

    float acc[4][8][4];
    #pragma unroll
    for (int i = 0; i < 4; i++)
        #pragma unroll
        for (int j = 0; j < 8; j++)
            #pragma unroll
            for (int t = 0; t < 4; t++) acc[i][j][t] = 0.f;

    const int arow = ((lane >> 3) & 1) * 8 + (lane & 7);
    const int acol = (lane >> 4) * 16;
    const int brow = (lane >> 4) * 8 + (lane & 7);
    const int bcol = ((lane >> 3) & 1) * 16;

    load_stage(sb0, pAh, pAl, pB, 0, tid);
    cp_commit();
    load_stage(sb0 + STAGEB, pAh, pAl, pB, BK, tid);
    cp_commit();

    #pragma unroll 1
    for (int kt = 0; kt < NIT; kt++) {
        cp_wait<1>();
        __syncthreads();
        if (kt + 2 < NIT)
            load_stage(sb0 + ((kt + 2) % STAGES) * STAGEB,
                       pAh, pAl, pB, (kt + 2) * BK, tid);
        cp_commit();

        const uint32_t sb = sb0 + (kt % STAGES) * STAGEB;
        #pragma unroll
        for (int ks = 0; ks < 2; ks++) {
            uint32_t ah[4][4], al[4][4];
            #pragma unroll
            for (int mt = 0; mt < 4; mt++) {
                uint32_t addr = sb + (warp_m + mt * 16 + arow) * ROWB
                              + ks * 32 + acol;
                ldsm4(ah[mt], addr);
                ldsm4(al[mt], addr + 256 * ROWB);
            }
            uint32_t bh[4][4];
            #pragma unroll
            for (int np = 0; np < 4; np++) {
                uint32_t addr = sb + OFF_B + (warp_n + np * 16 + brow) * ROWB
                              + ks * 32 + bcol;
                ldsm4(bh[np], addr);
            }
            #pragma unroll
            for (int mt = 0; mt < 4; mt++)
                #pragma unroll
                for (int nt = 0; nt < 8; nt++) {
                    const int np = nt >> 1, pp = (nt & 1) * 2;
                    mma16816(acc[mt][nt], ah[mt], bh[np][pp], bh[np][pp + 1]);
                    mma16816(acc[mt][nt], al[mt], bh[np][pp], bh[np][pp + 1]);
                }
        }
    }

    #pragma unroll
    for (int mt = 0; mt < 4; mt++) {
        const int row = m0 + warp_m + mt * 16 + (lane >> 2);
        #pragma unroll
        for (int nt = 0; nt < 8; nt++) {
            const int col = n0 + warp_n + nt * 8 + (lane & 3) * 2;
            const float b0 = bias[col], b1 = bias[col + 1];
            float2 lo = make_float2(acc[mt][nt][0] + b0, acc[mt][nt][1] + b1);
            float2 hi = make_float2(acc[mt][nt][2] + b0, acc[mt][nt][3] + b1);
            *(float2*)(C + (size_t)row * GN + col)       = lo;
            *(float2*)(C + (size_t)(row + 8) * GN + col) = hi;
        }
    }
}

// ---------------- RoPE over q and k, layout (b,l,h,hd), interleaved pairs ---
__global__ void rope_kernel(float* __restrict__ q, float* __restrict__ k,
                            const float* __restrict__ cosT,
                            const float* __restrict__ sinT)
{
    constexpr int NP = B * L * H * (HD / 2);
    int idx = blockIdx.x * blockDim.x + threadIdx.x;
    if (idx >= NP) return;
    int p = idx & 63;
    int l = ((idx >> 6) / H) % L;
    float c = cosT[l * 64 + p];
    float s = sinT[l * 64 + p];
    float2 qv = *(float2*)(q + 2 * (long long)idx);
    float2 kv = *(float2*)(k + 2 * (long long)idx);
    float2 qr = make_float2(qv.x * c - qv.y * s, qv.x * s + qv.y * c);
    float2 kr = make_float2(kv.x * c - kv.y * s, kv.x * s + kv.y * c);
    *(float2*)(q + 2 * (long long)idx) = qr;
    *(float2*)(k + 2 * (long long)idx) = kr;
}

// ---------------- compress: (b,l,h,:HD) @ Wc(HD,LD) + bc -> (b,h,l,:LD) -----
// 32 l-rows per block, 256 threads: thread = (row, 4 e's). grid (L/32, B*H)
__global__ void __launch_bounds__(256) compress_kernel(
    const float* __restrict__ X, const float* __restrict__ Wc,
    const float* __restrict__ bc, float* __restrict__ Xc)
{
    __shared__ float Ws[HD][LD];       // 16KB, rows 128B -> float4 over e
    __shared__ float xs[32][HD];       // 16KB
    const int bh = blockIdx.y;
    const int b = bh / H, h = bh % H;
    const int l0 = blockIdx.x * 32;
    const int tid = threadIdx.x;
    for (int i = tid; i < HD * LD; i += 256) Ws[i / LD][i % LD] = Wc[i];
    for (int i = tid; i < 32 * HD; i += 256) {
        int li = i >> 7, d = i & 127;
        xs[li][d] = X[((long long)((b * L + l0 + li) * H + h)) * HD + d];
    }
    __syncthreads();
    const int row = tid >> 3;          // 0..31
    const int e0  = (tid & 7) * 4;     // 0,4,...,28
    float4 acc = *(const float4*)(bc + e0);
    #pragma unroll
    for (int d = 0; d < HD; d++) {
        const float xv = xs[row][d];
        const float4 w = *(const float4*)&Ws[d][e0];
        acc.x += xv * w.x; acc.y += xv * w.y;
        acc.z += xv * w.z; acc.w += xv * w.w;
    }
    *(float4*)(Xc + ((long long)bh * L + l0 + row) * LD + e0) = acc;
}

// ---------------- causal flash attention in compressed space ----------------
// 64 queries / block (8 warps x 8 queries), shared 32-key K/V tiles.
__global__ void __launch_bounds__(256) attn_kernel(
    const float* __restrict__ qc, const float* __restrict__ kc,
    const float* __restrict__ vc, float* __restrict__ attn)
{
    __shared__ float ks[32][33];
    __shared__ float vs[32][33];
    __shared__ float qs[64][33];
    constexpr float SCALE = 0.17677669529663687f;  // 1/sqrt(32)

    const int bh  = blockIdx.y;
    const int q0  = (gridDim.x - 1 - blockIdx.x) * 64;   // long blocks first
    const int tid = threadIdx.x;
    const int w = tid >> 5, lane = tid & 31;

    const float* bq_ = qc + ((long long)bh * L + q0) * LD;
    const float* bk  = kc + (long long)bh * L * LD;
    const float* bv  = vc + (long long)bh * L * LD;

    for (int i = tid; i < 64 * 32; i += 256)
        qs[i >> 5][i & 31] = bq_[i];

    float m[8], lsum[8], acc[8];
    #pragma unroll
    for (int r = 0; r < 8; r++) { m[r] = -INFINITY; lsum[r] = 0.f; acc[r] = 0.f; }

    const int ntiles = q0 / 32 + 2;

    for (int t = 0; t < ntiles; t++) {
        __syncthreads();
        #pragma unroll
        for (int i = tid; i < 32 * 32; i += 256) {
            int r = i >> 5, c = i & 31;
            ks[r][c] = bk[((long long)(t * 32 + r)) * LD + c];
            vs[r][c] = bv[((long long)(t * 32 + r)) * LD + c];
        }
        __syncthreads();

        const int key = t * 32 + lane;
        #pragma unroll
        for (int r = 0; r < 8; r++) {
            const int qrow = w * 8 + r;
            const int q = q0 + qrow;
            float s = 0.f;
            #pragma unroll
            for (int e = 0; e < 32; e++) s += qs[qrow][e] * ks[lane][e];
            s = (key <= q) ? s * SCALE : -INFINITY;

            float tm = s;
            #pragma unroll
            for (int off = 16; off; off >>= 1)
                tm = fmaxf(tm, __shfl_xor_sync(0xffffffffu, tm, off));
            const float mnew  = fmaxf(m[r], tm);
            const float alpha = __expf(m[r] - mnew);
            const float p     = __expf(s - mnew);

            float psum = p;
            #pragma unroll
            for (int off = 16; off; off >>= 1)
                psum += __shfl_xor_sync(0xffffffffu, psum, off);
            lsum[r] = lsum[r] * alpha + psum;

            acc[r] *= alpha;
            #pragma unroll
            for (int j = 0; j < 32; j++) {
                float pj = __shfl_sync(0xffffffffu, p, j);
                acc[r] += pj * vs[j][lane];
            }
            m[r] = mnew;
        }
    }

    const int b = bh / H, h = bh % H;
    #pragma unroll
    for (int r = 0; r < 8; r++) {
        const int q = q0 + w * 8 + r;
        attn[((long long)(b * L + q) * H + h) * LD + lane] = acc[r] / lsum[r];
    }
}

// ---------------- decompress: rows(b,l,h) x LD @ Wd(LD,HD) + bd -> (b,l,D) --
// 32 rows per block; thread = (4 rows, 4 cols). grid (B*L*H/32)
__global__ void __launch_bounds__(256) decompress_kernel(
    const float* __restrict__ Ac, const float* __restrict__ Wd,
    const float* __restrict__ bd, float* __restrict__ Out)
{
    __shared__ float Ws[LD][HD];    // 16KB, rows 512B -> float4 over c
    __shared__ float as[32][LD];    // 4KB
    const int r0 = blockIdx.x * 32;
    const int tid = threadIdx.x;
    for (int i = tid; i < LD * HD; i += 256) Ws[i / HD][i % HD] = Wd[i];
    for (int i = tid; i < 32 * LD; i += 256)
        as[i >> 5][i & 31] = Ac[(long long)r0 * LD + i];
    __syncthreads();
    const int c0   = (tid & 31) * 4;     // 0..124
    const int rg   = (tid >> 5) * 4;     // 0,4,...,28
    const float4 bv4 = *(const float4*)(bd + c0);
    float4 acc[4];
    #pragma unroll
    for (int i = 0; i < 4; i++) acc[i] = bv4;
    #pragma unroll
    for (int e = 0; e < LD; e++) {
        const float4 w = *(const float4*)&Ws[e][c0];
        #pragma unroll
        for (int i = 0; i < 4; i++) {
            const float a = as[rg + i][e];
            acc[i].x += a * w.x; acc[i].y += a * w.y;
            acc[i].z += a * w.z; acc[i].w += a * w.w;
        }
    }
    #pragma unroll
    for (int i = 0; i < 4; i++)
        *(float4*)(Out + (long long)(r0 + rg + i) * HD + c0) = acc[i];
}

// ---------------------------------------------------------------------------
extern "C" void kernel_launch(void* const* d_in, const int* in_sizes, int n_in,
                              void* d_out, int out_size)
{
    const float* x    = (const float*)d_in[0];
    const float* cosT = (const float*)d_in[1];
    const float* sinT = (const float*)d_in[2];
    const float* Wq   = (const float*)d_in[3];
    const float* bq   = (const float*)d_in[4];
    const float* Wk   = (const float*)d_in[5];
    const float* bk   = (const float*)d_in[6];
    const float* Wv   = (const float*)d_in[7];
    const float* bv   = (const float*)d_in[8];
    const float* Wqc  = (const float*)d_in[9];
    const float* bqc  = (const float*)d_in[10];
    const float* Wkc  = (const float*)d_in[11];
    const float* bkc  = (const float*)d_in[12];
    const float* Wvc  = (const float*)d_in[13];
    const float* bvc  = (const float*)d_in[14];
    const float* Wd   = (const float*)d_in[15];
    const float* bd   = (const float*)d_in[16];
    const float* Wo   = (const float*)d_in[17];
    const float* bo   = (const float*)d_in[18];
    float* out = (float*)d_out;

    float *q, *k, *v, *qc, *kc, *vc, *attn;
    __half *ahi, *alo, *w16;
    cudaGetSymbolAddress((void**)&q,    g_q);
    cudaGetSymbolAddress((void**)&k,    g_k);
    cudaGetSymbolAddress((void**)&v,    g_v);
    cudaGetSymbolAddress((void**)&qc,   g_qc);
    cudaGetSymbolAddress((void**)&kc,   g_kc);
    cudaGetSymbolAddress((void**)&vc,   g_vc);
    cudaGetSymbolAddress((void**)&attn, g_attn);
    cudaGetSymbolAddress((void**)&ahi,  g_ahi);
    cudaGetSymbolAddress((void**)&alo,  g_alo);
    cudaGetSymbolAddress((void**)&w16,  g_w16);

    cudaFuncSetAttribute(hmma_gemm_kernel,
                         cudaFuncAttributeMaxDynamicSharedMemorySize, SMEMB);

    const int conv_a_blocks = (GM * GK / 4) / 256;       // 8192
    dim3 wgrid(GN / 32, GK / 32);                        // (64,64)
    dim3 wblk(32, 8);
    dim3 ggrid(GN / 128, GM / 256);                      // (16, 16)

    // --- Q/K/V projections (fp16 2-term HMMA) ---
    convert_a_kernel<<<conv_a_blocks, 256>>>(x, ahi, alo);
    convert_wT_kernel<<<wgrid, wblk>>>(Wq, w16);
    hmma_gemm_kernel<<<ggrid, 256, SMEMB>>>(ahi, alo, w16, bq, q);
    convert_wT_kernel<<<wgrid, wblk>>>(Wk, w16);
    hmma_gemm_kernel<<<ggrid, 256, SMEMB>>>(ahi, alo, w16, bk, k);
    convert_wT_kernel<<<wgrid, wblk>>>(Wv, w16);
    hmma_gemm_kernel<<<ggrid, 256, SMEMB>>>(ahi, alo, w16, bv, v);

    const int npairs = B * L * H * (HD / 2);
    rope_kernel<<<(npairs + 255) / 256, 256>>>(q, k, cosT, sinT);

    dim3 cgrid(L / 32, B * H);
    compress_kernel<<<cgrid, 256>>>(q, Wqc, bqc, qc);
    compress_kernel<<<cgrid, 256>>>(k, Wkc, bkc, kc);
    compress_kernel<<<cgrid, 256>>>(v, Wvc, bvc, vc);

    dim3 agrid(L / 64, B * H);
    attn_kernel<<<agrid, 256>>>(qc, kc, vc, attn);

    decompress_kernel<<<(B * L * H) / 32, 256>>>(attn, Wd, bd, q /* reuse */);

    // --- output projection ---
    convert_a_kernel<<<conv_a_blocks, 256>>>(q, ahi, alo);
    convert_wT_kernel<<<wgrid, wblk>>>(Wo, w16);
    hmma_gemm_kernel<<<ggrid, 256, SMEMB>>>(ahi, alo, w16, bo, out);
}

// round 8
// speedup vs baseline: 3.8166x; 1.5649x over previous
#include <cuda_runtime.h>
#include <cuda_fp16.h>
#include <math.h>
#include <cstdint>

namespace {
constexpr int B  = 2;
constexpr int L  = 2048;
constexpr int D  = 2048;
constexpr int H  = 16;
constexpr int HD = 128;
constexpr int LD = 32;
constexpr int BL = B * L;                 // 4096
constexpr int BHLLD = B * H * L * LD;     // 2097152

constexpr int GM = BL;    // 4096
constexpr int GN = D;     // 2048
constexpr int GK = D;     // 2048

// HMMA GEMM tiling: CTA 256x128, 8 warps of 64x64, BK=32, 3 stages
constexpr int BK     = 32;
constexpr int STAGES = 3;
constexpr int NIT    = GK / BK;            // 64
constexpr int ROWB   = 80;                 // smem row stride bytes
constexpr int OFF_B  = 512 * ROWB;
constexpr int STAGEB = 640 * ROWB;         // 51200 per stage
constexpr int SMEMB  = STAGES * STAGEB;    // 153600
}

// ---------------- scratch (static device memory, no allocation) -------------
__device__ float g_q[B * L * D];
__device__ float g_k[B * L * D];
__device__ float g_v[B * L * D];
__device__ __half g_qch[BHLLD];      // compressed q/k/v, fp16, (b,h,l,e)
__device__ __half g_kch[BHLLD];
__device__ __half g_vch[BHLLD];
__device__ float g_attn[BHLLD];      // (b,l,h,e)
__device__ __half g_ahi[GM * GK];    // A fp16 split, [M,K]
__device__ __half g_alo[GM * GK];
__device__ __half g_w16[GK * GN];    // W fp16, TRANSPOSED [N,K]

// ================= PTX helpers ==============================================
__device__ __forceinline__ uint32_t smem_u32(const void* p) {
    uint32_t a;
    asm("{ .reg .u64 t; cvta.to.shared.u64 t, %1; cvt.u32.u64 %0, t; }"
        : "=r"(a) : "l"(p));
    return a;
}
__device__ __forceinline__ uint32_t h2_u32(__half2 h) {
    return *reinterpret_cast<uint32_t*>(&h);
}
__device__ __forceinline__ void cp_async16(uint32_t dst, const void* src) {
    asm volatile("cp.async.cg.shared.global [%0], [%1], 16;"
                 :: "r"(dst), "l"(src) : "memory");
}
__device__ __forceinline__ void cp_commit() {
    asm volatile("cp.async.commit_group;" ::: "memory");
}
template <int N>
__device__ __forceinline__ void cp_wait() {
    asm volatile("cp.async.wait_group %0;" :: "n"(N) : "memory");
}
__device__ __forceinline__ void ldsm4(uint32_t* r, uint32_t addr) {
    asm volatile("ldmatrix.sync.aligned.m8n8.x4.shared.b16 {%0,%1,%2,%3}, [%4];"
                 : "=r"(r[0]), "=r"(r[1]), "=r"(r[2]), "=r"(r[3]) : "r"(addr));
}
__device__ __forceinline__ void ldsm4t(uint32_t* r, uint32_t addr) {
    asm volatile("ldmatrix.sync.aligned.m8n8.x4.trans.shared.b16 {%0,%1,%2,%3}, [%4];"
                 : "=r"(r[0]), "=r"(r[1]), "=r"(r[2]), "=r"(r[3]) : "r"(addr));
}
__device__ __forceinline__ void mma16816(float* d, const uint32_t* a,
                                         uint32_t b0, uint32_t b1) {
    asm volatile(
        "mma.sync.aligned.m16n8k16.row.col.f32.f16.f16.f32 "
        "{%0,%1,%2,%3}, {%4,%5,%6,%7}, {%8,%9}, {%0,%1,%2,%3};"
        : "+f"(d[0]), "+f"(d[1]), "+f"(d[2]), "+f"(d[3])
        : "r"(a[0]), "r"(a[1]), "r"(a[2]), "r"(a[3]), "r"(b0), "r"(b1));
}

// ================= conversion kernels =======================================
__global__ void __launch_bounds__(256) convert_a_kernel(
    const float* __restrict__ X, __half* __restrict__ hi,
    __half* __restrict__ lo)
{
    long long i = ((long long)blockIdx.x * 256 + threadIdx.x) * 4;
    float4 v = *(const float4*)(X + i);
    __half h0 = __float2half_rn(v.x);
    __half h1 = __float2half_rn(v.y);
    __half h2 = __float2half_rn(v.z);
    __half h3 = __float2half_rn(v.w);
    __half l0 = __float2half_rn(v.x - __half2float(h0));
    __half l1 = __float2half_rn(v.y - __half2float(h1));
    __half l2 = __float2half_rn(v.z - __half2float(h2));
    __half l3 = __float2half_rn(v.w - __half2float(h3));
    *(__half2*)(hi + i)     = __halves2half2(h0, h1);
    *(__half2*)(hi + i + 2) = __halves2half2(h2, h3);
    *(__half2*)(lo + i)     = __halves2half2(l0, l1);
    *(__half2*)(lo + i + 2) = __halves2half2(l2, l3);
}

// W [K,N] fp32 -> transposed [N,K] fp16. block (32,8), grid (N/32, K/32)
__global__ void __launch_bounds__(256) convert_wT_kernel(
    const float* __restrict__ W, __half* __restrict__ w16)
{
    __shared__ float t[32][33];
    const int n0 = blockIdx.x * 32, k0 = blockIdx.y * 32;
    const int tx = threadIdx.x, ty = threadIdx.y;
    #pragma unroll
    for (int r = ty; r < 32; r += 8)
        t[r][tx] = W[(size_t)(k0 + r) * GN + n0 + tx];
    __syncthreads();
    #pragma unroll
    for (int r = ty; r < 32; r += 8)
        w16[(size_t)(n0 + r) * GK + k0 + tx] = __float2half_rn(t[tx][r]);
}

// ================= HMMA fp16 2-term GEMM ====================================
__device__ __forceinline__ void load_stage(
    uint32_t sbase, const __half* pAh, const __half* pAl,
    const __half* pB, int kc, int tid)
{
    const int r0  = tid >> 2;
    const int seg = tid & 3;
    const uint32_t so = sbase + r0 * ROWB + seg * 16;
    const size_t   go = (size_t)r0 * GK + kc + seg * 8;
    #pragma unroll
    for (int j = 0; j < 4; j++)
        cp_async16(so + j * 64 * ROWB, pAh + go + (size_t)j * 64 * GK);
    #pragma unroll
    for (int j = 0; j < 4; j++)
        cp_async16(so + (256 + j * 64) * ROWB, pAl + go + (size_t)j * 64 * GK);
    #pragma unroll
    for (int j = 0; j < 2; j++)
        cp_async16(so + (512 + j * 64) * ROWB, pB + go + (size_t)j * 64 * GK);
}

__global__ void __launch_bounds__(256) hmma_gemm_kernel(
    const __half* __restrict__ Ahi, const __half* __restrict__ Alo,
    const __half* __restrict__ Bw,
    const float* __restrict__ bias, float* __restrict__ C)
{
    extern __shared__ char smem[];
    const uint32_t sb0 = smem_u32(smem);
    const int tid = threadIdx.x, wid = tid >> 5, lane = tid & 31;
    const int warp_m = (wid & 3) * 64;
    const int warp_n = (wid >> 2) * 64;
    const int m0 = blockIdx.y * 256, n0 = blockIdx.x * 128;

    const __half* pAh = Ahi + (size_t)m0 * GK;
    const __half* pAl = Alo + (size_t)m0 * GK;
    const __half* pB  = Bw  + (size_t)n0 * GK;

    float acc[4][8][4];
    #pragma unroll
    for (int i = 0; i < 4; i++)
        #pragma unroll
        for (int j = 0; j < 8; j++)
            #pragma unroll
            for (int t = 0; t < 4; t++) acc[i][j][t] = 0.f;

    const int arow = ((lane >> 3) & 1) * 8 + (lane & 7);
    const int acol = (lane >> 4) * 16;
    const int brow = (lane >> 4) * 8 + (lane & 7);
    const int bcol = ((lane >> 3) & 1) * 16;

    load_stage(sb0, pAh, pAl, pB, 0, tid);
    cp_commit();
    load_stage(sb0 + STAGEB, pAh, pAl, pB, BK, tid);
    cp_commit();

    #pragma unroll 1
    for (int kt = 0; kt < NIT; kt++) {
        cp_wait<1>();
        __syncthreads();
        if (kt + 2 < NIT)
            load_stage(sb0 + ((kt + 2) % STAGES) * STAGEB,
                       pAh, pAl, pB, (kt + 2) * BK, tid);
        cp_commit();

        const uint32_t sb = sb0 + (kt % STAGES) * STAGEB;
        #pragma unroll
        for (int ks = 0; ks < 2; ks++) {
            uint32_t ah[4][4], al[4][4];
            #pragma unroll
            for (int mt = 0; mt < 4; mt++) {
                uint32_t addr = sb + (warp_m + mt * 16 + arow) * ROWB
                              + ks * 32 + acol;
                ldsm4(ah[mt], addr);
                ldsm4(al[mt], addr + 256 * ROWB);
            }
            uint32_t bh[4][4];
            #pragma unroll
            for (int np = 0; np < 4; np++) {
                uint32_t addr = sb + OFF_B + (warp_n + np * 16 + brow) * ROWB
                              + ks * 32 + bcol;
                ldsm4(bh[np], addr);
            }
            #pragma unroll
            for (int mt = 0; mt < 4; mt++)
                #pragma unroll
                for (int nt = 0; nt < 8; nt++) {
                    const int np = nt >> 1, pp = (nt & 1) * 2;
                    mma16816(acc[mt][nt], ah[mt], bh[np][pp], bh[np][pp + 1]);
                    mma16816(acc[mt][nt], al[mt], bh[np][pp], bh[np][pp + 1]);
                }
        }
    }

    #pragma unroll
    for (int mt = 0; mt < 4; mt++) {
        const int row = m0 + warp_m + mt * 16 + (lane >> 2);
        #pragma unroll
        for (int nt = 0; nt < 8; nt++) {
            const int col = n0 + warp_n + nt * 8 + (lane & 3) * 2;
            const float b0 = bias[col], b1 = bias[col + 1];
            float2 lo = make_float2(acc[mt][nt][0] + b0, acc[mt][nt][1] + b1);
            float2 hi = make_float2(acc[mt][nt][2] + b0, acc[mt][nt][3] + b1);
            *(float2*)(C + (size_t)row * GN + col)       = lo;
            *(float2*)(C + (size_t)(row + 8) * GN + col) = hi;
        }
    }
}

// ---------------- RoPE over q and k, layout (b,l,h,hd), interleaved pairs ---
__global__ void rope_kernel(float* __restrict__ q, float* __restrict__ k,
                            const float* __restrict__ cosT,
                            const float* __restrict__ sinT)
{
    constexpr int NP = B * L * H * (HD / 2);
    int idx = blockIdx.x * blockDim.x + threadIdx.x;
    if (idx >= NP) return;
    int p = idx & 63;
    int l = ((idx >> 6) / H) % L;
    float c = cosT[l * 64 + p];
    float s = sinT[l * 64 + p];
    float2 qv = *(float2*)(q + 2 * (long long)idx);
    float2 kv = *(float2*)(k + 2 * (long long)idx);
    float2 qr = make_float2(qv.x * c - qv.y * s, qv.x * s + qv.y * c);
    float2 kr = make_float2(kv.x * c - kv.y * s, kv.x * s + kv.y * c);
    *(float2*)(q + 2 * (long long)idx) = qr;
    *(float2*)(k + 2 * (long long)idx) = kr;
}

// ---------------- compress: (b,l,h,:HD) @ Wc(HD,LD) + bc -> fp16 (b,h,l,e) --
__global__ void __launch_bounds__(256) compress_kernel(
    const float* __restrict__ X, const float* __restrict__ Wc,
    const float* __restrict__ bc, __half* __restrict__ Xc)
{
    __shared__ float Ws[HD][LD];
    __shared__ float xs[32][HD];
    const int bh = blockIdx.y;
    const int b = bh / H, h = bh % H;
    const int l0 = blockIdx.x * 32;
    const int tid = threadIdx.x;
    for (int i = tid; i < HD * LD; i += 256) Ws[i / LD][i % LD] = Wc[i];
    for (int i = tid; i < 32 * HD; i += 256) {
        int li = i >> 7, d = i & 127;
        xs[li][d] = X[((long long)((b * L + l0 + li) * H + h)) * HD + d];
    }
    __syncthreads();
    const int row = tid >> 3;
    const int e0  = (tid & 7) * 4;
    float4 acc = *(const float4*)(bc + e0);
    #pragma unroll
    for (int d = 0; d < HD; d++) {
        const float xv = xs[row][d];
        const float4 w = *(const float4*)&Ws[d][e0];
        acc.x += xv * w.x; acc.y += xv * w.y;
        acc.z += xv * w.z; acc.w += xv * w.w;
    }
    __half2 o01 = __floats2half2_rn(acc.x, acc.y);
    __half2 o23 = __floats2half2_rn(acc.z, acc.w);
    __half2* dst = (__half2*)(Xc + ((long long)bh * L + l0 + row) * LD + e0);
    dst[0] = o01; dst[1] = o23;
}

// ---------------- tensor-core causal flash attention ------------------------
// 64 queries/block, 4 warps x 16 rows. 64-key tiles. qc/kc/vc fp16 (b,h,l,32).
__global__ void __launch_bounds__(128) attn_kernel(
    const __half* __restrict__ qc, const __half* __restrict__ kc,
    const __half* __restrict__ vc, float* __restrict__ attn)
{
    __shared__ __half qs[64][40];   // 80B rows
    __shared__ __half ks[64][40];
    __shared__ __half vs[64][40];
    constexpr float SCALE = 0.17677669529663687f;  // 1/sqrt(32)

    const int bh  = blockIdx.y;
    const int q0  = (gridDim.x - 1 - blockIdx.x) * 64;   // long blocks first
    const int tid = threadIdx.x;
    const int w = tid >> 5, lane = tid & 31;

    const __half* bq = qc + ((size_t)bh * L + q0) * LD;
    const __half* bk = kc + (size_t)bh * L * LD;
    const __half* bv = vc + (size_t)bh * L * LD;

    // load Q tile (64 rows x 64B)
    for (int i = tid; i < 256; i += 128) {
        const int r = i >> 2, c = i & 3;
        *(uint4*)((char*)&qs[r][0] + c * 16) =
            *(const uint4*)((const char*)(bq + (size_t)r * LD) + c * 16);
    }
    __syncthreads();

    const uint32_t qs_b = smem_u32(qs);
    const uint32_t ks_b = smem_u32(ks);
    const uint32_t vs_b = smem_u32(vs);

    const int arow = ((lane >> 3) & 1) * 8 + (lane & 7);
    const int acol = (lane >> 4) * 16;
    const int brow = (lane >> 4) * 8 + (lane & 7);
    const int bcol = ((lane >> 3) & 1) * 16;

    // Q a-frags (row r = lane>>2 within warp's 16 rows)
    uint32_t aq[2][4];
    #pragma unroll
    for (int ks2 = 0; ks2 < 2; ks2++)
        ldsm4(aq[ks2], qs_b + (w * 16 + arow) * 80 + ks2 * 32 + acol);

    float o[4][4];
    #pragma unroll
    for (int i = 0; i < 4; i++)
        #pragma unroll
        for (int j = 0; j < 4; j++) o[i][j] = 0.f;
    float m_lo = -INFINITY, m_hi = -INFINITY, l_lo = 0.f, l_hi = 0.f;

    const int nt = q0 / 64 + 1;
    const int row_lo = q0 + w * 16 + (lane >> 2);
    const int row_hi = row_lo + 8;

    for (int t = 0; t < nt; t++) {
        __syncthreads();
        // load K,V tiles (64 keys x 64B each)
        for (int i = tid; i < 512; i += 128) {
            const int mtx = i >> 8;            // 0=K, 1=V
            const int r = (i >> 2) & 63, c = i & 3;
            const __half* src = (mtx ? bv : bk) + ((size_t)(t * 64 + r)) * LD;
            __half* dst = mtx ? &vs[r][0] : &ks[r][0];
            *(uint4*)((char*)dst + c * 16) =
                *(const uint4*)((const char*)src + c * 16);
        }
        __syncthreads();

        // S = Q K^T  (16 x 64)
        float s[8][4];
        #pragma unroll
        for (int i = 0; i < 8; i++)
            #pragma unroll
            for (int j = 0; j < 4; j++) s[i][j] = 0.f;
        #pragma unroll
        for (int ks2 = 0; ks2 < 2; ks2++) {
            #pragma unroll
            for (int ng = 0; ng < 4; ng++) {
                uint32_t bkf[4];
                ldsm4(bkf, ks_b + (ng * 16 + brow) * 80 + ks2 * 32 + bcol);
                mma16816(s[ng * 2],     aq[ks2], bkf[0], bkf[1]);
                mma16816(s[ng * 2 + 1], aq[ks2], bkf[2], bkf[3]);
            }
        }

        // scale + causal mask (only diagonal tile needs it)
        const bool diag = (t == nt - 1);
        #pragma unroll
        for (int nf = 0; nf < 8; nf++) {
            const int col = t * 64 + nf * 8 + (lane & 3) * 2;
            #pragma unroll
            for (int j = 0; j < 4; j++) s[nf][j] *= SCALE;
            if (diag) {
                if (col     > row_lo) s[nf][0] = -INFINITY;
                if (col + 1 > row_lo) s[nf][1] = -INFINITY;
                if (col     > row_hi) s[nf][2] = -INFINITY;
                if (col + 1 > row_hi) s[nf][3] = -INFINITY;
            }
        }

        // row max (tile) then quad-reduce
        float tm_lo = -INFINITY, tm_hi = -INFINITY;
        #pragma unroll
        for (int nf = 0; nf < 8; nf++) {
            tm_lo = fmaxf(tm_lo, fmaxf(s[nf][0], s[nf][1]));
            tm_hi = fmaxf(tm_hi, fmaxf(s[nf][2], s[nf][3]));
        }
        #pragma unroll
        for (int off = 1; off <= 2; off <<= 1) {
            tm_lo = fmaxf(tm_lo, __shfl_xor_sync(0xffffffffu, tm_lo, off));
            tm_hi = fmaxf(tm_hi, __shfl_xor_sync(0xffffffffu, tm_hi, off));
        }
        const float mn_lo = fmaxf(m_lo, tm_lo);
        const float mn_hi = fmaxf(m_hi, tm_hi);
        const float al_lo = __expf(m_lo - mn_lo);
        const float al_hi = __expf(m_hi - mn_hi);
        m_lo = mn_lo; m_hi = mn_hi;

        // p = exp(s - m), row sums
        float ps_lo = 0.f, ps_hi = 0.f;
        #pragma unroll
        for (int nf = 0; nf < 8; nf++) {
            s[nf][0] = __expf(s[nf][0] - mn_lo);
            s[nf][1] = __expf(s[nf][1] - mn_lo);
            s[nf][2] = __expf(s[nf][2] - mn_hi);
            s[nf][3] = __expf(s[nf][3] - mn_hi);
            ps_lo += s[nf][0] + s[nf][1];
            ps_hi += s[nf][2] + s[nf][3];
        }
        #pragma unroll
        for (int off = 1; off <= 2; off <<= 1) {
            ps_lo += __shfl_xor_sync(0xffffffffu, ps_lo, off);
            ps_hi += __shfl_xor_sync(0xffffffffu, ps_hi, off);
        }
        l_lo = l_lo * al_lo + ps_lo;
        l_hi = l_hi * al_hi + ps_hi;

        // rescale O
        #pragma unroll
        for (int nf = 0; nf < 4; nf++) {
            o[nf][0] *= al_lo; o[nf][1] *= al_lo;
            o[nf][2] *= al_hi; o[nf][3] *= al_hi;
        }

        // O += P V   (P as a-frags from s, V via ldmatrix.trans)
        #pragma unroll
        for (int kc4 = 0; kc4 < 4; kc4++) {
            uint32_t ap[4];
            const int f0 = 2 * kc4, f1 = 2 * kc4 + 1;
            ap[0] = h2_u32(__floats2half2_rn(s[f0][0], s[f0][1]));
            ap[1] = h2_u32(__floats2half2_rn(s[f0][2], s[f0][3]));
            ap[2] = h2_u32(__floats2half2_rn(s[f1][0], s[f1][1]));
            ap[3] = h2_u32(__floats2half2_rn(s[f1][2], s[f1][3]));
            #pragma unroll
            for (int half = 0; half < 2; half++) {
                uint32_t bvf[4];
                ldsm4t(bvf, vs_b + (kc4 * 16 + arow) * 80 + half * 32 + acol);
                mma16816(o[half * 2],     ap, bvf[0], bvf[1]);
                mma16816(o[half * 2 + 1], ap, bvf[2], bvf[3]);
            }
        }
    }

    // write out: attn (b,l,h,e) fp32
    const int b = bh / H, h = bh % H;
    const float inv_lo = 1.f / l_lo, inv_hi = 1.f / l_hi;
    #pragma unroll
    for (int nf = 0; nf < 4; nf++) {
        const int e = nf * 8 + (lane & 3) * 2;
        float* p_lo = attn + ((size_t)(b * L + row_lo) * H + h) * LD + e;
        float* p_hi = attn + ((size_t)(b * L + row_hi) * H + h) * LD + e;
        *(float2*)p_lo = make_float2(o[nf][0] * inv_lo, o[nf][1] * inv_lo);
        *(float2*)p_hi = make_float2(o[nf][2] * inv_hi, o[nf][3] * inv_hi);
    }
}

// ---------------- decompress: rows(b,l,h) x LD @ Wd(LD,HD) + bd -> (b,l,D) --
__global__ void __launch_bounds__(256) decompress_kernel(
    const float* __restrict__ Ac, const float* __restrict__ Wd,
    const float* __restrict__ bd, float* __restrict__ Out)
{
    __shared__ float Ws[LD][HD];
    __shared__ float as[32][LD];
    const int r0 = blockIdx.x * 32;
    const int tid = threadIdx.x;
    for (int i = tid; i < LD * HD; i += 256) Ws[i / HD][i % HD] = Wd[i];
    for (int i = tid; i < 32 * LD; i += 256)
        as[i >> 5][i & 31] = Ac[(long long)r0 * LD + i];
    __syncthreads();
    const int c0   = (tid & 31) * 4;
    const int rg   = (tid >> 5) * 4;
    const float4 bv4 = *(const float4*)(bd + c0);
    float4 acc[4];
    #pragma unroll
    for (int i = 0; i < 4; i++) acc[i] = bv4;
    #pragma unroll
    for (int e = 0; e < LD; e++) {
        const float4 w = *(const float4*)&Ws[e][c0];
        #pragma unroll
        for (int i = 0; i < 4; i++) {
            const float a = as[rg + i][e];
            acc[i].x += a * w.x; acc[i].y += a * w.y;
            acc[i].z += a * w.z; acc[i].w += a * w.w;
        }
    }
    #pragma unroll
    for (int i = 0; i < 4; i++)
        *(float4*)(Out + (long long)(r0 + rg + i) * HD + c0) = acc[i];
}

// ---------------------------------------------------------------------------
extern "C" void kernel_launch(void* const* d_in, const int* in_sizes, int n_in,
                              void* d_out, int out_size)
{
    const float* x    = (const float*)d_in[0];
    const float* cosT = (const float*)d_in[1];
    const float* sinT = (const float*)d_in[2];
    const float* Wq   = (const float*)d_in[3];
    const float* bq   = (const float*)d_in[4];
    const float* Wk   = (const float*)d_in[5];
    const float* bk   = (const float*)d_in[6];
    const float* Wv   = (const float*)d_in[7];
    const float* bv   = (const float*)d_in[8];
    const float* Wqc  = (const float*)d_in[9];
    const float* bqc  = (const float*)d_in[10];
    const float* Wkc  = (const float*)d_in[11];
    const float* bkc  = (const float*)d_in[12];
    const float* Wvc  = (const float*)d_in[13];
    const float* bvc  = (const float*)d_in[14];
    const float* Wd   = (const float*)d_in[15];
    const float* bd   = (const float*)d_in[16];
    const float* Wo   = (const float*)d_in[17];
    const float* bo   = (const float*)d_in[18];
    float* out = (float*)d_out;

    float *q, *k, *v, *attn;
    __half *qch, *kch, *vch, *ahi, *alo, *w16;
    cudaGetSymbolAddress((void**)&q,    g_q);
    cudaGetSymbolAddress((void**)&k,    g_k);
    cudaGetSymbolAddress((void**)&v,    g_v);
    cudaGetSymbolAddress((void**)&qch,  g_qch);
    cudaGetSymbolAddress((void**)&kch,  g_kch);
    cudaGetSymbolAddress((void**)&vch,  g_vch);
    cudaGetSymbolAddress((void**)&attn, g_attn);
    cudaGetSymbolAddress((void**)&ahi,  g_ahi);
    cudaGetSymbolAddress((void**)&alo,  g_alo);
    cudaGetSymbolAddress((void**)&w16,  g_w16);

    cudaFuncSetAttribute(hmma_gemm_kernel,
                         cudaFuncAttributeMaxDynamicSharedMemorySize, SMEMB);

    const int conv_a_blocks = (GM * GK / 4) / 256;       // 8192
    dim3 wgrid(GN / 32, GK / 32);                        // (64,64)
    dim3 wblk(32, 8);
    dim3 ggrid(GN / 128, GM / 256);                      // (16, 16)

    // --- Q/K/V projections (fp16 2-term HMMA) ---
    convert_a_kernel<<<conv_a_blocks, 256>>>(x, ahi, alo);
    convert_wT_kernel<<<wgrid, wblk>>>(Wq, w16);
    hmma_gemm_kernel<<<ggrid, 256, SMEMB>>>(ahi, alo, w16, bq, q);
    convert_wT_kernel<<<wgrid, wblk>>>(Wk, w16);
    hmma_gemm_kernel<<<ggrid, 256, SMEMB>>>(ahi, alo, w16, bk, k);
    convert_wT_kernel<<<wgrid, wblk>>>(Wv, w16);
    hmma_gemm_kernel<<<ggrid, 256, SMEMB>>>(ahi, alo, w16, bv, v);

    const int npairs = B * L * H * (HD / 2);
    rope_kernel<<<(npairs + 255) / 256, 256>>>(q, k, cosT, sinT);

    dim3 cgrid(L / 32, B * H);
    compress_kernel<<<cgrid, 256>>>(q, Wqc, bqc, qch);
    compress_kernel<<<cgrid, 256>>>(k, Wkc, bkc, kch);
    compress_kernel<<<cgrid, 256>>>(v, Wvc, bvc, vch);

    dim3 agrid(L / 64, B * H);
    attn_kernel<<<agrid, 128>>>(qch, kch, vch, attn);

    decompress_kernel<<<(B * L * H) / 32, 256>>>(attn, Wd, bd, q /* reuse */);

    // --- output projection ---
    convert_a_kernel<<<conv_a_blocks, 256>>>(q, ahi, alo);
    convert_wT_kernel<<<wgrid, wblk>>>(Wo, w16);
    hmma_gemm_kernel<<<ggrid, 256, SMEMB>>>(ahi, alo, w16, bo, out);
}

// round 9
// speedup vs baseline: 5.6391x; 1.4775x over previous
#include <cuda_runtime.h>
#include <cuda_fp16.h>
#include <math.h>
#include <cstdint>

namespace {
constexpr int B  = 2;
constexpr int L  = 2048;
constexpr int D  = 2048;
constexpr int H  = 16;
constexpr int HD = 128;
constexpr int LD = 32;
constexpr int BL = B * L;                 // 4096
constexpr int BHLLD = B * H * L * LD;     // 2097152

constexpr int GM = BL;    // 4096
constexpr int GN = D;     // 2048
constexpr int GK = D;     // 2048

// HMMA GEMM tiling: CTA 256x128, 8 warps of 64x64, BK=32, 3 stages
constexpr int BK     = 32;
constexpr int STAGES = 3;
constexpr int NIT    = GK / BK;            // 64
constexpr int ROWB   = 80;                 // smem row stride bytes
constexpr int OFF_B  = 256 * ROWB;         // B rows after 256 A rows
constexpr int STAGEB = 384 * ROWB;         // 30720 per stage
constexpr int SMEMB  = STAGES * STAGEB;    // 92160
}

// ---------------- scratch (static device memory, no allocation) -------------
__device__ float g_q[B * L * D];
__device__ float g_k[B * L * D];
__device__ float g_v[B * L * D];
__device__ __half g_qch[BHLLD];      // compressed q/k/v, fp16, (b,h,l,e)
__device__ __half g_kch[BHLLD];
__device__ __half g_vch[BHLLD];
__device__ float g_attn[BHLLD];      // (b,l,h,e)
__device__ __half g_a16[GM * GK];    // A fp16, [M,K]
__device__ __half g_w16[GK * GN];    // W fp16, TRANSPOSED [N,K]

// ================= PTX helpers ==============================================
__device__ __forceinline__ uint32_t smem_u32(const void* p) {
    uint32_t a;
    asm("{ .reg .u64 t; cvta.to.shared.u64 t, %1; cvt.u32.u64 %0, t; }"
        : "=r"(a) : "l"(p));
    return a;
}
__device__ __forceinline__ uint32_t h2_u32(__half2 h) {
    return *reinterpret_cast<uint32_t*>(&h);
}
__device__ __forceinline__ void cp_async16(uint32_t dst, const void* src) {
    asm volatile("cp.async.cg.shared.global [%0], [%1], 16;"
                 :: "r"(dst), "l"(src) : "memory");
}
__device__ __forceinline__ void cp_commit() {
    asm volatile("cp.async.commit_group;" ::: "memory");
}
template <int N>
__device__ __forceinline__ void cp_wait() {
    asm volatile("cp.async.wait_group %0;" :: "n"(N) : "memory");
}
__device__ __forceinline__ void ldsm4(uint32_t* r, uint32_t addr) {
    asm volatile("ldmatrix.sync.aligned.m8n8.x4.shared.b16 {%0,%1,%2,%3}, [%4];"
                 : "=r"(r[0]), "=r"(r[1]), "=r"(r[2]), "=r"(r[3]) : "r"(addr));
}
__device__ __forceinline__ void ldsm4t(uint32_t* r, uint32_t addr) {
    asm volatile("ldmatrix.sync.aligned.m8n8.x4.trans.shared.b16 {%0,%1,%2,%3}, [%4];"
                 : "=r"(r[0]), "=r"(r[1]), "=r"(r[2]), "=r"(r[3]) : "r"(addr));
}
__device__ __forceinline__ void mma16816(float* d, const uint32_t* a,
                                         uint32_t b0, uint32_t b1) {
    asm volatile(
        "mma.sync.aligned.m16n8k16.row.col.f32.f16.f16.f32 "
        "{%0,%1,%2,%3}, {%4,%5,%6,%7}, {%8,%9}, {%0,%1,%2,%3};"
        : "+f"(d[0]), "+f"(d[1]), "+f"(d[2]), "+f"(d[3])
        : "r"(a[0]), "r"(a[1]), "r"(a[2]), "r"(a[3]), "r"(b0), "r"(b1));
}

// ================= conversion kernels =======================================
__global__ void __launch_bounds__(256) convert_a_kernel(
    const float* __restrict__ X, __half* __restrict__ out)
{
    long long i = ((long long)blockIdx.x * 256 + threadIdx.x) * 4;
    float4 v = *(const float4*)(X + i);
    *(__half2*)(out + i)     = __floats2half2_rn(v.x, v.y);
    *(__half2*)(out + i + 2) = __floats2half2_rn(v.z, v.w);
}

// W [K,N] fp32 -> transposed [N,K] fp16. block (32,8), grid (N/32, K/32)
__global__ void __launch_bounds__(256) convert_wT_kernel(
    const float* __restrict__ W, __half* __restrict__ w16)
{
    __shared__ float t[32][33];
    const int n0 = blockIdx.x * 32, k0 = blockIdx.y * 32;
    const int tx = threadIdx.x, ty = threadIdx.y;
    #pragma unroll
    for (int r = ty; r < 32; r += 8)
        t[r][tx] = W[(size_t)(k0 + r) * GN + n0 + tx];
    __syncthreads();
    #pragma unroll
    for (int r = ty; r < 32; r += 8)
        w16[(size_t)(n0 + r) * GK + k0 + tx] = __float2half_rn(t[tx][r]);
}

// ================= HMMA fp16 GEMM ===========================================
// C = A[M,K] @ W[N,K]^T + bias.  CTA 256x128, warp 64x64.
// smem stage (row stride 80B): rows 0-255 A, 256-383 B.
__device__ __forceinline__ void load_stage(
    uint32_t sbase, const __half* pA, const __half* pB, int kc, int tid)
{
    const int r0  = tid >> 2;
    const int seg = tid & 3;
    const uint32_t so = sbase + r0 * ROWB + seg * 16;
    const size_t   go = (size_t)r0 * GK + kc + seg * 8;
    #pragma unroll
    for (int j = 0; j < 4; j++)
        cp_async16(so + j * 64 * ROWB, pA + go + (size_t)j * 64 * GK);
    #pragma unroll
    for (int j = 0; j < 2; j++)
        cp_async16(so + (256 + j * 64) * ROWB, pB + go + (size_t)j * 64 * GK);
}

__global__ void __launch_bounds__(256) hmma_gemm_kernel(
    const __half* __restrict__ A16, const __half* __restrict__ Bw,
    const float* __restrict__ bias, float* __restrict__ C)
{
    extern __shared__ char smem[];
    const uint32_t sb0 = smem_u32(smem);
    const int tid = threadIdx.x, wid = tid >> 5, lane = tid & 31;
    const int warp_m = (wid & 3) * 64;
    const int warp_n = (wid >> 2) * 64;
    const int m0 = blockIdx.y * 256, n0 = blockIdx.x * 128;

    const __half* pA = A16 + (size_t)m0 * GK;
    const __half* pB = Bw  + (size_t)n0 * GK;

    float acc[4][8][4];
    #pragma unroll
    for (int i = 0; i < 4; i++)
        #pragma unroll
        for (int j = 0; j < 8; j++)
            #pragma unroll
            for (int t = 0; t < 4; t++) acc[i][j][t] = 0.f;

    const int arow = ((lane >> 3) & 1) * 8 + (lane & 7);
    const int acol = (lane >> 4) * 16;
    const int brow = (lane >> 4) * 8 + (lane & 7);
    const int bcol = ((lane >> 3) & 1) * 16;

    load_stage(sb0, pA, pB, 0, tid);
    cp_commit();
    load_stage(sb0 + STAGEB, pA, pB, BK, tid);
    cp_commit();

    #pragma unroll 1
    for (int kt = 0; kt < NIT; kt++) {
        cp_wait<1>();
        __syncthreads();
        if (kt + 2 < NIT)
            load_stage(sb0 + ((kt + 2) % STAGES) * STAGEB,
                       pA, pB, (kt + 2) * BK, tid);
        cp_commit();

        const uint32_t sb = sb0 + (kt % STAGES) * STAGEB;
        #pragma unroll
        for (int ks = 0; ks < 2; ks++) {
            uint32_t ah[4][4];
            #pragma unroll
            for (int mt = 0; mt < 4; mt++)
                ldsm4(ah[mt], sb + (warp_m + mt * 16 + arow) * ROWB
                              + ks * 32 + acol);
            uint32_t bh[4][4];
            #pragma unroll
            for (int np = 0; np < 4; np++)
                ldsm4(bh[np], sb + OFF_B + (warp_n + np * 16 + brow) * ROWB
                              + ks * 32 + bcol);
            #pragma unroll
            for (int mt = 0; mt < 4; mt++)
                #pragma unroll
                for (int nt = 0; nt < 8; nt++) {
                    const int np = nt >> 1, pp = (nt & 1) * 2;
                    mma16816(acc[mt][nt], ah[mt], bh[np][pp], bh[np][pp + 1]);
                }
        }
    }

    #pragma unroll
    for (int mt = 0; mt < 4; mt++) {
        const int row = m0 + warp_m + mt * 16 + (lane >> 2);
        #pragma unroll
        for (int nt = 0; nt < 8; nt++) {
            const int col = n0 + warp_n + nt * 8 + (lane & 3) * 2;
            const float b0 = bias[col], b1 = bias[col + 1];
            float2 lo = make_float2(acc[mt][nt][0] + b0, acc[mt][nt][1] + b1);
            float2 hi = make_float2(acc[mt][nt][2] + b0, acc[mt][nt][3] + b1);
            *(float2*)(C + (size_t)row * GN + col)       = lo;
            *(float2*)(C + (size_t)(row + 8) * GN + col) = hi;
        }
    }
}

// ---------------- compress (+ fused RoPE): X(b,l,h,:HD) @ Wc + bc -> fp16 ---
// 32 l-rows per block, 256 threads. grid (L/32, B*H)
template <int DO_ROPE>
__global__ void __launch_bounds__(256) compress_kernel(
    const float* __restrict__ X, const float* __restrict__ Wc,
    const float* __restrict__ bc, __half* __restrict__ Xc,
    const float* __restrict__ cosT, const float* __restrict__ sinT)
{
    __shared__ float Ws[HD][LD];
    __shared__ float xs[32][HD];
    const int bh = blockIdx.y;
    const int b = bh / H, h = bh % H;
    const int l0 = blockIdx.x * 32;
    const int tid = threadIdx.x;
    for (int i = tid; i < HD * LD; i += 256) Ws[i / LD][i % LD] = Wc[i];
    if (DO_ROPE) {
        for (int i = tid; i < 32 * 64; i += 256) {
            const int li = i >> 6, p = i & 63;
            const int l = l0 + li;
            float2 xv = *(const float2*)&X[
                ((size_t)((b * L + l) * H + h)) * HD + 2 * p];
            const float c = cosT[l * 64 + p];
            const float s = sinT[l * 64 + p];
            xs[li][2 * p]     = xv.x * c - xv.y * s;
            xs[li][2 * p + 1] = xv.x * s + xv.y * c;
        }
    } else {
        for (int i = tid; i < 32 * HD; i += 256) {
            const int li = i >> 7, d = i & 127;
            xs[li][d] = X[((size_t)((b * L + l0 + li) * H + h)) * HD + d];
        }
    }
    __syncthreads();
    const int row = tid >> 3;
    const int e0  = (tid & 7) * 4;
    float4 acc = *(const float4*)(bc + e0);
    #pragma unroll
    for (int d = 0; d < HD; d++) {
        const float xv = xs[row][d];
        const float4 w = *(const float4*)&Ws[d][e0];
        acc.x += xv * w.x; acc.y += xv * w.y;
        acc.z += xv * w.z; acc.w += xv * w.w;
    }
    __half2* dst = (__half2*)(Xc + ((size_t)bh * L + l0 + row) * LD + e0);
    dst[0] = __floats2half2_rn(acc.x, acc.y);
    dst[1] = __floats2half2_rn(acc.z, acc.w);
}

// ---------------- tensor-core causal flash attention ------------------------
// 64 queries/block, 4 warps x 16 rows. 64-key tiles. qc/kc/vc fp16 (b,h,l,32).
__global__ void __launch_bounds__(128) attn_kernel(
    const __half* __restrict__ qc, const __half* __restrict__ kc,
    const __half* __restrict__ vc, float* __restrict__ attn)
{
    __shared__ __half qs[64][40];   // 80B rows
    __shared__ __half ks[64][40];
    __shared__ __half vs[64][40];
    constexpr float SCALE = 0.17677669529663687f;  // 1/sqrt(32)

    const int bh  = blockIdx.y;
    const int q0  = (gridDim.x - 1 - blockIdx.x) * 64;   // long blocks first
    const int tid = threadIdx.x;
    const int w = tid >> 5, lane = tid & 31;

    const __half* bq = qc + ((size_t)bh * L + q0) * LD;
    const __half* bk = kc + (size_t)bh * L * LD;
    const __half* bv = vc + (size_t)bh * L * LD;

    for (int i = tid; i < 256; i += 128) {
        const int r = i >> 2, c = i & 3;
        *(uint4*)((char*)&qs[r][0] + c * 16) =
            *(const uint4*)((const char*)(bq + (size_t)r * LD) + c * 16);
    }
    __syncthreads();

    const uint32_t qs_b = smem_u32(qs);
    const uint32_t ks_b = smem_u32(ks);
    const uint32_t vs_b = smem_u32(vs);

    const int arow = ((lane >> 3) & 1) * 8 + (lane & 7);
    const int acol = (lane >> 4) * 16;
    const int brow = (lane >> 4) * 8 + (lane & 7);
    const int bcol = ((lane >> 3) & 1) * 16;

    uint32_t aq[2][4];
    #pragma unroll
    for (int ks2 = 0; ks2 < 2; ks2++)
        ldsm4(aq[ks2], qs_b + (w * 16 + arow) * 80 + ks2 * 32 + acol);

    float o[4][4];
    #pragma unroll
    for (int i = 0; i < 4; i++)
        #pragma unroll
        for (int j = 0; j < 4; j++) o[i][j] = 0.f;
    float m_lo = -INFINITY, m_hi = -INFINITY, l_lo = 0.f, l_hi = 0.f;

    const int nt = q0 / 64 + 1;
    const int row_lo = q0 + w * 16 + (lane >> 2);
    const int row_hi = row_lo + 8;

    for (int t = 0; t < nt; t++) {
        __syncthreads();
        for (int i = tid; i < 512; i += 128) {
            const int mtx = i >> 8;
            const int r = (i >> 2) & 63, c = i & 3;
            const __half* src = (mtx ? bv : bk) + ((size_t)(t * 64 + r)) * LD;
            __half* dst = mtx ? &vs[r][0] : &ks[r][0];
            *(uint4*)((char*)dst + c * 16) =
                *(const uint4*)((const char*)src + c * 16);
        }
        __syncthreads();

        float s[8][4];
        #pragma unroll
        for (int i = 0; i < 8; i++)
            #pragma unroll
            for (int j = 0; j < 4; j++) s[i][j] = 0.f;
        #pragma unroll
        for (int ks2 = 0; ks2 < 2; ks2++) {
            #pragma unroll
            for (int ng = 0; ng < 4; ng++) {
                uint32_t bkf[4];
                ldsm4(bkf, ks_b + (ng * 16 + brow) * 80 + ks2 * 32 + bcol);
                mma16816(s[ng * 2],     aq[ks2], bkf[0], bkf[1]);
                mma16816(s[ng * 2 + 1], aq[ks2], bkf[2], bkf[3]);
            }
        }

        const bool diag = (t == nt - 1);
        #pragma unroll
        for (int nf = 0; nf < 8; nf++) {
            const int col = t * 64 + nf * 8 + (lane & 3) * 2;
            #pragma unroll
            for (int j = 0; j < 4; j++) s[nf][j] *= SCALE;
            if (diag) {
                if (col     > row_lo) s[nf][0] = -INFINITY;
                if (col + 1 > row_lo) s[nf][1] = -INFINITY;
                if (col     > row_hi) s[nf][2] = -INFINITY;
                if (col + 1 > row_hi) s[nf][3] = -INFINITY;
            }
        }

        float tm_lo = -INFINITY, tm_hi = -INFINITY;
        #pragma unroll
        for (int nf = 0; nf < 8; nf++) {
            tm_lo = fmaxf(tm_lo, fmaxf(s[nf][0], s[nf][1]));
            tm_hi = fmaxf(tm_hi, fmaxf(s[nf][2], s[nf][3]));
        }
        #pragma unroll
        for (int off = 1; off <= 2; off <<= 1) {
            tm_lo = fmaxf(tm_lo, __shfl_xor_sync(0xffffffffu, tm_lo, off));
            tm_hi = fmaxf(tm_hi, __shfl_xor_sync(0xffffffffu, tm_hi, off));
        }
        const float mn_lo = fmaxf(m_lo, tm_lo);
        const float mn_hi = fmaxf(m_hi, tm_hi);
        const float al_lo = __expf(m_lo - mn_lo);
        const float al_hi = __expf(m_hi - mn_hi);
        m_lo = mn_lo; m_hi = mn_hi;

        float ps_lo = 0.f, ps_hi = 0.f;
        #pragma unroll
        for (int nf = 0; nf < 8; nf++) {
            s[nf][0] = __expf(s[nf][0] - mn_lo);
            s[nf][1] = __expf(s[nf][1] - mn_lo);
            s[nf][2] = __expf(s[nf][2] - mn_hi);
            s[nf][3] = __expf(s[nf][3] - mn_hi);
            ps_lo += s[nf][0] + s[nf][1];
            ps_hi += s[nf][2] + s[nf][3];
        }
        #pragma unroll
        for (int off = 1; off <= 2; off <<= 1) {
            ps_lo += __shfl_xor_sync(0xffffffffu, ps_lo, off);
            ps_hi += __shfl_xor_sync(0xffffffffu, ps_hi, off);
        }
        l_lo = l_lo * al_lo + ps_lo;
        l_hi = l_hi * al_hi + ps_hi;

        #pragma unroll
        for (int nf = 0; nf < 4; nf++) {
            o[nf][0] *= al_lo; o[nf][1] *= al_lo;
            o[nf][2] *= al_hi; o[nf][3] *= al_hi;
        }

        #pragma unroll
        for (int kc4 = 0; kc4 < 4; kc4++) {
            uint32_t ap[4];
            const int f0 = 2 * kc4, f1 = 2 * kc4 + 1;
            ap[0] = h2_u32(__floats2half2_rn(s[f0][0], s[f0][1]));
            ap[1] = h2_u32(__floats2half2_rn(s[f0][2], s[f0][3]));
            ap[2] = h2_u32(__floats2half2_rn(s[f1][0], s[f1][1]));
            ap[3] = h2_u32(__floats2half2_rn(s[f1][2], s[f1][3]));
            #pragma unroll
            for (int half = 0; half < 2; half++) {
                uint32_t bvf[4];
                ldsm4t(bvf, vs_b + (kc4 * 16 + arow) * 80 + half * 32 + acol);
                mma16816(o[half * 2],     ap, bvf[0], bvf[1]);
                mma16816(o[half * 2 + 1], ap, bvf[2], bvf[3]);
            }
        }
    }

    const int b = bh / H, h = bh % H;
    const float inv_lo = 1.f / l_lo, inv_hi = 1.f / l_hi;
    #pragma unroll
    for (int nf = 0; nf < 4; nf++) {
        const int e = nf * 8 + (lane & 3) * 2;
        float* p_lo = attn + ((size_t)(b * L + row_lo) * H + h) * LD + e;
        float* p_hi = attn + ((size_t)(b * L + row_hi) * H + h) * LD + e;
        *(float2*)p_lo = make_float2(o[nf][0] * inv_lo, o[nf][1] * inv_lo);
        *(float2*)p_hi = make_float2(o[nf][2] * inv_hi, o[nf][3] * inv_hi);
    }
}

// ---------------- decompress -> fp16 GEMM-A directly ------------------------
// rows(b,l,h) x LD @ Wd(LD,HD) + bd -> fp16 [BL, D]. 32 rows/block.
__global__ void __launch_bounds__(256) decompress_kernel(
    const float* __restrict__ Ac, const float* __restrict__ Wd,
    const float* __restrict__ bd, __half* __restrict__ Out)
{
    __shared__ float Ws[LD][HD];
    __shared__ float as[32][LD];
    const int r0 = blockIdx.x * 32;
    const int tid = threadIdx.x;
    for (int i = tid; i < LD * HD; i += 256) Ws[i / HD][i % HD] = Wd[i];
    for (int i = tid; i < 32 * LD; i += 256)
        as[i >> 5][i & 31] = Ac[(size_t)r0 * LD + i];
    __syncthreads();
    const int c0 = (tid & 31) * 4;
    const int rg = (tid >> 5) * 4;
    const float4 bv4 = *(const float4*)(bd + c0);
    float4 acc[4];
    #pragma unroll
    for (int i = 0; i < 4; i++) acc[i] = bv4;
    #pragma unroll
    for (int e = 0; e < LD; e++) {
        const float4 w = *(const float4*)&Ws[e][c0];
        #pragma unroll
        for (int i = 0; i < 4; i++) {
            const float a = as[rg + i][e];
            acc[i].x += a * w.x; acc[i].y += a * w.y;
            acc[i].z += a * w.z; acc[i].w += a * w.w;
        }
    }
    #pragma unroll
    for (int i = 0; i < 4; i++) {
        __half2* dst = (__half2*)(Out + (size_t)(r0 + rg + i) * HD + c0);
        dst[0] = __floats2half2_rn(acc[i].x, acc[i].y);
        dst[1] = __floats2half2_rn(acc[i].z, acc[i].w);
    }
}

// ---------------------------------------------------------------------------
extern "C" void kernel_launch(void* const* d_in, const int* in_sizes, int n_in,
                              void* d_out, int out_size)
{
    const float* x    = (const float*)d_in[0];
    const float* cosT = (const float*)d_in[1];
    const float* sinT = (const float*)d_in[2];
    const float* Wq   = (const float*)d_in[3];
    const float* bq   = (const float*)d_in[4];
    const float* Wk   = (const float*)d_in[5];
    const float* bk   = (const float*)d_in[6];
    const float* Wv   = (const float*)d_in[7];
    const float* bv   = (const float*)d_in[8];
    const float* Wqc  = (const float*)d_in[9];
    const float* bqc  = (const float*)d_in[10];
    const float* Wkc  = (const float*)d_in[11];
    const float* bkc  = (const float*)d_in[12];
    const float* Wvc  = (const float*)d_in[13];
    const float* bvc  = (const float*)d_in[14];
    const float* Wd   = (const float*)d_in[15];
    const float* bd   = (const float*)d_in[16];
    const float* Wo   = (const float*)d_in[17];
    const float* bo   = (const float*)d_in[18];
    float* out = (float*)d_out;

    float *q, *k, *v, *attn;
    __half *qch, *kch, *vch, *a16, *w16;
    cudaGetSymbolAddress((void**)&q,    g_q);
    cudaGetSymbolAddress((void**)&k,    g_k);
    cudaGetSymbolAddress((void**)&v,    g_v);
    cudaGetSymbolAddress((void**)&qch,  g_qch);
    cudaGetSymbolAddress((void**)&kch,  g_kch);
    cudaGetSymbolAddress((void**)&vch,  g_vch);
    cudaGetSymbolAddress((void**)&attn, g_attn);
    cudaGetSymbolAddress((void**)&a16,  g_a16);
    cudaGetSymbolAddress((void**)&w16,  g_w16);

    cudaFuncSetAttribute(hmma_gemm_kernel,
                         cudaFuncAttributeMaxDynamicSharedMemorySize, SMEMB);

    const int conv_a_blocks = (GM * GK / 4) / 256;       // 8192
    dim3 wgrid(GN / 32, GK / 32);                        // (64,64)
    dim3 wblk(32, 8);
    dim3 ggrid(GN / 128, GM / 256);                      // (16, 16)

    // --- Q/K/V projections (fp16 HMMA) ---
    convert_a_kernel<<<conv_a_blocks, 256>>>(x, a16);
    convert_wT_kernel<<<wgrid, wblk>>>(Wq, w16);
    hmma_gemm_kernel<<<ggrid, 256, SMEMB>>>(a16, w16, bq, q);
    convert_wT_kernel<<<wgrid, wblk>>>(Wk, w16);
    hmma_gemm_kernel<<<ggrid, 256, SMEMB>>>(a16, w16, bk, k);
    convert_wT_kernel<<<wgrid, wblk>>>(Wv, w16);
    hmma_gemm_kernel<<<ggrid, 256, SMEMB>>>(a16, w16, bv, v);

    // --- compress (+rope for q,k) ---
    dim3 cgrid(L / 32, B * H);
    compress_kernel<1><<<cgrid, 256>>>(q, Wqc, bqc, qch, cosT, sinT);
    compress_kernel<1><<<cgrid, 256>>>(k, Wkc, bkc, kch, cosT, sinT);
    compress_kernel<0><<<cgrid, 256>>>(v, Wvc, bvc, vch, cosT, sinT);

    dim3 agrid(L / 64, B * H);
    attn_kernel<<<agrid, 128>>>(qch, kch, vch, attn);

    decompress_kernel<<<(B * L * H) / 32, 256>>>(attn, Wd, bd, a16);

    // --- output projection ---
    convert_wT_kernel<<<wgrid, wblk>>>(Wo, w16);
    hmma_gemm_kernel<<<ggrid, 256, SMEMB>>>(a16, w16, bo, out);
}

// round 10
// speedup vs baseline: 7.0474x; 1.2497x over previous
#include <cuda_runtime.h>
#include <cuda_fp16.h>
#include <math.h>
#include <cstdint>

namespace {
constexpr int B  = 2;
constexpr int L  = 2048;
constexpr int D  = 2048;
constexpr int H  = 16;
constexpr int HD = 128;
constexpr int LD = 32;
constexpr int BL = B * L;                 // 4096
constexpr int BHLLD = B * H * L * LD;     // 2097152
constexpr int CD = H * LD;                // 512 compressed dim

constexpr int GM = BL;    // 4096
constexpr int GN = D;     // 2048

// HMMA GEMM tiling (256x128 CTA): 8 warps of 64x64, BK=32, 3 stages
constexpr int BK     = 32;
constexpr int STAGES = 3;
constexpr int ROWB   = 80;                 // smem row stride bytes
constexpr int OFF_B  = 256 * ROWB;         // B rows after 256 A rows
constexpr int STAGEB = 384 * ROWB;         // 30720 per stage
constexpr int SMEMB  = STAGES * STAGEB;    // 92160

// 128x128 CTA variant (for N=512 GEMM): 8 warps of 32x64
constexpr int OFF_B128  = 128 * ROWB;
constexpr int STAGEB128 = 256 * ROWB;      // 20480
constexpr int SMEMB128  = STAGES * STAGEB128;  // 61440
}

// ---------------- scratch (static device memory, no allocation) -------------
__device__ float  g_q[B * L * D];
__device__ float  g_k[B * L * D];
__device__ __half g_qch[BHLLD];      // compressed q/k/v, fp16, (b,h,l,e)
__device__ __half g_kch[BHLLD];
__device__ __half g_vch[BHLLD];
__device__ __half g_ao[BL * CD];     // attn out fp16, (b*l, h*32+e)
__device__ __half g_a16[GM * D];     // x fp16, [M,K]
__device__ __half g_wqk[2 * D * D];  // Wq,Wk fp16 TRANSPOSED [N=4096, K=2048]
__device__ __half g_wv[CD * D];      // Wveff fp16 [N=512, K=2048]
__device__ __half g_wo[D * CD];      // Weffo fp16 [N=2048, K=512]
__device__ float  g_bo[D];           // folded output bias
__device__ float  g_bv[CD];          // folded vc bias

// ================= PTX helpers ==============================================
__device__ __forceinline__ uint32_t smem_u32(const void* p) {
    uint32_t a;
    asm("{ .reg .u64 t; cvta.to.shared.u64 t, %1; cvt.u32.u64 %0, t; }"
        : "=r"(a) : "l"(p));
    return a;
}
__device__ __forceinline__ uint32_t h2_u32(__half2 h) {
    return *reinterpret_cast<uint32_t*>(&h);
}
__device__ __forceinline__ void cp_async16(uint32_t dst, const void* src) {
    asm volatile("cp.async.cg.shared.global [%0], [%1], 16;"
                 :: "r"(dst), "l"(src) : "memory");
}
__device__ __forceinline__ void cp_commit() {
    asm volatile("cp.async.commit_group;" ::: "memory");
}
template <int N>
__device__ __forceinline__ void cp_wait() {
    asm volatile("cp.async.wait_group %0;" :: "n"(N) : "memory");
}
__device__ __forceinline__ void ldsm4(uint32_t* r, uint32_t addr) {
    asm volatile("ldmatrix.sync.aligned.m8n8.x4.shared.b16 {%0,%1,%2,%3}, [%4];"
                 : "=r"(r[0]), "=r"(r[1]), "=r"(r[2]), "=r"(r[3]) : "r"(addr));
}
__device__ __forceinline__ void ldsm4t(uint32_t* r, uint32_t addr) {
    asm volatile("ldmatrix.sync.aligned.m8n8.x4.trans.shared.b16 {%0,%1,%2,%3}, [%4];"
                 : "=r"(r[0]), "=r"(r[1]), "=r"(r[2]), "=r"(r[3]) : "r"(addr));
}
__device__ __forceinline__ void mma16816(float* d, const uint32_t* a,
                                         uint32_t b0, uint32_t b1) {
    asm volatile(
        "mma.sync.aligned.m16n8k16.row.col.f32.f16.f16.f32 "
        "{%0,%1,%2,%3}, {%4,%5,%6,%7}, {%8,%9}, {%0,%1,%2,%3};"
        : "+f"(d[0]), "+f"(d[1]), "+f"(d[2]), "+f"(d[3])
        : "r"(a[0]), "r"(a[1]), "r"(a[2]), "r"(a[3]), "r"(b0), "r"(b1));
}

// ================= conversion / precompute kernels ==========================
__global__ void __launch_bounds__(256) convert_a_kernel(
    const float* __restrict__ X, __half* __restrict__ out)
{
    long long i = ((long long)blockIdx.x * 256 + threadIdx.x) * 4;
    float4 v = *(const float4*)(X + i);
    *(__half2*)(out + i)     = __floats2half2_rn(v.x, v.y);
    *(__half2*)(out + i + 2) = __floats2half2_rn(v.z, v.w);
}

// Wq/Wk [K,N] fp32 -> transposed [N,K] fp16 slabs. grid (N/32, K/32, 2)
__global__ void __launch_bounds__(256) convert_wqk_kernel(
    const float* __restrict__ Wq, const float* __restrict__ Wk,
    __half* __restrict__ w16)
{
    __shared__ float t[32][33];
    const float* W = blockIdx.z ? Wk : Wq;
    __half* dst = w16 + (size_t)blockIdx.z * D * D;
    const int n0 = blockIdx.x * 32, k0 = blockIdx.y * 32;
    const int tx = threadIdx.x, ty = threadIdx.y;
    #pragma unroll
    for (int r = ty; r < 32; r += 8)
        t[r][tx] = W[(size_t)(k0 + r) * GN + n0 + tx];
    __syncthreads();
    #pragma unroll
    for (int r = ty; r < 32; r += 8)
        dst[(size_t)(n0 + r) * D + k0 + tx] = __float2half_rn(t[tx][r]);
}

// Wveff[n=h*32+e][i] = sum_d Wv[i, h*128+d] * Wvc[d,e].  grid (2048/32, H)
__global__ void __launch_bounds__(256) prep_wv_kernel(
    const float* __restrict__ Wv, const float* __restrict__ Wvc,
    __half* __restrict__ w16v)
{
    __shared__ float Wcs[HD][LD];
    __shared__ float xs[32][HD];
    const int h = blockIdx.y, i0 = blockIdx.x * 32;
    const int tid = threadIdx.x;
    for (int i = tid; i < HD * LD; i += 256) Wcs[i / LD][i % LD] = Wvc[i];
    for (int i = tid; i < 32 * HD; i += 256) {
        const int il = i >> 7, d = i & 127;
        xs[il][d] = Wv[(size_t)(i0 + il) * D + h * HD + d];
    }
    __syncthreads();
    const int row = tid >> 3, e0 = (tid & 7) * 4;
    float4 acc = make_float4(0.f, 0.f, 0.f, 0.f);
    #pragma unroll
    for (int d = 0; d < HD; d++) {
        const float xv = xs[row][d];
        const float4 w = *(const float4*)&Wcs[d][e0];
        acc.x += xv * w.x; acc.y += xv * w.y;
        acc.z += xv * w.z; acc.w += xv * w.w;
    }
    const size_t base = (size_t)(h * LD + e0) * D + i0 + row;
    w16v[base]         = __float2half_rn(acc.x);
    w16v[base + D]     = __float2half_rn(acc.y);
    w16v[base + 2 * D] = __float2half_rn(acc.z);
    w16v[base + 3 * D] = __float2half_rn(acc.w);
}

// Weffo[n][h*32+e] = sum_d Wd[e,d] * Wo[h*128+d, n].  grid (2048/32, H)
__global__ void __launch_bounds__(256) prep_wo_kernel(
    const float* __restrict__ Wd, const float* __restrict__ Wo,
    __half* __restrict__ w16o)
{
    __shared__ float Wds[LD][133];
    __shared__ float Wos[HD][LD];
    const int h = blockIdx.y, n0 = blockIdx.x * 32;
    const int tid = threadIdx.x;
    for (int i = tid; i < LD * HD; i += 256) Wds[i >> 7][i & 127] = Wd[i];
    for (int i = tid; i < HD * LD; i += 256) {
        const int d = i >> 5, nl = i & 31;
        Wos[d][nl] = Wo[(size_t)(h * HD + d) * D + n0 + nl];
    }
    __syncthreads();
    const int nl = tid >> 3, e0 = (tid & 7) * 4;
    float acc[4] = {0.f, 0.f, 0.f, 0.f};
    #pragma unroll
    for (int d = 0; d < HD; d++) {
        const float wv = Wos[d][nl];
        #pragma unroll
        for (int j = 0; j < 4; j++) acc[j] += Wds[e0 + j][d] * wv;
    }
    #pragma unroll
    for (int j = 0; j < 4; j++)
        w16o[(size_t)(n0 + nl) * CD + h * LD + e0 + j] = __float2half_rn(acc[j]);
}

// bias_o[n] = sum_r bd[r%128]*Wo[r,n] + bo[n].  grid (2048/64), block 256
__global__ void __launch_bounds__(256) prep_bias_o_kernel(
    const float* __restrict__ bd, const float* __restrict__ Wo,
    const float* __restrict__ bo, float* __restrict__ bias_o)
{
    __shared__ float part[4][64];
    const int tid = threadIdx.x;
    const int n = blockIdx.x * 64 + (tid & 63);
    const int rp = tid >> 6;
    float acc = 0.f;
    for (int r = rp * 512; r < rp * 512 + 512; r++)
        acc += bd[r & 127] * Wo[(size_t)r * D + n];
    part[rp][tid & 63] = acc;
    __syncthreads();
    if (tid < 64)
        bias_o[n] = part[0][tid] + part[1][tid] + part[2][tid] + part[3][tid]
                  + bo[n];
}

// bveff[h*32+e] = sum_d bv[h*128+d]*Wvc[d,e] + bvc[e].  1 block, 256 threads
__global__ void __launch_bounds__(256) prep_bias_v_kernel(
    const float* __restrict__ bv, const float* __restrict__ Wvc,
    const float* __restrict__ bvc, float* __restrict__ bveff)
{
    for (int o = threadIdx.x; o < CD; o += 256) {
        const int h = o >> 5, e = o & 31;
        float acc = bvc[e];
        for (int d = 0; d < HD; d++)
            acc += bv[h * HD + d] * Wvc[d * LD + e];
        bveff[o] = acc;
    }
}

// ================= 256x128 HMMA GEMM (templated K, optional dual out) =======
template <int KDIM>
__device__ __forceinline__ void load_stage256(
    uint32_t sbase, const __half* pA, const __half* pB, int kc, int tid)
{
    const int r0 = tid >> 2, seg = tid & 3;
    const uint32_t so = sbase + r0 * ROWB + seg * 16;
    const size_t go = (size_t)r0 * KDIM + kc + seg * 8;
    #pragma unroll
    for (int j = 0; j < 4; j++)
        cp_async16(so + j * 64 * ROWB, pA + go + (size_t)j * 64 * KDIM);
    #pragma unroll
    for (int j = 0; j < 2; j++)
        cp_async16(so + (256 + j * 64) * ROWB, pB + go + (size_t)j * 64 * KDIM);
}

template <int KDIM, bool DUAL>
__global__ void __launch_bounds__(256) hmma_gemm256_kernel(
    const __half* __restrict__ A16, const __half* __restrict__ Bw,
    const float* __restrict__ bias0, const float* __restrict__ bias1,
    float* __restrict__ C0, float* __restrict__ C1)
{
    constexpr int NITL = KDIM / BK;
    extern __shared__ char smem[];
    const uint32_t sb0 = smem_u32(smem);
    const int tid = threadIdx.x, wid = tid >> 5, lane = tid & 31;
    const int warp_m = (wid & 3) * 64;
    const int warp_n = (wid >> 2) * 64;
    const int m0 = blockIdx.y * 256;
    const int n0 = blockIdx.x * 128;

    const __half* pA = A16 + (size_t)m0 * KDIM;
    const __half* pB = Bw  + (size_t)n0 * KDIM;
    float* C = C0; const float* bias = bias0; int nc0 = n0;
    if (DUAL && n0 >= D) { C = C1; bias = bias1; nc0 = n0 - D; }

    float acc[4][8][4];
    #pragma unroll
    for (int i = 0; i < 4; i++)
        #pragma unroll
        for (int j = 0; j < 8; j++)
            #pragma unroll
            for (int t = 0; t < 4; t++) acc[i][j][t] = 0.f;

    const int arow = ((lane >> 3) & 1) * 8 + (lane & 7);
    const int acol = (lane >> 4) * 16;
    const int brow = (lane >> 4) * 8 + (lane & 7);
    const int bcol = ((lane >> 3) & 1) * 16;

    load_stage256<KDIM>(sb0, pA, pB, 0, tid);
    cp_commit();
    load_stage256<KDIM>(sb0 + STAGEB, pA, pB, BK, tid);
    cp_commit();

    #pragma unroll 1
    for (int kt = 0; kt < NITL; kt++) {
        cp_wait<1>();
        __syncthreads();
        if (kt + 2 < NITL)
            load_stage256<KDIM>(sb0 + ((kt + 2) % STAGES) * STAGEB,
                                pA, pB, (kt + 2) * BK, tid);
        cp_commit();

        const uint32_t sb = sb0 + (kt % STAGES) * STAGEB;
        #pragma unroll
        for (int ks = 0; ks < 2; ks++) {
            uint32_t ah[4][4];
            #pragma unroll
            for (int mt = 0; mt < 4; mt++)
                ldsm4(ah[mt], sb + (warp_m + mt * 16 + arow) * ROWB
                              + ks * 32 + acol);
            uint32_t bh[4][4];
            #pragma unroll
            for (int np = 0; np < 4; np++)
                ldsm4(bh[np], sb + OFF_B + (warp_n + np * 16 + brow) * ROWB
                              + ks * 32 + bcol);
            #pragma unroll
            for (int mt = 0; mt < 4; mt++)
                #pragma unroll
                for (int nt = 0; nt < 8; nt++) {
                    const int np = nt >> 1, pp = (nt & 1) * 2;
                    mma16816(acc[mt][nt], ah[mt], bh[np][pp], bh[np][pp + 1]);
                }
        }
    }

    #pragma unroll
    for (int mt = 0; mt < 4; mt++) {
        const int row = m0 + warp_m + mt * 16 + (lane >> 2);
        #pragma unroll
        for (int nt = 0; nt < 8; nt++) {
            const int col = nc0 + warp_n + nt * 8 + (lane & 3) * 2;
            const float b0 = bias[col], b1 = bias[col + 1];
            float2 lo = make_float2(acc[mt][nt][0] + b0, acc[mt][nt][1] + b1);
            float2 hi = make_float2(acc[mt][nt][2] + b0, acc[mt][nt][3] + b1);
            *(float2*)(C + (size_t)row * D + col)       = lo;
            *(float2*)(C + (size_t)(row + 8) * D + col) = hi;
        }
    }
}

// ================= 128x128 GEMM -> vc fp16 (b,h,l,e) ========================
__global__ void __launch_bounds__(256) gemm_vc_kernel(
    const __half* __restrict__ A16, const __half* __restrict__ Bw,
    const float* __restrict__ bveff, __half* __restrict__ vch)
{
    constexpr int KDIM = D;
    constexpr int NITL = KDIM / BK;
    extern __shared__ char smem[];
    const uint32_t sb0 = smem_u32(smem);
    const int tid = threadIdx.x, wid = tid >> 5, lane = tid & 31;
    const int warp_m = (wid & 3) * 32;
    const int warp_n = (wid >> 2) * 64;
    const int m0 = blockIdx.y * 128;
    const int n0 = blockIdx.x * 128;

    const __half* pA = A16 + (size_t)m0 * KDIM;
    const __half* pB = Bw  + (size_t)n0 * KDIM;

    float acc[2][8][4];
    #pragma unroll
    for (int i = 0; i < 2; i++)
        #pragma unroll
        for (int j = 0; j < 8; j++)
            #pragma unroll
            for (int t = 0; t < 4; t++) acc[i][j][t] = 0.f;

    const int arow = ((lane >> 3) & 1) * 8 + (lane & 7);
    const int acol = (lane >> 4) * 16;
    const int brow = (lane >> 4) * 8 + (lane & 7);
    const int bcol = ((lane >> 3) & 1) * 16;

    auto load_stage = [&](uint32_t sbase, int kc) {
        const int r0 = tid >> 2, seg = tid & 3;
        const uint32_t so = sbase + r0 * ROWB + seg * 16;
        const size_t go = (size_t)r0 * KDIM + kc + seg * 8;
        #pragma unroll
        for (int j = 0; j < 2; j++)
            cp_async16(so + j * 64 * ROWB, pA + go + (size_t)j * 64 * KDIM);
        #pragma unroll
        for (int j = 0; j < 2; j++)
            cp_async16(so + (128 + j * 64) * ROWB,
                       pB + go + (size_t)j * 64 * KDIM);
    };

    load_stage(sb0, 0);
    cp_commit();
    load_stage(sb0 + STAGEB128, BK);
    cp_commit();

    #pragma unroll 1
    for (int kt = 0; kt < NITL; kt++) {
        cp_wait<1>();
        __syncthreads();
        if (kt + 2 < NITL)
            load_stage(sb0 + ((kt + 2) % STAGES) * STAGEB128, (kt + 2) * BK);
        cp_commit();

        const uint32_t sb = sb0 + (kt % STAGES) * STAGEB128;
        #pragma unroll
        for (int ks = 0; ks < 2; ks++) {
            uint32_t ah[2][4];
            #pragma unroll
            for (int mt = 0; mt < 2; mt++)
                ldsm4(ah[mt], sb + (warp_m + mt * 16 + arow) * ROWB
                              + ks * 32 + acol);
            uint32_t bh[4][4];
            #pragma unroll
            for (int np = 0; np < 4; np++)
                ldsm4(bh[np], sb + OFF_B128 + (warp_n + np * 16 + brow) * ROWB
                              + ks * 32 + bcol);
            #pragma unroll
            for (int mt = 0; mt < 2; mt++)
                #pragma unroll
                for (int nt = 0; nt < 8; nt++) {
                    const int np = nt >> 1, pp = (nt & 1) * 2;
                    mma16816(acc[mt][nt], ah[mt], bh[np][pp], bh[np][pp + 1]);
                }
        }
    }

    // epilogue: write fp16 to (b,h,l,e)
    #pragma unroll
    for (int mt = 0; mt < 2; mt++) {
        const int row = m0 + warp_m + mt * 16 + (lane >> 2);
        const int b0i = row >> 11, l0i = row & 2047;
        const int b1i = (row + 8) >> 11, l1i = (row + 8) & 2047;
        #pragma unroll
        for (int nt = 0; nt < 8; nt++) {
            const int col = n0 + warp_n + nt * 8 + (lane & 3) * 2;
            const int h = col >> 5, e = col & 31;
            const float bb0 = bveff[col], bb1 = bveff[col + 1];
            *(__half2*)(vch + ((size_t)(b0i * H + h) * L + l0i) * LD + e) =
                __floats2half2_rn(acc[mt][nt][0] + bb0, acc[mt][nt][1] + bb1);
            *(__half2*)(vch + ((size_t)(b1i * H + h) * L + l1i) * LD + e) =
                __floats2half2_rn(acc[mt][nt][2] + bb0, acc[mt][nt][3] + bb1);
        }
    }
}

// ---------------- compress (+ fused RoPE): X(b,l,h,:HD) @ Wc + bc -> fp16 ---
__global__ void __launch_bounds__(256) compress_kernel(
    const float* __restrict__ X, const float* __restrict__ Wc,
    const float* __restrict__ bc, __half* __restrict__ Xc,
    const float* __restrict__ cosT, const float* __restrict__ sinT)
{
    __shared__ float Ws[HD][LD];
    __shared__ float xs[32][HD];
    const int bh = blockIdx.y;
    const int b = bh / H, h = bh % H;
    const int l0 = blockIdx.x * 32;
    const int tid = threadIdx.x;
    for (int i = tid; i < HD * LD; i += 256) Ws[i / LD][i % LD] = Wc[i];
    for (int i = tid; i < 32 * 64; i += 256) {
        const int li = i >> 6, p = i & 63;
        const int l = l0 + li;
        float2 xv = *(const float2*)&X[
            ((size_t)((b * L + l) * H + h)) * HD + 2 * p];
        const float c = cosT[l * 64 + p];
        const float s = sinT[l * 64 + p];
        xs[li][2 * p]     = xv.x * c - xv.y * s;
        xs[li][2 * p + 1] = xv.x * s + xv.y * c;
    }
    __syncthreads();
    const int row = tid >> 3;
    const int e0  = (tid & 7) * 4;
    float4 acc = *(const float4*)(bc + e0);
    #pragma unroll
    for (int d = 0; d < HD; d++) {
        const float xv = xs[row][d];
        const float4 w = *(const float4*)&Ws[d][e0];
        acc.x += xv * w.x; acc.y += xv * w.y;
        acc.z += xv * w.z; acc.w += xv * w.w;
    }
    __half2* dst = (__half2*)(Xc + ((size_t)bh * L + l0 + row) * LD + e0);
    dst[0] = __floats2half2_rn(acc.x, acc.y);
    dst[1] = __floats2half2_rn(acc.z, acc.w);
}

// ---------------- tensor-core causal flash attention ------------------------
// 64 queries/block, 4 warps x 16 rows. 64-key tiles. out fp16 (b*l, h*32+e).
__global__ void __launch_bounds__(128) attn_kernel(
    const __half* __restrict__ qc, const __half* __restrict__ kc,
    const __half* __restrict__ vc, __half* __restrict__ ao)
{
    __shared__ __half qs[64][40];
    __shared__ __half ks[64][40];
    __shared__ __half vs[64][40];
    constexpr float SCALE = 0.17677669529663687f;  // 1/sqrt(32)

    const int bh  = blockIdx.y;
    const int q0  = (gridDim.x - 1 - blockIdx.x) * 64;
    const int tid = threadIdx.x;
    const int w = tid >> 5, lane = tid & 31;

    const __half* bq = qc + ((size_t)bh * L + q0) * LD;
    const __half* bk = kc + (size_t)bh * L * LD;
    const __half* bv = vc + (size_t)bh * L * LD;

    for (int i = tid; i < 256; i += 128) {
        const int r = i >> 2, c = i & 3;
        *(uint4*)((char*)&qs[r][0] + c * 16) =
            *(const uint4*)((const char*)(bq + (size_t)r * LD) + c * 16);
    }
    __syncthreads();

    const uint32_t qs_b = smem_u32(qs);
    const uint32_t ks_b = smem_u32(ks);
    const uint32_t vs_b = smem_u32(vs);

    const int arow = ((lane >> 3) & 1) * 8 + (lane & 7);
    const int acol = (lane >> 4) * 16;
    const int brow = (lane >> 4) * 8 + (lane & 7);
    const int bcol = ((lane >> 3) & 1) * 16;

    uint32_t aq[2][4];
    #pragma unroll
    for (int ks2 = 0; ks2 < 2; ks2++)
        ldsm4(aq[ks2], qs_b + (w * 16 + arow) * 80 + ks2 * 32 + acol);

    float o[4][4];
    #pragma unroll
    for (int i = 0; i < 4; i++)
        #pragma unroll
        for (int j = 0; j < 4; j++) o[i][j] = 0.f;
    float m_lo = -INFINITY, m_hi = -INFINITY, l_lo = 0.f, l_hi = 0.f;

    const int nt = q0 / 64 + 1;
    const int row_lo = q0 + w * 16 + (lane >> 2);
    const int row_hi = row_lo + 8;

    for (int t = 0; t < nt; t++) {
        __syncthreads();
        for (int i = tid; i < 512; i += 128) {
            const int mtx = i >> 8;
            const int r = (i >> 2) & 63, c = i & 3;
            const __half* src = (mtx ? bv : bk) + ((size_t)(t * 64 + r)) * LD;
            __half* dst = mtx ? &vs[r][0] : &ks[r][0];
            *(uint4*)((char*)dst + c * 16) =
                *(const uint4*)((const char*)src + c * 16);
        }
        __syncthreads();

        float s[8][4];
        #pragma unroll
        for (int i = 0; i < 8; i++)
            #pragma unroll
            for (int j = 0; j < 4; j++) s[i][j] = 0.f;
        #pragma unroll
        for (int ks2 = 0; ks2 < 2; ks2++) {
            #pragma unroll
            for (int ng = 0; ng < 4; ng++) {
                uint32_t bkf[4];
                ldsm4(bkf, ks_b + (ng * 16 + brow) * 80 + ks2 * 32 + bcol);
                mma16816(s[ng * 2],     aq[ks2], bkf[0], bkf[1]);
                mma16816(s[ng * 2 + 1], aq[ks2], bkf[2], bkf[3]);
            }
        }

        const bool diag = (t == nt - 1);
        #pragma unroll
        for (int nf = 0; nf < 8; nf++) {
            const int col = t * 64 + nf * 8 + (lane & 3) * 2;
            #pragma unroll
            for (int j = 0; j < 4; j++) s[nf][j] *= SCALE;
            if (diag) {
                if (col     > row_lo) s[nf][0] = -INFINITY;
                if (col + 1 > row_lo) s[nf][1] = -INFINITY;
                if (col     > row_hi) s[nf][2] = -INFINITY;
                if (col + 1 > row_hi) s[nf][3] = -INFINITY;
            }
        }

        float tm_lo = -INFINITY, tm_hi = -INFINITY;
        #pragma unroll
        for (int nf = 0; nf < 8; nf++) {
            tm_lo = fmaxf(tm_lo, fmaxf(s[nf][0], s[nf][1]));
            tm_hi = fmaxf(tm_hi, fmaxf(s[nf][2], s[nf][3]));
        }
        #pragma unroll
        for (int off = 1; off <= 2; off <<= 1) {
            tm_lo = fmaxf(tm_lo, __shfl_xor_sync(0xffffffffu, tm_lo, off));
            tm_hi = fmaxf(tm_hi, __shfl_xor_sync(0xffffffffu, tm_hi, off));
        }
        const float mn_lo = fmaxf(m_lo, tm_lo);
        const float mn_hi = fmaxf(m_hi, tm_hi);
        const float al_lo = __expf(m_lo - mn_lo);
        const float al_hi = __expf(m_hi - mn_hi);
        m_lo = mn_lo; m_hi = mn_hi;

        float ps_lo = 0.f, ps_hi = 0.f;
        #pragma unroll
        for (int nf = 0; nf < 8; nf++) {
            s[nf][0] = __expf(s[nf][0] - mn_lo);
            s[nf][1] = __expf(s[nf][1] - mn_lo);
            s[nf][2] = __expf(s[nf][2] - mn_hi);
            s[nf][3] = __expf(s[nf][3] - mn_hi);
            ps_lo += s[nf][0] + s[nf][1];
            ps_hi += s[nf][2] + s[nf][3];
        }
        #pragma unroll
        for (int off = 1; off <= 2; off <<= 1) {
            ps_lo += __shfl_xor_sync(0xffffffffu, ps_lo, off);
            ps_hi += __shfl_xor_sync(0xffffffffu, ps_hi, off);
        }
        l_lo = l_lo * al_lo + ps_lo;
        l_hi = l_hi * al_hi + ps_hi;

        #pragma unroll
        for (int nf = 0; nf < 4; nf++) {
            o[nf][0] *= al_lo; o[nf][1] *= al_lo;
            o[nf][2] *= al_hi; o[nf][3] *= al_hi;
        }

        #pragma unroll
        for (int kc4 = 0; kc4 < 4; kc4++) {
            uint32_t ap[4];
            const int f0 = 2 * kc4, f1 = 2 * kc4 + 1;
            ap[0] = h2_u32(__floats2half2_rn(s[f0][0], s[f0][1]));
            ap[1] = h2_u32(__floats2half2_rn(s[f0][2], s[f0][3]));
            ap[2] = h2_u32(__floats2half2_rn(s[f1][0], s[f1][1]));
            ap[3] = h2_u32(__floats2half2_rn(s[f1][2], s[f1][3]));
            #pragma unroll
            for (int half = 0; half < 2; half++) {
                uint32_t bvf[4];
                ldsm4t(bvf, vs_b + (kc4 * 16 + arow) * 80 + half * 32 + acol);
                mma16816(o[half * 2],     ap, bvf[0], bvf[1]);
                mma16816(o[half * 2 + 1], ap, bvf[2], bvf[3]);
            }
        }
    }

    const int b = bh / H, h = bh % H;
    const float inv_lo = 1.f / l_lo, inv_hi = 1.f / l_hi;
    #pragma unroll
    for (int nf = 0; nf < 4; nf++) {
        const int e = nf * 8 + (lane & 3) * 2;
        __half* p_lo = ao + (size_t)(b * L + row_lo) * CD + h * LD + e;
        __half* p_hi = ao + (size_t)(b * L + row_hi) * CD + h * LD + e;
        *(__half2*)p_lo = __floats2half2_rn(o[nf][0] * inv_lo, o[nf][1] * inv_lo);
        *(__half2*)p_hi = __floats2half2_rn(o[nf][2] * inv_hi, o[nf][3] * inv_hi);
    }
}

// ---------------------------------------------------------------------------
extern "C" void kernel_launch(void* const* d_in, const int* in_sizes, int n_in,
                              void* d_out, int out_size)
{
    const float* x    = (const float*)d_in[0];
    const float* cosT = (const float*)d_in[1];
    const float* sinT = (const float*)d_in[2];
    const float* Wq   = (const float*)d_in[3];
    const float* bq   = (const float*)d_in[4];
    const float* Wk   = (const float*)d_in[5];
    const float* bk   = (const float*)d_in[6];
    const float* Wv   = (const float*)d_in[7];
    const float* bv   = (const float*)d_in[8];
    const float* Wqc  = (const float*)d_in[9];
    const float* bqc  = (const float*)d_in[10];
    const float* Wkc  = (const float*)d_in[11];
    const float* bkc  = (const float*)d_in[12];
    const float* Wvc  = (const float*)d_in[13];
    const float* bvc  = (const float*)d_in[14];
    const float* Wd   = (const float*)d_in[15];
    const float* bd   = (const float*)d_in[16];
    const float* Wo   = (const float*)d_in[17];
    const float* bo   = (const float*)d_in[18];
    float* out = (float*)d_out;

    float *q, *k, *bias_o, *bveff;
    __half *qch, *kch, *vch, *ao, *a16, *wqk, *wv, *wo;
    cudaGetSymbolAddress((void**)&q,      g_q);
    cudaGetSymbolAddress((void**)&k,      g_k);
    cudaGetSymbolAddress((void**)&qch,    g_qch);
    cudaGetSymbolAddress((void**)&kch,    g_kch);
    cudaGetSymbolAddress((void**)&vch,    g_vch);
    cudaGetSymbolAddress((void**)&ao,     g_ao);
    cudaGetSymbolAddress((void**)&a16,    g_a16);
    cudaGetSymbolAddress((void**)&wqk,    g_wqk);
    cudaGetSymbolAddress((void**)&wv,     g_wv);
    cudaGetSymbolAddress((void**)&wo,     g_wo);
    cudaGetSymbolAddress((void**)&bias_o, g_bo);
    cudaGetSymbolAddress((void**)&bveff,  g_bv);

    cudaFuncSetAttribute(hmma_gemm256_kernel<D, true>,
                         cudaFuncAttributeMaxDynamicSharedMemorySize, SMEMB);
    cudaFuncSetAttribute(hmma_gemm256_kernel<CD, false>,
                         cudaFuncAttributeMaxDynamicSharedMemorySize, SMEMB);
    cudaFuncSetAttribute(gemm_vc_kernel,
                         cudaFuncAttributeMaxDynamicSharedMemorySize, SMEMB128);

    // --- conversions + weight folding ---
    convert_a_kernel<<<(GM * D / 4) / 256, 256>>>(x, a16);
    convert_wqk_kernel<<<dim3(D / 32, D / 32, 2), dim3(32, 8)>>>(Wq, Wk, wqk);
    prep_wv_kernel<<<dim3(D / 32, H), 256>>>(Wv, Wvc, wv);
    prep_wo_kernel<<<dim3(D / 32, H), 256>>>(Wd, Wo, wo);
    prep_bias_o_kernel<<<D / 64, 256>>>(bd, Wo, bo, bias_o);
    prep_bias_v_kernel<<<1, 256>>>(bv, Wvc, bvc, bveff);

    // --- Q,K projections (dual-output GEMM) ---
    hmma_gemm256_kernel<D, true><<<dim3(2 * D / 128, GM / 256), 256, SMEMB>>>(
        a16, wqk, bq, bk, q, k);

    // --- V projection+compress folded ---
    gemm_vc_kernel<<<dim3(CD / 128, GM / 128), 256, SMEMB128>>>(
        a16, wv, bveff, vch);

    // --- compress + rope for q,k ---
    dim3 cgrid(L / 32, B * H);
    compress_kernel<<<cgrid, 256>>>(q, Wqc, bqc, qch, cosT, sinT);
    compress_kernel<<<cgrid, 256>>>(k, Wkc, bkc, kch, cosT, sinT);

    // --- attention ---
    attn_kernel<<<dim3(L / 64, B * H), 128>>>(qch, kch, vch, ao);

    // --- decompress+output projection folded ---
    hmma_gemm256_kernel<CD, false><<<dim3(D / 128, GM / 256), 256, SMEMB>>>(
        ao, wo, bias_o, bias_o, out, out);
}

// round 11
// speedup vs baseline: 7.6773x; 1.0894x over previous
#include <cuda_runtime.h>
#include <cuda_fp16.h>
#include <math.h>
#include <cstdint>

namespace {
constexpr int B  = 2;
constexpr int L  = 2048;
constexpr int D  = 2048;
constexpr int H  = 16;
constexpr int HD = 128;
constexpr int LD = 32;
constexpr int BL = B * L;                 // 4096
constexpr int BHLLD = B * H * L * LD;     // 2097152
constexpr int CD = H * LD;                // 512
constexpr int GM = BL;                    // 4096
constexpr int NB = 2 * D + CD;            // 4608 total B rows (Wq|Wk|Wveff)

constexpr int BK     = 32;
constexpr int STAGES = 3;
constexpr int ROWB   = 80;
constexpr int OFF_B  = 256 * ROWB;
constexpr int STAGEB = 384 * ROWB;        // 30720
constexpr int SMEMB  = STAGES * STAGEB;   // 92160
}

// ---------------- scratch ----------------------------------------------------
__device__ float  g_q[B * L * D];
__device__ float  g_k[B * L * D];
__device__ __half g_qch[BHLLD];      // (b,h,l,e)
__device__ __half g_kch[BHLLD];
__device__ __half g_vch[BHLLD];
__device__ __half g_ao[BL * CD];     // attn out fp16 (b*l, h*32+e)
__device__ __half g_a16[GM * D];     // x fp16 [M,K]
__device__ __half g_wB[(size_t)NB * D];  // Wq|Wk|Wveff fp16 [N,K]
__device__ __half g_wo[D * CD];      // Weffo fp16 [N=2048, K=512]
__device__ float  g_bo[D];
__device__ float  g_bv[CD];

// ================= PTX helpers ==============================================
__device__ __forceinline__ uint32_t smem_u32(const void* p) {
    uint32_t a;
    asm("{ .reg .u64 t; cvta.to.shared.u64 t, %1; cvt.u32.u64 %0, t; }"
        : "=r"(a) : "l"(p));
    return a;
}
__device__ __forceinline__ uint32_t h2_u32(__half2 h) {
    return *reinterpret_cast<uint32_t*>(&h);
}
__device__ __forceinline__ void cp_async16(uint32_t dst, const void* src) {
    asm volatile("cp.async.cg.shared.global [%0], [%1], 16;"
                 :: "r"(dst), "l"(src) : "memory");
}
__device__ __forceinline__ void cp_commit() {
    asm volatile("cp.async.commit_group;" ::: "memory");
}
template <int N>
__device__ __forceinline__ void cp_wait() {
    asm volatile("cp.async.wait_group %0;" :: "n"(N) : "memory");
}
__device__ __forceinline__ void ldsm4(uint32_t* r, uint32_t addr) {
    asm volatile("ldmatrix.sync.aligned.m8n8.x4.shared.b16 {%0,%1,%2,%3}, [%4];"
                 : "=r"(r[0]), "=r"(r[1]), "=r"(r[2]), "=r"(r[3]) : "r"(addr));
}
__device__ __forceinline__ void ldsm4t(uint32_t* r, uint32_t addr) {
    asm volatile("ldmatrix.sync.aligned.m8n8.x4.trans.shared.b16 {%0,%1,%2,%3}, [%4];"
                 : "=r"(r[0]), "=r"(r[1]), "=r"(r[2]), "=r"(r[3]) : "r"(addr));
}
__device__ __forceinline__ void mma16816(float* d, const uint32_t* a,
                                         uint32_t b0, uint32_t b1) {
    asm volatile(
        "mma.sync.aligned.m16n8k16.row.col.f32.f16.f16.f32 "
        "{%0,%1,%2,%3}, {%4,%5,%6,%7}, {%8,%9}, {%0,%1,%2,%3};"
        : "+f"(d[0]), "+f"(d[1]), "+f"(d[2]), "+f"(d[3])
        : "r"(a[0]), "r"(a[1]), "r"(a[2]), "r"(a[3]), "r"(b0), "r"(b1));
}

// ================= conversion / precompute ==================================
__global__ void __launch_bounds__(256) convert_a_kernel(
    const float* __restrict__ X, __half* __restrict__ out)
{
    long long i = ((long long)blockIdx.x * 256 + threadIdx.x) * 4;
    float4 v = *(const float4*)(X + i);
    *(__half2*)(out + i)     = __floats2half2_rn(v.x, v.y);
    *(__half2*)(out + i + 2) = __floats2half2_rn(v.z, v.w);
}

// Wq/Wk [K,N] -> transposed [N,K] fp16 into wB. grid (D/32, D/64, 2), blk (32,8)
__global__ void __launch_bounds__(256) convert_wqk_kernel(
    const float* __restrict__ Wq, const float* __restrict__ Wk,
    __half* __restrict__ wB)
{
    __shared__ float t[64][33];
    const float* W = blockIdx.z ? Wk : Wq;
    __half* dst = wB + (size_t)blockIdx.z * D * D;
    const int n0 = blockIdx.x * 32, k0 = blockIdx.y * 64;
    const int tx = threadIdx.x, ty = threadIdx.y;
    #pragma unroll
    for (int i = 0; i < 8; i++)
        t[ty + i * 8][tx] = W[(size_t)(k0 + ty + i * 8) * D + n0 + tx];
    __syncthreads();
    #pragma unroll
    for (int i = 0; i < 4; i++) {
        const int nr = ty + i * 8;
        *(__half2*)(dst + (size_t)(n0 + nr) * D + k0 + 2 * tx) =
            __floats2half2_rn(t[2 * tx][nr], t[2 * tx + 1][nr]);
    }
}

// Wveff[he][i] = sum_d Wv[i, h*128+d]*Wvc[d,e]  -> wB rows 4096+he.
// grid (D/32, H), 128 threads, 4e x 2i register tile, float4 dots.
__global__ void __launch_bounds__(128) prep_wv_kernel(
    const float* __restrict__ Wv, const float* __restrict__ Wvc,
    __half* __restrict__ w16v)
{
    __shared__ float Wvs[32][132];   // [i][d]
    __shared__ float Wcs[32][132];   // [e][d]
    const int h = blockIdx.y, i0 = blockIdx.x * 32;
    const int tid = threadIdx.x;
    for (int idx = tid; idx < 32 * 32; idx += 128) {
        const int il = idx >> 5, dq = idx & 31;
        *(float4*)&Wvs[il][dq * 4] =
            *(const float4*)(Wv + (size_t)(i0 + il) * D + h * HD + dq * 4);
    }
    for (int idx = tid; idx < 32 * 128; idx += 128)
        Wcs[idx & 31][idx >> 5] = Wvc[idx];
    __syncthreads();
    const int e0  = (tid & 7) * 4;
    const int il0 = (tid >> 3) * 2;
    float acc[4][2] = {};
    #pragma unroll 4
    for (int d = 0; d < HD; d += 4) {
        const float4 b0 = *(const float4*)&Wvs[il0][d];
        const float4 b1 = *(const float4*)&Wvs[il0 + 1][d];
        #pragma unroll
        for (int j = 0; j < 4; j++) {
            const float4 a = *(const float4*)&Wcs[e0 + j][d];
            acc[j][0] += a.x * b0.x + a.y * b0.y + a.z * b0.z + a.w * b0.w;
            acc[j][1] += a.x * b1.x + a.y * b1.y + a.z * b1.z + a.w * b1.w;
        }
    }
    #pragma unroll
    for (int j = 0; j < 4; j++)
        #pragma unroll
        for (int i = 0; i < 2; i++)
            w16v[(size_t)(h * LD + e0 + j) * D + i0 + il0 + i] =
                __float2half_rn(acc[j][i]);
}

// Weffo[n][he] = sum_d Wd[e*128+d]*Wo[(h*128+d)*D+n]. grid (D/32, H), 128 thr.
__global__ void __launch_bounds__(128) prep_wo_kernel(
    const float* __restrict__ Wd, const float* __restrict__ Wo,
    __half* __restrict__ w16o)
{
    __shared__ float Wds[32][132];   // [e][d]
    __shared__ float Wos[32][132];   // [n][d]
    const int h = blockIdx.y, n0 = blockIdx.x * 32;
    const int tid = threadIdx.x;
    for (int idx = tid; idx < 32 * 32; idx += 128) {
        const int e = idx >> 5, dq = idx & 31;
        *(float4*)&Wds[e][dq * 4] = *(const float4*)(Wd + e * HD + dq * 4);
    }
    for (int idx = tid; idx < 32 * 128; idx += 128) {
        const int d = idx >> 5, nl = idx & 31;
        Wos[nl][d] = Wo[(size_t)(h * HD + d) * D + n0 + nl];
    }
    __syncthreads();
    const int e0  = (tid & 7) * 4;
    const int nl0 = (tid >> 3) * 2;
    float acc[4][2] = {};
    #pragma unroll 4
    for (int d = 0; d < HD; d += 4) {
        const float4 b0 = *(const float4*)&Wos[nl0][d];
        const float4 b1 = *(const float4*)&Wos[nl0 + 1][d];
        #pragma unroll
        for (int j = 0; j < 4; j++) {
            const float4 a = *(const float4*)&Wds[e0 + j][d];
            acc[j][0] += a.x * b0.x + a.y * b0.y + a.z * b0.z + a.w * b0.w;
            acc[j][1] += a.x * b1.x + a.y * b1.y + a.z * b1.z + a.w * b1.w;
        }
    }
    #pragma unroll
    for (int i = 0; i < 2; i++) {
        __half2* dst =
            (__half2*)(w16o + (size_t)(n0 + nl0 + i) * CD + h * LD + e0);
        dst[0] = __floats2half2_rn(acc[0][i], acc[1][i]);
        dst[1] = __floats2half2_rn(acc[2][i], acc[3][i]);
    }
}

// bias_o[n] = sum_r bd[r%128]*Wo[r,n] + bo[n].  grid 64, block 256 (coalesced)
__global__ void __launch_bounds__(256) prep_bias_o_kernel(
    const float* __restrict__ bd, const float* __restrict__ Wo,
    const float* __restrict__ bo, float* __restrict__ bias_o)
{
    __shared__ float part[8][32];
    const int tid = threadIdx.x;
    const int nl = tid & 31, rc = tid >> 5;
    const int n = blockIdx.x * 32 + nl;
    float acc = 0.f;
    for (int r = rc * 256; r < rc * 256 + 256; r++)
        acc += bd[r & 127] * Wo[(size_t)r * D + n];
    part[rc][nl] = acc;
    __syncthreads();
    if (tid < 32) {
        float s = bo[blockIdx.x * 32 + tid];
        #pragma unroll
        for (int j = 0; j < 8; j++) s += part[j][tid];
        bias_o[blockIdx.x * 32 + tid] = s;
    }
}

// bveff[h*32+e] = sum_d bv[h*128+d]*Wvc[d,e] + bvc[e]
__global__ void __launch_bounds__(256) prep_bias_v_kernel(
    const float* __restrict__ bv, const float* __restrict__ Wvc,
    const float* __restrict__ bvc, float* __restrict__ bveff)
{
    for (int o = threadIdx.x; o < CD; o += 256) {
        const int h = o >> 5, e = o & 31;
        float acc = bvc[e];
        for (int d = 0; d < HD; d++)
            acc += bv[h * HD + d] * Wvc[d * LD + e];
        bveff[o] = acc;
    }
}

// ================= unified QKV GEMM (K=2048, N=4608) ========================
__device__ __forceinline__ void load_stage_qkv(
    uint32_t sbase, const __half* pA, const __half* pB, int kc, int tid)
{
    const int r0 = tid >> 2, seg = tid & 3;
    const uint32_t so = sbase + r0 * ROWB + seg * 16;
    const size_t go = (size_t)r0 * D + kc + seg * 8;
    #pragma unroll
    for (int j = 0; j < 4; j++)
        cp_async16(so + j * 64 * ROWB, pA + go + (size_t)j * 64 * D);
    #pragma unroll
    for (int j = 0; j < 2; j++)
        cp_async16(so + (256 + j * 64) * ROWB, pB + go + (size_t)j * 64 * D);
}

__global__ void __launch_bounds__(256) gemm_qkv_kernel(
    const __half* __restrict__ A16, const __half* __restrict__ wB,
    const float* __restrict__ bq, const float* __restrict__ bk,
    const float* __restrict__ bveff,
    float* __restrict__ q, float* __restrict__ k, __half* __restrict__ vch)
{
    constexpr int NITL = D / BK;   // 64
    extern __shared__ char smem[];
    const uint32_t sb0 = smem_u32(smem);
    const int tid = threadIdx.x, wid = tid >> 5, lane = tid & 31;
    const int warp_m = (wid & 3) * 64;
    const int warp_n = (wid >> 2) * 64;
    const int m0 = blockIdx.y * 256;
    const int n0 = blockIdx.x * 128;

    const __half* pA = A16 + (size_t)m0 * D;
    const __half* pB = wB  + (size_t)n0 * D;

    float acc[4][8][4];
    #pragma unroll
    for (int i = 0; i < 4; i++)
        #pragma unroll
        for (int j = 0; j < 8; j++)
            #pragma unroll
            for (int t = 0; t < 4; t++) acc[i][j][t] = 0.f;

    const int arow = ((lane >> 3) & 1) * 8 + (lane & 7);
    const int acol = (lane >> 4) * 16;
    const int brow = (lane >> 4) * 8 + (lane & 7);
    const int bcol = ((lane >> 3) & 1) * 16;

    load_stage_qkv(sb0, pA, pB, 0, tid);
    cp_commit();
    load_stage_qkv(sb0 + STAGEB, pA, pB, BK, tid);
    cp_commit();

    #pragma unroll 1
    for (int kt = 0; kt < NITL; kt++) {
        cp_wait<1>();
        __syncthreads();
        if (kt + 2 < NITL)
            load_stage_qkv(sb0 + ((kt + 2) % STAGES) * STAGEB,
                           pA, pB, (kt + 2) * BK, tid);
        cp_commit();

        const uint32_t sb = sb0 + (kt % STAGES) * STAGEB;
        #pragma unroll
        for (int ks = 0; ks < 2; ks++) {
            uint32_t ah[4][4];
            #pragma unroll
            for (int mt = 0; mt < 4; mt++)
                ldsm4(ah[mt], sb + (warp_m + mt * 16 + arow) * ROWB
                              + ks * 32 + acol);
            uint32_t bh[4][4];
            #pragma unroll
            for (int np = 0; np < 4; np++)
                ldsm4(bh[np], sb + OFF_B + (warp_n + np * 16 + brow) * ROWB
                              + ks * 32 + bcol);
            #pragma unroll
            for (int mt = 0; mt < 4; mt++)
                #pragma unroll
                for (int nt = 0; nt < 8; nt++) {
                    const int np = nt >> 1, pp = (nt & 1) * 2;
                    mma16816(acc[mt][nt], ah[mt], bh[np][pp], bh[np][pp + 1]);
                }
        }
    }

    if (n0 < 2 * D) {
        float* C = (n0 < D) ? q : k;
        const float* bias = (n0 < D) ? bq : bk;
        const int nc0 = (n0 < D) ? n0 : n0 - D;
        #pragma unroll
        for (int mt = 0; mt < 4; mt++) {
            const int row = m0 + warp_m + mt * 16 + (lane >> 2);
            #pragma unroll
            for (int nt = 0; nt < 8; nt++) {
                const int col = nc0 + warp_n + nt * 8 + (lane & 3) * 2;
                const float b0 = bias[col], b1 = bias[col + 1];
                *(float2*)(C + (size_t)row * D + col) =
                    make_float2(acc[mt][nt][0] + b0, acc[mt][nt][1] + b1);
                *(float2*)(C + (size_t)(row + 8) * D + col) =
                    make_float2(acc[mt][nt][2] + b0, acc[mt][nt][3] + b1);
            }
        }
    } else {
        const int ncv = n0 - 2 * D;
        #pragma unroll
        for (int mt = 0; mt < 4; mt++) {
            const int row = m0 + warp_m + mt * 16 + (lane >> 2);
            const int b0i = row >> 11, l0i = row & (L - 1);
            const int b1i = (row + 8) >> 11, l1i = (row + 8) & (L - 1);
            #pragma unroll
            for (int nt = 0; nt < 8; nt++) {
                const int col = ncv + warp_n + nt * 8 + (lane & 3) * 2;
                const int h = col >> 5, e = col & 31;
                const float bb0 = bveff[col], bb1 = bveff[col + 1];
                *(__half2*)(vch + ((size_t)(b0i * H + h) * L + l0i) * LD + e) =
                    __floats2half2_rn(acc[mt][nt][0] + bb0,
                                      acc[mt][nt][1] + bb1);
                *(__half2*)(vch + ((size_t)(b1i * H + h) * L + l1i) * LD + e) =
                    __floats2half2_rn(acc[mt][nt][2] + bb0,
                                      acc[mt][nt][3] + bb1);
            }
        }
    }
}

// ================= output GEMM (K=512) ======================================
__device__ __forceinline__ void load_stage_out(
    uint32_t sbase, const __half* pA, const __half* pB, int kc, int tid)
{
    const int r0 = tid >> 2, seg = tid & 3;
    const uint32_t so = sbase + r0 * ROWB + seg * 16;
    const size_t go = (size_t)r0 * CD + kc + seg * 8;
    #pragma unroll
    for (int j = 0; j < 4; j++)
        cp_async16(so + j * 64 * ROWB, pA + go + (size_t)j * 64 * CD);
    #pragma unroll
    for (int j = 0; j < 2; j++)
        cp_async16(so + (256 + j * 64) * ROWB, pB + go + (size_t)j * 64 * CD);
}

__global__ void __launch_bounds__(256) gemm_out_kernel(
    const __half* __restrict__ A16, const __half* __restrict__ Bw,
    const float* __restrict__ bias, float* __restrict__ C)
{
    constexpr int NITL = CD / BK;  // 16
    extern __shared__ char smem[];
    const uint32_t sb0 = smem_u32(smem);
    const int tid = threadIdx.x, wid = tid >> 5, lane = tid & 31;
    const int warp_m = (wid & 3) * 64;
    const int warp_n = (wid >> 2) * 64;
    const int m0 = blockIdx.y * 256, n0 = blockIdx.x * 128;

    const __half* pA = A16 + (size_t)m0 * CD;
    const __half* pB = Bw  + (size_t)n0 * CD;

    float acc[4][8][4];
    #pragma unroll
    for (int i = 0; i < 4; i++)
        #pragma unroll
        for (int j = 0; j < 8; j++)
            #pragma unroll
            for (int t = 0; t < 4; t++) acc[i][j][t] = 0.f;

    const int arow = ((lane >> 3) & 1) * 8 + (lane & 7);
    const int acol = (lane >> 4) * 16;
    const int brow = (lane >> 4) * 8 + (lane & 7);
    const int bcol = ((lane >> 3) & 1) * 16;

    load_stage_out(sb0, pA, pB, 0, tid);
    cp_commit();
    load_stage_out(sb0 + STAGEB, pA, pB, BK, tid);
    cp_commit();

    #pragma unroll 1
    for (int kt = 0; kt < NITL; kt++) {
        cp_wait<1>();
        __syncthreads();
        if (kt + 2 < NITL)
            load_stage_out(sb0 + ((kt + 2) % STAGES) * STAGEB,
                           pA, pB, (kt + 2) * BK, tid);
        cp_commit();

        const uint32_t sb = sb0 + (kt % STAGES) * STAGEB;
        #pragma unroll
        for (int ks = 0; ks < 2; ks++) {
            uint32_t ah[4][4];
            #pragma unroll
            for (int mt = 0; mt < 4; mt++)
                ldsm4(ah[mt], sb + (warp_m + mt * 16 + arow) * ROWB
                              + ks * 32 + acol);
            uint32_t bh[4][4];
            #pragma unroll
            for (int np = 0; np < 4; np++)
                ldsm4(bh[np], sb + OFF_B + (warp_n + np * 16 + brow) * ROWB
                              + ks * 32 + bcol);
            #pragma unroll
            for (int mt = 0; mt < 4; mt++)
                #pragma unroll
                for (int nt = 0; nt < 8; nt++) {
                    const int np = nt >> 1, pp = (nt & 1) * 2;
                    mma16816(acc[mt][nt], ah[mt], bh[np][pp], bh[np][pp + 1]);
                }
        }
    }

    #pragma unroll
    for (int mt = 0; mt < 4; mt++) {
        const int row = m0 + warp_m + mt * 16 + (lane >> 2);
        #pragma unroll
        for (int nt = 0; nt < 8; nt++) {
            const int col = n0 + warp_n + nt * 8 + (lane & 3) * 2;
            const float b0 = bias[col], b1 = bias[col + 1];
            *(float2*)(C + (size_t)row * D + col) =
                make_float2(acc[mt][nt][0] + b0, acc[mt][nt][1] + b1);
            *(float2*)(C + (size_t)(row + 8) * D + col) =
                make_float2(acc[mt][nt][2] + b0, acc[mt][nt][3] + b1);
        }
    }
}

// ---------------- compress (+ fused RoPE) -----------------------------------
__global__ void __launch_bounds__(256) compress_kernel(
    const float* __restrict__ X, const float* __restrict__ Wc,
    const float* __restrict__ bc, __half* __restrict__ Xc,
    const float* __restrict__ cosT, const float* __restrict__ sinT)
{
    __shared__ float Ws[HD][LD];
    __shared__ float xs[32][HD];
    const int bh = blockIdx.y;
    const int b = bh / H, h = bh % H;
    const int l0 = blockIdx.x * 32;
    const int tid = threadIdx.x;
    for (int i = tid; i < HD * LD; i += 256) Ws[i / LD][i % LD] = Wc[i];
    for (int i = tid; i < 32 * 64; i += 256) {
        const int li = i >> 6, p = i & 63;
        const int l = l0 + li;
        float2 xv = *(const float2*)&X[
            ((size_t)((b * L + l) * H + h)) * HD + 2 * p];
        const float c = cosT[l * 64 + p];
        const float s = sinT[l * 64 + p];
        xs[li][2 * p]     = xv.x * c - xv.y * s;
        xs[li][2 * p + 1] = xv.x * s + xv.y * c;
    }
    __syncthreads();
    const int row = tid >> 3;
    const int e0  = (tid & 7) * 4;
    float4 acc = *(const float4*)(bc + e0);
    #pragma unroll
    for (int d = 0; d < HD; d++) {
        const float xv = xs[row][d];
        const float4 w = *(const float4*)&Ws[d][e0];
        acc.x += xv * w.x; acc.y += xv * w.y;
        acc.z += xv * w.z; acc.w += xv * w.w;
    }
    __half2* dst = (__half2*)(Xc + ((size_t)bh * L + l0 + row) * LD + e0);
    dst[0] = __floats2half2_rn(acc.x, acc.y);
    dst[1] = __floats2half2_rn(acc.z, acc.w);
}

// ---------------- tensor-core causal flash attention ------------------------
__global__ void __launch_bounds__(128) attn_kernel(
    const __half* __restrict__ qc, const __half* __restrict__ kc,
    const __half* __restrict__ vc, __half* __restrict__ ao)
{
    __shared__ __half qs[64][40];
    __shared__ __half ks[64][40];
    __shared__ __half vs[64][40];
    constexpr float SCALE = 0.17677669529663687f;

    const int bh  = blockIdx.y;
    const int q0  = (gridDim.x - 1 - blockIdx.x) * 64;
    const int tid = threadIdx.x;
    const int w = tid >> 5, lane = tid & 31;

    const __half* bq = qc + ((size_t)bh * L + q0) * LD;
    const __half* bk = kc + (size_t)bh * L * LD;
    const __half* bv = vc + (size_t)bh * L * LD;

    for (int i = tid; i < 256; i += 128) {
        const int r = i >> 2, c = i & 3;
        *(uint4*)((char*)&qs[r][0] + c * 16) =
            *(const uint4*)((const char*)(bq + (size_t)r * LD) + c * 16);
    }
    __syncthreads();

    const uint32_t qs_b = smem_u32(qs);
    const uint32_t ks_b = smem_u32(ks);
    const uint32_t vs_b = smem_u32(vs);

    const int arow = ((lane >> 3) & 1) * 8 + (lane & 7);
    const int acol = (lane >> 4) * 16;
    const int brow = (lane >> 4) * 8 + (lane & 7);
    const int bcol = ((lane >> 3) & 1) * 16;

    uint32_t aq[2][4];
    #pragma unroll
    for (int ks2 = 0; ks2 < 2; ks2++)
        ldsm4(aq[ks2], qs_b + (w * 16 + arow) * 80 + ks2 * 32 + acol);

    float o[4][4];
    #pragma unroll
    for (int i = 0; i < 4; i++)
        #pragma unroll
        for (int j = 0; j < 4; j++) o[i][j] = 0.f;
    float m_lo = -INFINITY, m_hi = -INFINITY, l_lo = 0.f, l_hi = 0.f;

    const int nt = q0 / 64 + 1;
    const int row_lo = q0 + w * 16 + (lane >> 2);
    const int row_hi = row_lo + 8;

    for (int t = 0; t < nt; t++) {
        __syncthreads();
        for (int i = tid; i < 512; i += 128) {
            const int mtx = i >> 8;
            const int r = (i >> 2) & 63, c = i & 3;
            const __half* src = (mtx ? bv : bk) + ((size_t)(t * 64 + r)) * LD;
            __half* dst = mtx ? &vs[r][0] : &ks[r][0];
            *(uint4*)((char*)dst + c * 16) =
                *(const uint4*)((const char*)src + c * 16);
        }
        __syncthreads();

        float s[8][4];
        #pragma unroll
        for (int i = 0; i < 8; i++)
            #pragma unroll
            for (int j = 0; j < 4; j++) s[i][j] = 0.f;
        #pragma unroll
        for (int ks2 = 0; ks2 < 2; ks2++) {
            #pragma unroll
            for (int ng = 0; ng < 4; ng++) {
                uint32_t bkf[4];
                ldsm4(bkf, ks_b + (ng * 16 + brow) * 80 + ks2 * 32 + bcol);
                mma16816(s[ng * 2],     aq[ks2], bkf[0], bkf[1]);
                mma16816(s[ng * 2 + 1], aq[ks2], bkf[2], bkf[3]);
            }
        }

        const bool diag = (t == nt - 1);
        #pragma unroll
        for (int nf = 0; nf < 8; nf++) {
            const int col = t * 64 + nf * 8 + (lane & 3) * 2;
            #pragma unroll
            for (int j = 0; j < 4; j++) s[nf][j] *= SCALE;
            if (diag) {
                if (col     > row_lo) s[nf][0] = -INFINITY;
                if (col + 1 > row_lo) s[nf][1] = -INFINITY;
                if (col     > row_hi) s[nf][2] = -INFINITY;
                if (col + 1 > row_hi) s[nf][3] = -INFINITY;
            }
        }

        float tm_lo = -INFINITY, tm_hi = -INFINITY;
        #pragma unroll
        for (int nf = 0; nf < 8; nf++) {
            tm_lo = fmaxf(tm_lo, fmaxf(s[nf][0], s[nf][1]));
            tm_hi = fmaxf(tm_hi, fmaxf(s[nf][2], s[nf][3]));
        }
        #pragma unroll
        for (int off = 1; off <= 2; off <<= 1) {
            tm_lo = fmaxf(tm_lo, __shfl_xor_sync(0xffffffffu, tm_lo, off));
            tm_hi = fmaxf(tm_hi, __shfl_xor_sync(0xffffffffu, tm_hi, off));
        }
        const float mn_lo = fmaxf(m_lo, tm_lo);
        const float mn_hi = fmaxf(m_hi, tm_hi);
        const float al_lo = __expf(m_lo - mn_lo);
        const float al_hi = __expf(m_hi - mn_hi);
        m_lo = mn_lo; m_hi = mn_hi;

        float ps_lo = 0.f, ps_hi = 0.f;
        #pragma unroll
        for (int nf = 0; nf < 8; nf++) {
            s[nf][0] = __expf(s[nf][0] - mn_lo);
            s[nf][1] = __expf(s[nf][1] - mn_lo);
            s[nf][2] = __expf(s[nf][2] - mn_hi);
            s[nf][3] = __expf(s[nf][3] - mn_hi);
            ps_lo += s[nf][0] + s[nf][1];
            ps_hi += s[nf][2] + s[nf][3];
        }
        #pragma unroll
        for (int off = 1; off <= 2; off <<= 1) {
            ps_lo += __shfl_xor_sync(0xffffffffu, ps_lo, off);
            ps_hi += __shfl_xor_sync(0xffffffffu, ps_hi, off);
        }
        l_lo = l_lo * al_lo + ps_lo;
        l_hi = l_hi * al_hi + ps_hi;

        #pragma unroll
        for (int nf = 0; nf < 4; nf++) {
            o[nf][0] *= al_lo; o[nf][1] *= al_lo;
            o[nf][2] *= al_hi; o[nf][3] *= al_hi;
        }

        #pragma unroll
        for (int kc4 = 0; kc4 < 4; kc4++) {
            uint32_t ap[4];
            const int f0 = 2 * kc4, f1 = 2 * kc4 + 1;
            ap[0] = h2_u32(__floats2half2_rn(s[f0][0], s[f0][1]));
            ap[1] = h2_u32(__floats2half2_rn(s[f0][2], s[f0][3]));
            ap[2] = h2_u32(__floats2half2_rn(s[f1][0], s[f1][1]));
            ap[3] = h2_u32(__floats2half2_rn(s[f1][2], s[f1][3]));
            #pragma unroll
            for (int half = 0; half < 2; half++) {
                uint32_t bvf[4];
                ldsm4t(bvf, vs_b + (kc4 * 16 + arow) * 80 + half * 32 + acol);
                mma16816(o[half * 2],     ap, bvf[0], bvf[1]);
                mma16816(o[half * 2 + 1], ap, bvf[2], bvf[3]);
            }
        }
    }

    const int b = bh / H, h = bh % H;
    const float inv_lo = 1.f / l_lo, inv_hi = 1.f / l_hi;
    #pragma unroll
    for (int nf = 0; nf < 4; nf++) {
        const int e = nf * 8 + (lane & 3) * 2;
        __half* p_lo = ao + (size_t)(b * L + row_lo) * CD + h * LD + e;
        __half* p_hi = ao + (size_t)(b * L + row_hi) * CD + h * LD + e;
        *(__half2*)p_lo = __floats2half2_rn(o[nf][0] * inv_lo, o[nf][1] * inv_lo);
        *(__half2*)p_hi = __floats2half2_rn(o[nf][2] * inv_hi, o[nf][3] * inv_hi);
    }
}

// ---------------------------------------------------------------------------
extern "C" void kernel_launch(void* const* d_in, const int* in_sizes, int n_in,
                              void* d_out, int out_size)
{
    const float* x    = (const float*)d_in[0];
    const float* cosT = (const float*)d_in[1];
    const float* sinT = (const float*)d_in[2];
    const float* Wq   = (const float*)d_in[3];
    const float* bq   = (const float*)d_in[4];
    const float* Wk   = (const float*)d_in[5];
    const float* bk   = (const float*)d_in[6];
    const float* Wv   = (const float*)d_in[7];
    const float* bv   = (const float*)d_in[8];
    const float* Wqc  = (const float*)d_in[9];
    const float* bqc  = (const float*)d_in[10];
    const float* Wkc  = (const float*)d_in[11];
    const float* bkc  = (const float*)d_in[12];
    const float* Wvc  = (const float*)d_in[13];
    const float* bvc  = (const float*)d_in[14];
    const float* Wd   = (const float*)d_in[15];
    const float* bd   = (const float*)d_in[16];
    const float* Wo   = (const float*)d_in[17];
    const float* bo   = (const float*)d_in[18];
    float* out = (float*)d_out;

    float *q, *k, *bias_o, *bveff;
    __half *qch, *kch, *vch, *ao, *a16, *wB, *wo;
    cudaGetSymbolAddress((void**)&q,      g_q);
    cudaGetSymbolAddress((void**)&k,      g_k);
    cudaGetSymbolAddress((void**)&qch,    g_qch);
    cudaGetSymbolAddress((void**)&kch,    g_kch);
    cudaGetSymbolAddress((void**)&vch,    g_vch);
    cudaGetSymbolAddress((void**)&ao,     g_ao);
    cudaGetSymbolAddress((void**)&a16,    g_a16);
    cudaGetSymbolAddress((void**)&wB,     g_wB);
    cudaGetSymbolAddress((void**)&wo,     g_wo);
    cudaGetSymbolAddress((void**)&bias_o, g_bo);
    cudaGetSymbolAddress((void**)&bveff,  g_bv);

    cudaFuncSetAttribute(gemm_qkv_kernel,
                         cudaFuncAttributeMaxDynamicSharedMemorySize, SMEMB);
    cudaFuncSetAttribute(gemm_out_kernel,
                         cudaFuncAttributeMaxDynamicSharedMemorySize, SMEMB);

    // --- conversions + weight folding ---
    convert_a_kernel<<<(GM * D / 4) / 256, 256>>>(x, a16);
    convert_wqk_kernel<<<dim3(D / 32, D / 64, 2), dim3(32, 8)>>>(Wq, Wk, wB);
    prep_wv_kernel<<<dim3(D / 32, H), 128>>>(Wv, Wvc, wB + (size_t)2 * D * D);
    prep_wo_kernel<<<dim3(D / 32, H), 128>>>(Wd, Wo, wo);
    prep_bias_o_kernel<<<D / 32, 256>>>(bd, Wo, bo, bias_o);
    prep_bias_v_kernel<<<1, 256>>>(bv, Wvc, bvc, bveff);

    // --- unified Q,K,Vc GEMM ---
    gemm_qkv_kernel<<<dim3(NB / 128, GM / 256), 256, SMEMB>>>(
        a16, wB, bq, bk, bveff, q, k, vch);

    // --- compress + rope for q,k ---
    dim3 cgrid(L / 32, B * H);
    compress_kernel<<<cgrid, 256>>>(q, Wqc, bqc, qch, cosT, sinT);
    compress_kernel<<<cgrid, 256>>>(k, Wkc, bkc, kch, cosT, sinT);

    // --- attention ---
    attn_kernel<<<dim3(L / 64, B * H), 128>>>(qch, kch, vch, ao);

    // --- decompress+output projection folded ---
    gemm_out_kernel<<<dim3(D / 128, GM / 256), 256, SMEMB>>>(
        ao, wo, bias_o, out);
}

// round 12
// speedup vs baseline: 8.4431x; 1.0998x over previous
#include <cuda_runtime.h>
#include <cuda_fp16.h>
#include <math.h>
#include <cstdint>

namespace {
constexpr int B  = 2;
constexpr int L  = 2048;
constexpr int D  = 2048;
constexpr int H  = 16;
constexpr int HD = 128;
constexpr int LD = 32;
constexpr int BL = B * L;                 // 4096
constexpr int BHLLD = B * H * L * LD;     // 2097152
constexpr int CD = H * LD;                // 512
constexpr int GM = BL;                    // 4096
constexpr int NB = 2 * D + CD;            // 4608 total B rows (Wq|Wk|Wveff)

constexpr int BK     = 32;
constexpr int STAGES = 3;
constexpr int ROWB   = 80;
constexpr int OFF_B  = 256 * ROWB;
constexpr int STAGEB = 384 * ROWB;        // 30720
constexpr int SMEMB  = STAGES * STAGEB;   // 92160
}

// ---------------- scratch ----------------------------------------------------
__device__ float  g_q[B * L * D];
__device__ float  g_k[B * L * D];
__device__ __half g_qch[BHLLD];      // (b,h,l,e)
__device__ __half g_kch[BHLLD];
__device__ __half g_vch[BHLLD];
__device__ __half g_ao[BL * CD];     // attn out fp16 (b*l, h*32+e)
__device__ __half g_a16[GM * D];     // x fp16 [M,K]
__device__ __half g_wB[(size_t)NB * D];  // Wq|Wk|Wveff fp16 [N,K]
__device__ __half g_wo[D * CD];      // Weffo fp16 [N=2048, K=512]
__device__ float  g_bo[D];
__device__ float  g_bv[CD];

// ================= PTX helpers ==============================================
__device__ __forceinline__ uint32_t smem_u32(const void* p) {
    uint32_t a;
    asm("{ .reg .u64 t; cvta.to.shared.u64 t, %1; cvt.u32.u64 %0, t; }"
        : "=r"(a) : "l"(p));
    return a;
}
__device__ __forceinline__ uint32_t h2_u32(__half2 h) {
    return *reinterpret_cast<uint32_t*>(&h);
}
__device__ __forceinline__ void cp_async16(uint32_t dst, const void* src) {
    asm volatile("cp.async.cg.shared.global [%0], [%1], 16;"
                 :: "r"(dst), "l"(src) : "memory");
}
__device__ __forceinline__ void cp_commit() {
    asm volatile("cp.async.commit_group;" ::: "memory");
}
template <int N>
__device__ __forceinline__ void cp_wait() {
    asm volatile("cp.async.wait_group %0;" :: "n"(N) : "memory");
}
__device__ __forceinline__ void ldsm4(uint32_t* r, uint32_t addr) {
    asm volatile("ldmatrix.sync.aligned.m8n8.x4.shared.b16 {%0,%1,%2,%3}, [%4];"
                 : "=r"(r[0]), "=r"(r[1]), "=r"(r[2]), "=r"(r[3]) : "r"(addr));
}
__device__ __forceinline__ void ldsm4t(uint32_t* r, uint32_t addr) {
    asm volatile("ldmatrix.sync.aligned.m8n8.x4.trans.shared.b16 {%0,%1,%2,%3}, [%4];"
                 : "=r"(r[0]), "=r"(r[1]), "=r"(r[2]), "=r"(r[3]) : "r"(addr));
}
__device__ __forceinline__ void mma16816(float* d, const uint32_t* a,
                                         uint32_t b0, uint32_t b1) {
    asm volatile(
        "mma.sync.aligned.m16n8k16.row.col.f32.f16.f16.f32 "
        "{%0,%1,%2,%3}, {%4,%5,%6,%7}, {%8,%9}, {%0,%1,%2,%3};"
        : "+f"(d[0]), "+f"(d[1]), "+f"(d[2]), "+f"(d[3])
        : "r"(a[0]), "r"(a[1]), "r"(a[2]), "r"(a[3]), "r"(b0), "r"(b1));
}

// ================= conversion / precompute ==================================
__global__ void __launch_bounds__(256) convert_a_kernel(
    const float* __restrict__ X, __half* __restrict__ out)
{
    long long i = ((long long)blockIdx.x * 256 + threadIdx.x) * 4;
    float4 v = *(const float4*)(X + i);
    *(__half2*)(out + i)     = __floats2half2_rn(v.x, v.y);
    *(__half2*)(out + i + 2) = __floats2half2_rn(v.z, v.w);
}

// Wq/Wk [K,N] -> transposed [N,K] fp16 into wB. grid (D/32, D/64, 2), blk (32,8)
__global__ void __launch_bounds__(256) convert_wqk_kernel(
    const float* __restrict__ Wq, const float* __restrict__ Wk,
    __half* __restrict__ wB)
{
    __shared__ float t[64][33];
    const float* W = blockIdx.z ? Wk : Wq;
    __half* dst = wB + (size_t)blockIdx.z * D * D;
    const int n0 = blockIdx.x * 32, k0 = blockIdx.y * 64;
    const int tx = threadIdx.x, ty = threadIdx.y;
    #pragma unroll
    for (int i = 0; i < 8; i++)
        t[ty + i * 8][tx] = W[(size_t)(k0 + ty + i * 8) * D + n0 + tx];
    __syncthreads();
    #pragma unroll
    for (int i = 0; i < 4; i++) {
        const int nr = ty + i * 8;
        *(__half2*)(dst + (size_t)(n0 + nr) * D + k0 + 2 * tx) =
            __floats2half2_rn(t[2 * tx][nr], t[2 * tx + 1][nr]);
    }
}

// Wveff[h*32+e][i] = sum_d Wvc[d][e]*Wv[i][h*128+d] -> wB rows 4096+.
// grid (D/64, H), 256 thr. smem [d][.] layouts, conflict-free float2 reads.
__global__ void __launch_bounds__(256) prep_wv_kernel(
    const float* __restrict__ Wv, const float* __restrict__ Wvc,
    __half* __restrict__ w16v)
{
    __shared__ float a_s[HD][34];    // [d][e]  (Wvc native [d][e])
    __shared__ float b_s[HD][66];    // [d][il] (Wv transposed)
    const int h = blockIdx.y, i0 = blockIdx.x * 64;
    const int tid = threadIdx.x;
    for (int idx = tid; idx < HD * LD; idx += 256) {
        const int d = idx >> 5, e = idx & 31;
        a_s[d][e] = Wvc[idx];
    }
    for (int idx = tid; idx < 64 * HD; idx += 256) {
        const int il = idx >> 7, d = idx & 127;
        b_s[d][il] = Wv[(size_t)(i0 + il) * D + h * HD + d];
    }
    __syncthreads();
    const int e0  = (tid & 7) * 4;
    const int il0 = (tid >> 3) * 2;
    float acc[4][2] = {};
    #pragma unroll 8
    for (int d = 0; d < HD; d++) {
        const float2 a01 = *(const float2*)&a_s[d][e0];
        const float2 a23 = *(const float2*)&a_s[d][e0 + 2];
        const float2 bb  = *(const float2*)&b_s[d][il0];
        acc[0][0] += a01.x * bb.x; acc[0][1] += a01.x * bb.y;
        acc[1][0] += a01.y * bb.x; acc[1][1] += a01.y * bb.y;
        acc[2][0] += a23.x * bb.x; acc[2][1] += a23.x * bb.y;
        acc[3][0] += a23.y * bb.x; acc[3][1] += a23.y * bb.y;
    }
    #pragma unroll
    for (int j = 0; j < 4; j++)
        *(__half2*)(w16v + (size_t)(h * LD + e0 + j) * D + i0 + il0) =
            __floats2half2_rn(acc[j][0], acc[j][1]);
}

// Weffo[n][h*32+e] = sum_d Wd[e][d]*Wo[h*128+d][n]. grid (D/64, H), 256 thr.
__global__ void __launch_bounds__(256) prep_wo_kernel(
    const float* __restrict__ Wd, const float* __restrict__ Wo,
    __half* __restrict__ w16o)
{
    __shared__ float a_s[HD][34];    // [d][e]  (Wd transposed)
    __shared__ float b_s[HD][66];    // [d][nl] (Wo native slice)
    const int h = blockIdx.y, n0 = blockIdx.x * 64;
    const int tid = threadIdx.x;
    for (int idx = tid; idx < LD * HD; idx += 256) {
        const int e = idx >> 7, d = idx & 127;
        a_s[d][e] = Wd[idx];
    }
    for (int idx = tid; idx < HD * 64; idx += 256) {
        const int d = idx >> 6, nl = idx & 63;
        b_s[d][nl] = Wo[(size_t)(h * HD + d) * D + n0 + nl];
    }
    __syncthreads();
    const int e0  = (tid & 7) * 4;
    const int nl0 = (tid >> 3) * 2;
    float acc[4][2] = {};
    #pragma unroll 8
    for (int d = 0; d < HD; d++) {
        const float2 a01 = *(const float2*)&a_s[d][e0];
        const float2 a23 = *(const float2*)&a_s[d][e0 + 2];
        const float2 bb  = *(const float2*)&b_s[d][nl0];
        acc[0][0] += a01.x * bb.x; acc[0][1] += a01.x * bb.y;
        acc[1][0] += a01.y * bb.x; acc[1][1] += a01.y * bb.y;
        acc[2][0] += a23.x * bb.x; acc[2][1] += a23.x * bb.y;
        acc[3][0] += a23.y * bb.x; acc[3][1] += a23.y * bb.y;
    }
    #pragma unroll
    for (int i = 0; i < 2; i++) {
        __half2* dst =
            (__half2*)(w16o + (size_t)(n0 + nl0 + i) * CD + h * LD + e0);
        dst[0] = __floats2half2_rn(acc[0][i], acc[1][i]);
        dst[1] = __floats2half2_rn(acc[2][i], acc[3][i]);
    }
}

// bias_o[n] = sum_r bd[r%128]*Wo[r,n] + bo[n].  grid 64, block 256
__global__ void __launch_bounds__(256) prep_bias_o_kernel(
    const float* __restrict__ bd, const float* __restrict__ Wo,
    const float* __restrict__ bo, float* __restrict__ bias_o)
{
    __shared__ float part[8][32];
    const int tid = threadIdx.x;
    const int nl = tid & 31, rc = tid >> 5;
    const int n = blockIdx.x * 32 + nl;
    float acc = 0.f;
    for (int r = rc * 256; r < rc * 256 + 256; r++)
        acc += bd[r & 127] * Wo[(size_t)r * D + n];
    part[rc][nl] = acc;
    __syncthreads();
    if (tid < 32) {
        float s = bo[blockIdx.x * 32 + tid];
        #pragma unroll
        for (int j = 0; j < 8; j++) s += part[j][tid];
        bias_o[blockIdx.x * 32 + tid] = s;
    }
}

// bveff[h*32+e] = sum_d bv[h*128+d]*Wvc[d,e] + bvc[e]
__global__ void __launch_bounds__(256) prep_bias_v_kernel(
    const float* __restrict__ bv, const float* __restrict__ Wvc,
    const float* __restrict__ bvc, float* __restrict__ bveff)
{
    for (int o = threadIdx.x; o < CD; o += 256) {
        const int h = o >> 5, e = o & 31;
        float acc = bvc[e];
        for (int d = 0; d < HD; d++)
            acc += bv[h * HD + d] * Wvc[d * LD + e];
        bveff[o] = acc;
    }
}

// ================= unified QKV GEMM (K=2048, N=4608) ========================
__device__ __forceinline__ void load_stage_qkv(
    uint32_t sbase, const __half* pA, const __half* pB, int kc, int tid)
{
    const int r0 = tid >> 2, seg = tid & 3;
    const uint32_t so = sbase + r0 * ROWB + seg * 16;
    const size_t go = (size_t)r0 * D + kc + seg * 8;
    #pragma unroll
    for (int j = 0; j < 4; j++)
        cp_async16(so + j * 64 * ROWB, pA + go + (size_t)j * 64 * D);
    #pragma unroll
    for (int j = 0; j < 2; j++)
        cp_async16(so + (256 + j * 64) * ROWB, pB + go + (size_t)j * 64 * D);
}

__global__ void __launch_bounds__(256) gemm_qkv_kernel(
    const __half* __restrict__ A16, const __half* __restrict__ wB,
    const float* __restrict__ bq, const float* __restrict__ bk,
    const float* __restrict__ bveff,
    float* __restrict__ q, float* __restrict__ k, __half* __restrict__ vch)
{
    constexpr int NITL = D / BK;   // 64
    extern __shared__ char smem[];
    const uint32_t sb0 = smem_u32(smem);
    const int tid = threadIdx.x, wid = tid >> 5, lane = tid & 31;
    const int warp_m = (wid & 3) * 64;
    const int warp_n = (wid >> 2) * 64;
    const int m0 = blockIdx.y * 256;
    const int n0 = blockIdx.x * 128;

    const __half* pA = A16 + (size_t)m0 * D;
    const __half* pB = wB  + (size_t)n0 * D;

    float acc[4][8][4];
    #pragma unroll
    for (int i = 0; i < 4; i++)
        #pragma unroll
        for (int j = 0; j < 8; j++)
            #pragma unroll
            for (int t = 0; t < 4; t++) acc[i][j][t] = 0.f;

    const int arow = ((lane >> 3) & 1) * 8 + (lane & 7);
    const int acol = (lane >> 4) * 16;
    const int brow = (lane >> 4) * 8 + (lane & 7);
    const int bcol = ((lane >> 3) & 1) * 16;

    load_stage_qkv(sb0, pA, pB, 0, tid);
    cp_commit();
    load_stage_qkv(sb0 + STAGEB, pA, pB, BK, tid);
    cp_commit();

    #pragma unroll 1
    for (int kt = 0; kt < NITL; kt++) {
        cp_wait<1>();
        __syncthreads();
        if (kt + 2 < NITL)
            load_stage_qkv(sb0 + ((kt + 2) % STAGES) * STAGEB,
                           pA, pB, (kt + 2) * BK, tid);
        cp_commit();

        const uint32_t sb = sb0 + (kt % STAGES) * STAGEB;
        #pragma unroll
        for (int ks = 0; ks < 2; ks++) {
            uint32_t ah[4][4];
            #pragma unroll
            for (int mt = 0; mt < 4; mt++)
                ldsm4(ah[mt], sb + (warp_m + mt * 16 + arow) * ROWB
                              + ks * 32 + acol);
            uint32_t bh[4][4];
            #pragma unroll
            for (int np = 0; np < 4; np++)
                ldsm4(bh[np], sb + OFF_B + (warp_n + np * 16 + brow) * ROWB
                              + ks * 32 + bcol);
            #pragma unroll
            for (int mt = 0; mt < 4; mt++)
                #pragma unroll
                for (int nt = 0; nt < 8; nt++) {
                    const int np = nt >> 1, pp = (nt & 1) * 2;
                    mma16816(acc[mt][nt], ah[mt], bh[np][pp], bh[np][pp + 1]);
                }
        }
    }

    if (n0 < 2 * D) {
        float* C = (n0 < D) ? q : k;
        const float* bias = (n0 < D) ? bq : bk;
        const int nc0 = (n0 < D) ? n0 : n0 - D;
        #pragma unroll
        for (int mt = 0; mt < 4; mt++) {
            const int row = m0 + warp_m + mt * 16 + (lane >> 2);
            #pragma unroll
            for (int nt = 0; nt < 8; nt++) {
                const int col = nc0 + warp_n + nt * 8 + (lane & 3) * 2;
                const float b0 = bias[col], b1 = bias[col + 1];
                *(float2*)(C + (size_t)row * D + col) =
                    make_float2(acc[mt][nt][0] + b0, acc[mt][nt][1] + b1);
                *(float2*)(C + (size_t)(row + 8) * D + col) =
                    make_float2(acc[mt][nt][2] + b0, acc[mt][nt][3] + b1);
            }
        }
    } else {
        const int ncv = n0 - 2 * D;
        #pragma unroll
        for (int mt = 0; mt < 4; mt++) {
            const int row = m0 + warp_m + mt * 16 + (lane >> 2);
            const int b0i = row >> 11, l0i = row & (L - 1);
            const int b1i = (row + 8) >> 11, l1i = (row + 8) & (L - 1);
            #pragma unroll
            for (int nt = 0; nt < 8; nt++) {
                const int col = ncv + warp_n + nt * 8 + (lane & 3) * 2;
                const int h = col >> 5, e = col & 31;
                const float bb0 = bveff[col], bb1 = bveff[col + 1];
                *(__half2*)(vch + ((size_t)(b0i * H + h) * L + l0i) * LD + e) =
                    __floats2half2_rn(acc[mt][nt][0] + bb0,
                                      acc[mt][nt][1] + bb1);
                *(__half2*)(vch + ((size_t)(b1i * H + h) * L + l1i) * LD + e) =
                    __floats2half2_rn(acc[mt][nt][2] + bb0,
                                      acc[mt][nt][3] + bb1);
            }
        }
    }
}

// ================= output GEMM (K=512) ======================================
__device__ __forceinline__ void load_stage_out(
    uint32_t sbase, const __half* pA, const __half* pB, int kc, int tid)
{
    const int r0 = tid >> 2, seg = tid & 3;
    const uint32_t so = sbase + r0 * ROWB + seg * 16;
    const size_t go = (size_t)r0 * CD + kc + seg * 8;
    #pragma unroll
    for (int j = 0; j < 4; j++)
        cp_async16(so + j * 64 * ROWB, pA + go + (size_t)j * 64 * CD);
    #pragma unroll
    for (int j = 0; j < 2; j++)
        cp_async16(so + (256 + j * 64) * ROWB, pB + go + (size_t)j * 64 * CD);
}

__global__ void __launch_bounds__(256) gemm_out_kernel(
    const __half* __restrict__ A16, const __half* __restrict__ Bw,
    const float* __restrict__ bias, float* __restrict__ C)
{
    constexpr int NITL = CD / BK;  // 16
    extern __shared__ char smem[];
    const uint32_t sb0 = smem_u32(smem);
    const int tid = threadIdx.x, wid = tid >> 5, lane = tid & 31;
    const int warp_m = (wid & 3) * 64;
    const int warp_n = (wid >> 2) * 64;
    const int m0 = blockIdx.y * 256, n0 = blockIdx.x * 128;

    const __half* pA = A16 + (size_t)m0 * CD;
    const __half* pB = Bw  + (size_t)n0 * CD;

    float acc[4][8][4];
    #pragma unroll
    for (int i = 0; i < 4; i++)
        #pragma unroll
        for (int j = 0; j < 8; j++)
            #pragma unroll
            for (int t = 0; t < 4; t++) acc[i][j][t] = 0.f;

    const int arow = ((lane >> 3) & 1) * 8 + (lane & 7);
    const int acol = (lane >> 4) * 16;
    const int brow = (lane >> 4) * 8 + (lane & 7);
    const int bcol = ((lane >> 3) & 1) * 16;

    load_stage_out(sb0, pA, pB, 0, tid);
    cp_commit();
    load_stage_out(sb0 + STAGEB, pA, pB, BK, tid);
    cp_commit();

    #pragma unroll 1
    for (int kt = 0; kt < NITL; kt++) {
        cp_wait<1>();
        __syncthreads();
        if (kt + 2 < NITL)
            load_stage_out(sb0 + ((kt + 2) % STAGES) * STAGEB,
                           pA, pB, (kt + 2) * BK, tid);
        cp_commit();

        const uint32_t sb = sb0 + (kt % STAGES) * STAGEB;
        #pragma unroll
        for (int ks = 0; ks < 2; ks++) {
            uint32_t ah[4][4];
            #pragma unroll
            for (int mt = 0; mt < 4; mt++)
                ldsm4(ah[mt], sb + (warp_m + mt * 16 + arow) * ROWB
                              + ks * 32 + acol);
            uint32_t bh[4][4];
            #pragma unroll
            for (int np = 0; np < 4; np++)
                ldsm4(bh[np], sb + OFF_B + (warp_n + np * 16 + brow) * ROWB
                              + ks * 32 + bcol);
            #pragma unroll
            for (int mt = 0; mt < 4; mt++)
                #pragma unroll
                for (int nt = 0; nt < 8; nt++) {
                    const int np = nt >> 1, pp = (nt & 1) * 2;
                    mma16816(acc[mt][nt], ah[mt], bh[np][pp], bh[np][pp + 1]);
                }
        }
    }

    #pragma unroll
    for (int mt = 0; mt < 4; mt++) {
        const int row = m0 + warp_m + mt * 16 + (lane >> 2);
        #pragma unroll
        for (int nt = 0; nt < 8; nt++) {
            const int col = n0 + warp_n + nt * 8 + (lane & 3) * 2;
            const float b0 = bias[col], b1 = bias[col + 1];
            *(float2*)(C + (size_t)row * D + col) =
                make_float2(acc[mt][nt][0] + b0, acc[mt][nt][1] + b1);
            *(float2*)(C + (size_t)(row + 8) * D + col) =
                make_float2(acc[mt][nt][2] + b0, acc[mt][nt][3] + b1);
        }
    }
}

// ---------------- compress (+ fused RoPE), q & k in one launch --------------
__global__ void __launch_bounds__(256) compress_kernel(
    const float* __restrict__ Q, const float* __restrict__ K,
    const float* __restrict__ Wqc, const float* __restrict__ Wkc,
    const float* __restrict__ bqc, const float* __restrict__ bkc,
    __half* __restrict__ qch, __half* __restrict__ kch,
    const float* __restrict__ cosT, const float* __restrict__ sinT)
{
    __shared__ float Ws[HD][LD];
    __shared__ float xs[32][HD];
    const int z = blockIdx.z;
    const float* X = z ? K : Q;
    const float* Wc = z ? Wkc : Wqc;
    const float* bc = z ? bkc : bqc;
    __half* Xc = z ? kch : qch;
    const int bh = blockIdx.y;
    const int b = bh / H, h = bh % H;
    const int l0 = blockIdx.x * 32;
    const int tid = threadIdx.x;
    for (int i = tid; i < HD * LD; i += 256) Ws[i / LD][i % LD] = Wc[i];
    for (int i = tid; i < 32 * 64; i += 256) {
        const int li = i >> 6, p = i & 63;
        const int l = l0 + li;
        float2 xv = *(const float2*)&X[
            ((size_t)((b * L + l) * H + h)) * HD + 2 * p];
        const float c = cosT[l * 64 + p];
        const float s = sinT[l * 64 + p];
        xs[li][2 * p]     = xv.x * c - xv.y * s;
        xs[li][2 * p + 1] = xv.x * s + xv.y * c;
    }
    __syncthreads();
    const int row = tid >> 3;
    const int e0  = (tid & 7) * 4;
    float4 acc = *(const float4*)(bc + e0);
    #pragma unroll
    for (int d = 0; d < HD; d++) {
        const float xv = xs[row][d];
        const float4 w = *(const float4*)&Ws[d][e0];
        acc.x += xv * w.x; acc.y += xv * w.y;
        acc.z += xv * w.z; acc.w += xv * w.w;
    }
    __half2* dst = (__half2*)(Xc + ((size_t)bh * L + l0 + row) * LD + e0);
    dst[0] = __floats2half2_rn(acc.x, acc.y);
    dst[1] = __floats2half2_rn(acc.z, acc.w);
}

// ---------------- tensor-core causal flash attention ------------------------
__global__ void __launch_bounds__(128) attn_kernel(
    const __half* __restrict__ qc, const __half* __restrict__ kc,
    const __half* __restrict__ vc, __half* __restrict__ ao)
{
    __shared__ __half qs[64][40];
    __shared__ __half ks[64][40];
    __shared__ __half vs[64][40];
    constexpr float SCALE = 0.17677669529663687f;

    const int bh  = blockIdx.y;
    const int q0  = (gridDim.x - 1 - blockIdx.x) * 64;
    const int tid = threadIdx.x;
    const int w = tid >> 5, lane = tid & 31;

    const __half* bq = qc + ((size_t)bh * L + q0) * LD;
    const __half* bk = kc + (size_t)bh * L * LD;
    const __half* bv = vc + (size_t)bh * L * LD;

    for (int i = tid; i < 256; i += 128) {
        const int r = i >> 2, c = i & 3;
        *(uint4*)((char*)&qs[r][0] + c * 16) =
            *(const uint4*)((const char*)(bq + (size_t)r * LD) + c * 16);
    }
    __syncthreads();

    const uint32_t qs_b = smem_u32(qs);
    const uint32_t ks_b = smem_u32(ks);
    const uint32_t vs_b = smem_u32(vs);

    const int arow = ((lane >> 3) & 1) * 8 + (lane & 7);
    const int acol = (lane >> 4) * 16;
    const int brow = (lane >> 4) * 8 + (lane & 7);
    const int bcol = ((lane >> 3) & 1) * 16;

    uint32_t aq[2][4];
    #pragma unroll
    for (int ks2 = 0; ks2 < 2; ks2++)
        ldsm4(aq[ks2], qs_b + (w * 16 + arow) * 80 + ks2 * 32 + acol);

    float o[4][4];
    #pragma unroll
    for (int i = 0; i < 4; i++)
        #pragma unroll
        for (int j = 0; j < 4; j++) o[i][j] = 0.f;
    float m_lo = -INFINITY, m_hi = -INFINITY, l_lo = 0.f, l_hi = 0.f;

    const int nt = q0 / 64 + 1;
    const int row_lo = q0 + w * 16 + (lane >> 2);
    const int row_hi = row_lo + 8;

    for (int t = 0; t < nt; t++) {
        __syncthreads();
        for (int i = tid; i < 512; i += 128) {
            const int mtx = i >> 8;
            const int r = (i >> 2) & 63, c = i & 3;
            const __half* src = (mtx ? bv : bk) + ((size_t)(t * 64 + r)) * LD;
            __half* dst = mtx ? &vs[r][0] : &ks[r][0];
            *(uint4*)((char*)dst + c * 16) =
                *(const uint4*)((const char*)src + c * 16);
        }
        __syncthreads();

        float s[8][4];
        #pragma unroll
        for (int i = 0; i < 8; i++)
            #pragma unroll
            for (int j = 0; j < 4; j++) s[i][j] = 0.f;
        #pragma unroll
        for (int ks2 = 0; ks2 < 2; ks2++) {
            #pragma unroll
            for (int ng = 0; ng < 4; ng++) {
                uint32_t bkf[4];
                ldsm4(bkf, ks_b + (ng * 16 + brow) * 80 + ks2 * 32 + bcol);
                mma16816(s[ng * 2],     aq[ks2], bkf[0], bkf[1]);
                mma16816(s[ng * 2 + 1], aq[ks2], bkf[2], bkf[3]);
            }
        }

        const bool diag = (t == nt - 1);
        #pragma unroll
        for (int nf = 0; nf < 8; nf++) {
            const int col = t * 64 + nf * 8 + (lane & 3) * 2;
            #pragma unroll
            for (int j = 0; j < 4; j++) s[nf][j] *= SCALE;
            if (diag) {
                if (col     > row_lo) s[nf][0] = -INFINITY;
                if (col + 1 > row_lo) s[nf][1] = -INFINITY;
                if (col     > row_hi) s[nf][2] = -INFINITY;
                if (col + 1 > row_hi) s[nf][3] = -INFINITY;
            }
        }

        float tm_lo = -INFINITY, tm_hi = -INFINITY;
        #pragma unroll
        for (int nf = 0; nf < 8; nf++) {
            tm_lo = fmaxf(tm_lo, fmaxf(s[nf][0], s[nf][1]));
            tm_hi = fmaxf(tm_hi, fmaxf(s[nf][2], s[nf][3]));
        }
        #pragma unroll
        for (int off = 1; off <= 2; off <<= 1) {
            tm_lo = fmaxf(tm_lo, __shfl_xor_sync(0xffffffffu, tm_lo, off));
            tm_hi = fmaxf(tm_hi, __shfl_xor_sync(0xffffffffu, tm_hi, off));
        }
        const float mn_lo = fmaxf(m_lo, tm_lo);
        const float mn_hi = fmaxf(m_hi, tm_hi);
        const float al_lo = __expf(m_lo - mn_lo);
        const float al_hi = __expf(m_hi - mn_hi);
        m_lo = mn_lo; m_hi = mn_hi;

        float ps_lo = 0.f, ps_hi = 0.f;
        #pragma unroll
        for (int nf = 0; nf < 8; nf++) {
            s[nf][0] = __expf(s[nf][0] - mn_lo);
            s[nf][1] = __expf(s[nf][1] - mn_lo);
            s[nf][2] = __expf(s[nf][2] - mn_hi);
            s[nf][3] = __expf(s[nf][3] - mn_hi);
            ps_lo += s[nf][0] + s[nf][1];
            ps_hi += s[nf][2] + s[nf][3];
        }
        #pragma unroll
        for (int off = 1; off <= 2; off <<= 1) {
            ps_lo += __shfl_xor_sync(0xffffffffu, ps_lo, off);
            ps_hi += __shfl_xor_sync(0xffffffffu, ps_hi, off);
        }
        l_lo = l_lo * al_lo + ps_lo;
        l_hi = l_hi * al_hi + ps_hi;

        #pragma unroll
        for (int nf = 0; nf < 4; nf++) {
            o[nf][0] *= al_lo; o[nf][1] *= al_lo;
            o[nf][2] *= al_hi; o[nf][3] *= al_hi;
        }

        #pragma unroll
        for (int kc4 = 0; kc4 < 4; kc4++) {
            uint32_t ap[4];
            const int f0 = 2 * kc4, f1 = 2 * kc4 + 1;
            ap[0] = h2_u32(__floats2half2_rn(s[f0][0], s[f0][1]));
            ap[1] = h2_u32(__floats2half2_rn(s[f0][2], s[f0][3]));
            ap[2] = h2_u32(__floats2half2_rn(s[f1][0], s[f1][1]));
            ap[3] = h2_u32(__floats2half2_rn(s[f1][2], s[f1][3]));
            #pragma unroll
            for (int half = 0; half < 2; half++) {
                uint32_t bvf[4];
                ldsm4t(bvf, vs_b + (kc4 * 16 + arow) * 80 + half * 32 + acol);
                mma16816(o[half * 2],     ap, bvf[0], bvf[1]);
                mma16816(o[half * 2 + 1], ap, bvf[2], bvf[3]);
            }
        }
    }

    const int b = bh / H, h = bh % H;
    const float inv_lo = 1.f / l_lo, inv_hi = 1.f / l_hi;
    #pragma unroll
    for (int nf = 0; nf < 4; nf++) {
        const int e = nf * 8 + (lane & 3) * 2;
        __half* p_lo = ao + (size_t)(b * L + row_lo) * CD + h * LD + e;
        __half* p_hi = ao + (size_t)(b * L + row_hi) * CD + h * LD + e;
        *(__half2*)p_lo = __floats2half2_rn(o[nf][0] * inv_lo, o[nf][1] * inv_lo);
        *(__half2*)p_hi = __floats2half2_rn(o[nf][2] * inv_hi, o[nf][3] * inv_hi);
    }
}

// ---------------------------------------------------------------------------
extern "C" void kernel_launch(void* const* d_in, const int* in_sizes, int n_in,
                              void* d_out, int out_size)
{
    const float* x    = (const float*)d_in[0];
    const float* cosT = (const float*)d_in[1];
    const float* sinT = (const float*)d_in[2];
    const float* Wq   = (const float*)d_in[3];
    const float* bq   = (const float*)d_in[4];
    const float* Wk   = (const float*)d_in[5];
    const float* bk   = (const float*)d_in[6];
    const float* Wv   = (const float*)d_in[7];
    const float* bv   = (const float*)d_in[8];
    const float* Wqc  = (const float*)d_in[9];
    const float* bqc  = (const float*)d_in[10];
    const float* Wkc  = (const float*)d_in[11];
    const float* bkc  = (const float*)d_in[12];
    const float* Wvc  = (const float*)d_in[13];
    const float* bvc  = (const float*)d_in[14];
    const float* Wd   = (const float*)d_in[15];
    const float* bd   = (const float*)d_in[16];
    const float* Wo   = (const float*)d_in[17];
    const float* bo   = (const float*)d_in[18];
    float* out = (float*)d_out;

    float *q, *k, *bias_o, *bveff;
    __half *qch, *kch, *vch, *ao, *a16, *wB, *wo;
    cudaGetSymbolAddress((void**)&q,      g_q);
    cudaGetSymbolAddress((void**)&k,      g_k);
    cudaGetSymbolAddress((void**)&qch,    g_qch);
    cudaGetSymbolAddress((void**)&kch,    g_kch);
    cudaGetSymbolAddress((void**)&vch,    g_vch);
    cudaGetSymbolAddress((void**)&ao,     g_ao);
    cudaGetSymbolAddress((void**)&a16,    g_a16);
    cudaGetSymbolAddress((void**)&wB,     g_wB);
    cudaGetSymbolAddress((void**)&wo,     g_wo);
    cudaGetSymbolAddress((void**)&bias_o, g_bo);
    cudaGetSymbolAddress((void**)&bveff,  g_bv);

    cudaFuncSetAttribute(gemm_qkv_kernel,
                         cudaFuncAttributeMaxDynamicSharedMemorySize, SMEMB);
    cudaFuncSetAttribute(gemm_out_kernel,
                         cudaFuncAttributeMaxDynamicSharedMemorySize, SMEMB);

    // --- conversions + weight folding ---
    convert_a_kernel<<<(GM * D / 4) / 256, 256>>>(x, a16);
    convert_wqk_kernel<<<dim3(D / 32, D / 64, 2), dim3(32, 8)>>>(Wq, Wk, wB);
    prep_wv_kernel<<<dim3(D / 64, H), 256>>>(Wv, Wvc, wB + (size_t)2 * D * D);
    prep_wo_kernel<<<dim3(D / 64, H), 256>>>(Wd, Wo, wo);
    prep_bias_o_kernel<<<D / 32, 256>>>(bd, Wo, bo, bias_o);
    prep_bias_v_kernel<<<1, 256>>>(bv, Wvc, bvc, bveff);

    // --- unified Q,K,Vc GEMM ---
    gemm_qkv_kernel<<<dim3(NB / 128, GM / 256), 256, SMEMB>>>(
        a16, wB, bq, bk, bveff, q, k, vch);

    // --- compress + rope for q,k (single launch) ---
    compress_kernel<<<dim3(L / 32, B * H, 2), 256>>>(
        q, k, Wqc, Wkc, bqc, bkc, qch, kch, cosT, sinT);

    // --- attention ---
    attn_kernel<<<dim3(L / 64, B * H), 128>>>(qch, kch, vch, ao);

    // --- decompress+output projection folded ---
    gemm_out_kernel<<<dim3(D / 128, GM / 256), 256, SMEMB>>>(
        ao, wo, bias_o, out);
}

// round 13
// speedup vs baseline: 8.5611x; 1.0140x over previous
#include <cuda_runtime.h>
#include <cuda_fp16.h>
#include <math.h>
#include <cstdint>

namespace {
constexpr int B  = 2;
constexpr int L  = 2048;
constexpr int D  = 2048;
constexpr int H  = 16;
constexpr int HD = 128;
constexpr int LD = 32;
constexpr int BL = B * L;                 // 4096
constexpr int BHLLD = B * H * L * LD;     // 2097152
constexpr int CD = H * LD;                // 512
constexpr int GM = BL;                    // 4096
constexpr int NB = 2 * D + CD;            // 4608 B rows (Wq|Wk|Wveff)

constexpr int BK     = 32;
constexpr int STAGES = 3;
constexpr int ROWB   = 80;
constexpr int OFF_B  = 256 * ROWB;
constexpr int STAGEB = 384 * ROWB;        // 30720
constexpr int SMEMB  = STAGES * STAGEB;   // 92160

constexpr int SMEM_PREP = (HD * 36 + HD * 132) * 4;  // 86016
}

// ---------------- scratch ----------------------------------------------------
__device__ __half g_q16[GM * D];     // q fp16 (b,l,h,hd)
__device__ __half g_k16[GM * D];
__device__ __half g_qch[BHLLD];      // (b,h,l,e)
__device__ __half g_kch[BHLLD];
__device__ __half g_vch[BHLLD];
__device__ __half g_ao[BL * CD];     // attn out fp16 (b*l, h*32+e)
__device__ __half g_a16[GM * D];     // x fp16 [M,K]
__device__ __half g_wB[(size_t)NB * D];  // Wq|Wk|Wveff fp16 [N,K]
__device__ __half g_wo[D * CD];      // Weffo fp16 [N=2048, K=512]
__device__ float  g_bo[D];
__device__ float  g_bv[CD];

// ================= PTX helpers ==============================================
__device__ __forceinline__ uint32_t smem_u32(const void* p) {
    uint32_t a;
    asm("{ .reg .u64 t; cvta.to.shared.u64 t, %1; cvt.u32.u64 %0, t; }"
        : "=r"(a) : "l"(p));
    return a;
}
__device__ __forceinline__ uint32_t h2_u32(__half2 h) {
    return *reinterpret_cast<uint32_t*>(&h);
}
__device__ __forceinline__ void cp_async16(uint32_t dst, const void* src) {
    asm volatile("cp.async.cg.shared.global [%0], [%1], 16;"
                 :: "r"(dst), "l"(src) : "memory");
}
__device__ __forceinline__ void cp_commit() {
    asm volatile("cp.async.commit_group;" ::: "memory");
}
template <int N>
__device__ __forceinline__ void cp_wait() {
    asm volatile("cp.async.wait_group %0;" :: "n"(N) : "memory");
}
__device__ __forceinline__ void ldsm4(uint32_t* r, uint32_t addr) {
    asm volatile("ldmatrix.sync.aligned.m8n8.x4.shared.b16 {%0,%1,%2,%3}, [%4];"
                 : "=r"(r[0]), "=r"(r[1]), "=r"(r[2]), "=r"(r[3]) : "r"(addr));
}
__device__ __forceinline__ void ldsm4t(uint32_t* r, uint32_t addr) {
    asm volatile("ldmatrix.sync.aligned.m8n8.x4.trans.shared.b16 {%0,%1,%2,%3}, [%4];"
                 : "=r"(r[0]), "=r"(r[1]), "=r"(r[2]), "=r"(r[3]) : "r"(addr));
}
__device__ __forceinline__ void mma16816(float* d, const uint32_t* a,
                                         uint32_t b0, uint32_t b1) {
    asm volatile(
        "mma.sync.aligned.m16n8k16.row.col.f32.f16.f16.f32 "
        "{%0,%1,%2,%3}, {%4,%5,%6,%7}, {%8,%9}, {%0,%1,%2,%3};"
        : "+f"(d[0]), "+f"(d[1]), "+f"(d[2]), "+f"(d[3])
        : "r"(a[0]), "r"(a[1]), "r"(a[2]), "r"(a[3]), "r"(b0), "r"(b1));
}

// ================= conversion / precompute ==================================
__global__ void __launch_bounds__(256) convert_a_kernel(
    const float* __restrict__ X, __half* __restrict__ out)
{
    long long i = ((long long)blockIdx.x * 256 + threadIdx.x) * 4;
    float4 v = *(const float4*)(X + i);
    *(__half2*)(out + i)     = __floats2half2_rn(v.x, v.y);
    *(__half2*)(out + i + 2) = __floats2half2_rn(v.z, v.w);
}

// Wq/Wk [K,N] -> transposed [N,K] fp16 into wB. grid (D/32, D/64, 2), blk (32,8)
__global__ void __launch_bounds__(256) convert_wqk_kernel(
    const float* __restrict__ Wq, const float* __restrict__ Wk,
    __half* __restrict__ wB)
{
    __shared__ float t[64][33];
    const float* W = blockIdx.z ? Wk : Wq;
    __half* dst = wB + (size_t)blockIdx.z * D * D;
    const int n0 = blockIdx.x * 32, k0 = blockIdx.y * 64;
    const int tx = threadIdx.x, ty = threadIdx.y;
    #pragma unroll
    for (int i = 0; i < 8; i++)
        t[ty + i * 8][tx] = W[(size_t)(k0 + ty + i * 8) * D + n0 + tx];
    __syncthreads();
    #pragma unroll
    for (int i = 0; i < 4; i++) {
        const int nr = ty + i * 8;
        *(__half2*)(dst + (size_t)(n0 + nr) * D + k0 + 2 * tx) =
            __floats2half2_rn(t[2 * tx][nr], t[2 * tx + 1][nr]);
    }
}

// Wveff[h*32+e][i] = sum_d Wvc[d][e]*Wv[i][h*128+d] -> wB rows 4096+.
// grid (D/128, H), 256 thr, dynamic smem, float4 operands, 4x4 tile.
__global__ void __launch_bounds__(256) prep_wv_kernel(
    const float* __restrict__ Wv, const float* __restrict__ Wvc,
    __half* __restrict__ w16v)
{
    extern __shared__ float psm[];
    float (*a_s)[36]  = (float(*)[36])psm;              // [d][e]
    float (*b_s)[132] = (float(*)[132])(psm + HD * 36); // [d][il]
    const int h = blockIdx.y, i0 = blockIdx.x * 128;
    const int tid = threadIdx.x;
    for (int idx = tid; idx < HD * LD; idx += 256) {
        const int d = idx >> 5, e = idx & 31;
        a_s[d][e] = Wvc[idx];
    }
    for (int idx = tid; idx < 128 * HD; idx += 256) {
        const int il = idx >> 7, d = idx & 127;   // d contiguous: coalesced
        b_s[d][il] = Wv[(size_t)(i0 + il) * D + h * HD + d];
    }
    __syncthreads();
    const int e0  = (tid & 7) * 4;
    const int il0 = (tid >> 3) * 4;
    float acc[4][4] = {};
    #pragma unroll 4
    for (int d = 0; d < HD; d++) {
        const float4 a4 = *(const float4*)&a_s[d][e0];
        const float4 b4 = *(const float4*)&b_s[d][il0];
        acc[0][0] += a4.x * b4.x; acc[0][1] += a4.x * b4.y;
        acc[0][2] += a4.x * b4.z; acc[0][3] += a4.x * b4.w;
        acc[1][0] += a4.y * b4.x; acc[1][1] += a4.y * b4.y;
        acc[1][2] += a4.y * b4.z; acc[1][3] += a4.y * b4.w;
        acc[2][0] += a4.z * b4.x; acc[2][1] += a4.z * b4.y;
        acc[2][2] += a4.z * b4.z; acc[2][3] += a4.z * b4.w;
        acc[3][0] += a4.w * b4.x; acc[3][1] += a4.w * b4.y;
        acc[3][2] += a4.w * b4.z; acc[3][3] += a4.w * b4.w;
    }
    #pragma unroll
    for (int j = 0; j < 4; j++) {
        __half2* dst = (__half2*)(w16v + (size_t)(h * LD + e0 + j) * D
                                  + i0 + il0);
        dst[0] = __floats2half2_rn(acc[j][0], acc[j][1]);
        dst[1] = __floats2half2_rn(acc[j][2], acc[j][3]);
    }
}

// Weffo[n][h*32+e] = sum_d Wd[e][d]*Wo[h*128+d][n]. grid (D/128, H), 256 thr.
__global__ void __launch_bounds__(256) prep_wo_kernel(
    const float* __restrict__ Wd, const float* __restrict__ Wo,
    __half* __restrict__ w16o)
{
    extern __shared__ float psm[];
    float (*a_s)[36]  = (float(*)[36])psm;              // [d][e]
    float (*b_s)[132] = (float(*)[132])(psm + HD * 36); // [d][nl]
    const int h = blockIdx.y, n0 = blockIdx.x * 128;
    const int tid = threadIdx.x;
    for (int idx = tid; idx < LD * HD; idx += 256) {
        const int e = idx >> 7, d = idx & 127;    // d contiguous: coalesced
        a_s[d][e] = Wd[idx];
    }
    for (int idx = tid; idx < HD * 128; idx += 256) {
        const int d = idx >> 7, nl = idx & 127;   // nl contiguous: coalesced
        b_s[d][nl] = Wo[(size_t)(h * HD + d) * D + n0 + nl];
    }
    __syncthreads();
    const int e0  = (tid & 7) * 4;
    const int nl0 = (tid >> 3) * 4;
    float acc[4][4] = {};
    #pragma unroll 4
    for (int d = 0; d < HD; d++) {
        const float4 a4 = *(const float4*)&a_s[d][e0];
        const float4 b4 = *(const float4*)&b_s[d][nl0];
        acc[0][0] += a4.x * b4.x; acc[0][1] += a4.x * b4.y;
        acc[0][2] += a4.x * b4.z; acc[0][3] += a4.x * b4.w;
        acc[1][0] += a4.y * b4.x; acc[1][1] += a4.y * b4.y;
        acc[1][2] += a4.y * b4.z; acc[1][3] += a4.y * b4.w;
        acc[2][0] += a4.z * b4.x; acc[2][1] += a4.z * b4.y;
        acc[2][2] += a4.z * b4.z; acc[2][3] += a4.z * b4.w;
        acc[3][0] += a4.w * b4.x; acc[3][1] += a4.w * b4.y;
        acc[3][2] += a4.w * b4.z; acc[3][3] += a4.w * b4.w;
    }
    #pragma unroll
    for (int i = 0; i < 4; i++) {
        __half2* dst = (__half2*)(w16o + (size_t)(n0 + nl0 + i) * CD
                                  + h * LD + e0);
        dst[0] = __floats2half2_rn(acc[0][i], acc[1][i]);
        dst[1] = __floats2half2_rn(acc[2][i], acc[3][i]);
    }
}

// bias_o[n] = sum_r bd[r%128]*Wo[r,n] + bo[n].  grid 64, block 256
__global__ void __launch_bounds__(256) prep_bias_o_kernel(
    const float* __restrict__ bd, const float* __restrict__ Wo,
    const float* __restrict__ bo, float* __restrict__ bias_o)
{
    __shared__ float part[8][32];
    const int tid = threadIdx.x;
    const int nl = tid & 31, rc = tid >> 5;
    const int n = blockIdx.x * 32 + nl;
    float acc = 0.f;
    for (int r = rc * 256; r < rc * 256 + 256; r++)
        acc += bd[r & 127] * Wo[(size_t)r * D + n];
    part[rc][nl] = acc;
    __syncthreads();
    if (tid < 32) {
        float s = bo[blockIdx.x * 32 + tid];
        #pragma unroll
        for (int j = 0; j < 8; j++) s += part[j][tid];
        bias_o[blockIdx.x * 32 + tid] = s;
    }
}

// bveff[h*32+e] = sum_d bv[h*128+d]*Wvc[d,e] + bvc[e]
__global__ void __launch_bounds__(256) prep_bias_v_kernel(
    const float* __restrict__ bv, const float* __restrict__ Wvc,
    const float* __restrict__ bvc, float* __restrict__ bveff)
{
    for (int o = threadIdx.x; o < CD; o += 256) {
        const int h = o >> 5, e = o & 31;
        float acc = bvc[e];
        for (int d = 0; d < HD; d++)
            acc += bv[h * HD + d] * Wvc[d * LD + e];
        bveff[o] = acc;
    }
}

// ================= unified QKV GEMM (K=2048, N=4608) ========================
__device__ __forceinline__ void load_stage_qkv(
    uint32_t sbase, const __half* pA, const __half* pB, int kc, int tid)
{
    const int r0 = tid >> 2, seg = tid & 3;
    const uint32_t so = sbase + r0 * ROWB + seg * 16;
    const size_t go = (size_t)r0 * D + kc + seg * 8;
    #pragma unroll
    for (int j = 0; j < 4; j++)
        cp_async16(so + j * 64 * ROWB, pA + go + (size_t)j * 64 * D);
    #pragma unroll
    for (int j = 0; j < 2; j++)
        cp_async16(so + (256 + j * 64) * ROWB, pB + go + (size_t)j * 64 * D);
}

__global__ void __launch_bounds__(256) gemm_qkv_kernel(
    const __half* __restrict__ A16, const __half* __restrict__ wB,
    const float* __restrict__ bq, const float* __restrict__ bk,
    const float* __restrict__ bveff,
    __half* __restrict__ q16, __half* __restrict__ k16,
    __half* __restrict__ vch)
{
    constexpr int NITL = D / BK;   // 64
    extern __shared__ char smem[];
    const uint32_t sb0 = smem_u32(smem);
    const int tid = threadIdx.x, wid = tid >> 5, lane = tid & 31;
    const int warp_m = (wid & 3) * 64;
    const int warp_n = (wid >> 2) * 64;
    const int m0 = blockIdx.y * 256;
    const int n0 = blockIdx.x * 128;

    const __half* pA = A16 + (size_t)m0 * D;
    const __half* pB = wB  + (size_t)n0 * D;

    float acc[4][8][4];
    #pragma unroll
    for (int i = 0; i < 4; i++)
        #pragma unroll
        for (int j = 0; j < 8; j++)
            #pragma unroll
            for (int t = 0; t < 4; t++) acc[i][j][t] = 0.f;

    const int arow = ((lane >> 3) & 1) * 8 + (lane & 7);
    const int acol = (lane >> 4) * 16;
    const int brow = (lane >> 4) * 8 + (lane & 7);
    const int bcol = ((lane >> 3) & 1) * 16;

    load_stage_qkv(sb0, pA, pB, 0, tid);
    cp_commit();
    load_stage_qkv(sb0 + STAGEB, pA, pB, BK, tid);
    cp_commit();

    #pragma unroll 1
    for (int kt = 0; kt < NITL; kt++) {
        cp_wait<1>();
        __syncthreads();
        if (kt + 2 < NITL)
            load_stage_qkv(sb0 + ((kt + 2) % STAGES) * STAGEB,
                           pA, pB, (kt + 2) * BK, tid);
        cp_commit();

        const uint32_t sb = sb0 + (kt % STAGES) * STAGEB;
        #pragma unroll
        for (int ks = 0; ks < 2; ks++) {
            uint32_t ah[4][4];
            #pragma unroll
            for (int mt = 0; mt < 4; mt++)
                ldsm4(ah[mt], sb + (warp_m + mt * 16 + arow) * ROWB
                              + ks * 32 + acol);
            uint32_t bh[4][4];
            #pragma unroll
            for (int np = 0; np < 4; np++)
                ldsm4(bh[np], sb + OFF_B + (warp_n + np * 16 + brow) * ROWB
                              + ks * 32 + bcol);
            #pragma unroll
            for (int mt = 0; mt < 4; mt++)
                #pragma unroll
                for (int nt = 0; nt < 8; nt++) {
                    const int np = nt >> 1, pp = (nt & 1) * 2;
                    mma16816(acc[mt][nt], ah[mt], bh[np][pp], bh[np][pp + 1]);
                }
        }
    }

    if (n0 < 2 * D) {
        __half* C = (n0 < D) ? q16 : k16;
        const float* bias = (n0 < D) ? bq : bk;
        const int nc0 = (n0 < D) ? n0 : n0 - D;
        #pragma unroll
        for (int mt = 0; mt < 4; mt++) {
            const int row = m0 + warp_m + mt * 16 + (lane >> 2);
            #pragma unroll
            for (int nt = 0; nt < 8; nt++) {
                const int col = nc0 + warp_n + nt * 8 + (lane & 3) * 2;
                const float b0 = bias[col], b1 = bias[col + 1];
                *(__half2*)(C + (size_t)row * D + col) =
                    __floats2half2_rn(acc[mt][nt][0] + b0, acc[mt][nt][1] + b1);
                *(__half2*)(C + (size_t)(row + 8) * D + col) =
                    __floats2half2_rn(acc[mt][nt][2] + b0, acc[mt][nt][3] + b1);
            }
        }
    } else {
        const int ncv = n0 - 2 * D;
        #pragma unroll
        for (int mt = 0; mt < 4; mt++) {
            const int row = m0 + warp_m + mt * 16 + (lane >> 2);
            const int b0i = row >> 11, l0i = row & (L - 1);
            const int b1i = (row + 8) >> 11, l1i = (row + 8) & (L - 1);
            #pragma unroll
            for (int nt = 0; nt < 8; nt++) {
                const int col = ncv + warp_n + nt * 8 + (lane & 3) * 2;
                const int h = col >> 5, e = col & 31;
                const float bb0 = bveff[col], bb1 = bveff[col + 1];
                *(__half2*)(vch + ((size_t)(b0i * H + h) * L + l0i) * LD + e) =
                    __floats2half2_rn(acc[mt][nt][0] + bb0,
                                      acc[mt][nt][1] + bb1);
                *(__half2*)(vch + ((size_t)(b1i * H + h) * L + l1i) * LD + e) =
                    __floats2half2_rn(acc[mt][nt][2] + bb0,
                                      acc[mt][nt][3] + bb1);
            }
        }
    }
}

// ================= output GEMM (K=512) ======================================
__device__ __forceinline__ void load_stage_out(
    uint32_t sbase, const __half* pA, const __half* pB, int kc, int tid)
{
    const int r0 = tid >> 2, seg = tid & 3;
    const uint32_t so = sbase + r0 * ROWB + seg * 16;
    const size_t go = (size_t)r0 * CD + kc + seg * 8;
    #pragma unroll
    for (int j = 0; j < 4; j++)
        cp_async16(so + j * 64 * ROWB, pA + go + (size_t)j * 64 * CD);
    #pragma unroll
    for (int j = 0; j < 2; j++)
        cp_async16(so + (256 + j * 64) * ROWB, pB + go + (size_t)j * 64 * CD);
}

__global__ void __launch_bounds__(256) gemm_out_kernel(
    const __half* __restrict__ A16, const __half* __restrict__ Bw,
    const float* __restrict__ bias, float* __restrict__ C)
{
    constexpr int NITL = CD / BK;  // 16
    extern __shared__ char smem[];
    const uint32_t sb0 = smem_u32(smem);
    const int tid = threadIdx.x, wid = tid >> 5, lane = tid & 31;
    const int warp_m = (wid & 3) * 64;
    const int warp_n = (wid >> 2) * 64;
    const int m0 = blockIdx.y * 256, n0 = blockIdx.x * 128;

    const __half* pA = A16 + (size_t)m0 * CD;
    const __half* pB = Bw  + (size_t)n0 * CD;

    float acc[4][8][4];
    #pragma unroll
    for (int i = 0; i < 4; i++)
        #pragma unroll
        for (int j = 0; j < 8; j++)
            #pragma unroll
            for (int t = 0; t < 4; t++) acc[i][j][t] = 0.f;

    const int arow = ((lane >> 3) & 1) * 8 + (lane & 7);
    const int acol = (lane >> 4) * 16;
    const int brow = (lane >> 4) * 8 + (lane & 7);
    const int bcol = ((lane >> 3) & 1) * 16;

    load_stage_out(sb0, pA, pB, 0, tid);
    cp_commit();
    load_stage_out(sb0 + STAGEB, pA, pB, BK, tid);
    cp_commit();

    #pragma unroll 1
    for (int kt = 0; kt < NITL; kt++) {
        cp_wait<1>();
        __syncthreads();
        if (kt + 2 < NITL)
            load_stage_out(sb0 + ((kt + 2) % STAGES) * STAGEB,
                           pA, pB, (kt + 2) * BK, tid);
        cp_commit();

        const uint32_t sb = sb0 + (kt % STAGES) * STAGEB;
        #pragma unroll
        for (int ks = 0; ks < 2; ks++) {
            uint32_t ah[4][4];
            #pragma unroll
            for (int mt = 0; mt < 4; mt++)
                ldsm4(ah[mt], sb + (warp_m + mt * 16 + arow) * ROWB
                              + ks * 32 + acol);
            uint32_t bh[4][4];
            #pragma unroll
            for (int np = 0; np < 4; np++)
                ldsm4(bh[np], sb + OFF_B + (warp_n + np * 16 + brow) * ROWB
                              + ks * 32 + bcol);
            #pragma unroll
            for (int mt = 0; mt < 4; mt++)
                #pragma unroll
                for (int nt = 0; nt < 8; nt++) {
                    const int np = nt >> 1, pp = (nt & 1) * 2;
                    mma16816(acc[mt][nt], ah[mt], bh[np][pp], bh[np][pp + 1]);
                }
        }
    }

    #pragma unroll
    for (int mt = 0; mt < 4; mt++) {
        const int row = m0 + warp_m + mt * 16 + (lane >> 2);
        #pragma unroll
        for (int nt = 0; nt < 8; nt++) {
            const int col = n0 + warp_n + nt * 8 + (lane & 3) * 2;
            const float b0 = bias[col], b1 = bias[col + 1];
            *(float2*)(C + (size_t)row * D + col) =
                make_float2(acc[mt][nt][0] + b0, acc[mt][nt][1] + b1);
            *(float2*)(C + (size_t)(row + 8) * D + col) =
                make_float2(acc[mt][nt][2] + b0, acc[mt][nt][3] + b1);
        }
    }
}

// ---------------- compress (+ fused RoPE), q & k in one launch, fp16 in -----
__global__ void __launch_bounds__(256) compress_kernel(
    const __half* __restrict__ Q, const __half* __restrict__ K,
    const float* __restrict__ Wqc, const float* __restrict__ Wkc,
    const float* __restrict__ bqc, const float* __restrict__ bkc,
    __half* __restrict__ qch, __half* __restrict__ kch,
    const float* __restrict__ cosT, const float* __restrict__ sinT)
{
    __shared__ float Ws[HD][LD];
    __shared__ float xs[32][HD];
    const int z = blockIdx.z;
    const __half* X = z ? K : Q;
    const float* Wc = z ? Wkc : Wqc;
    const float* bc = z ? bkc : bqc;
    __half* Xc = z ? kch : qch;
    const int bh = blockIdx.y;
    const int b = bh / H, h = bh % H;
    const int l0 = blockIdx.x * 32;
    const int tid = threadIdx.x;
    for (int i = tid; i < HD * LD; i += 256) Ws[i / LD][i % LD] = Wc[i];
    for (int i = tid; i < 32 * 64; i += 256) {
        const int li = i >> 6, p = i & 63;
        const int l = l0 + li;
        float2 xv = __half22float2(*(const __half2*)&X[
            ((size_t)((b * L + l) * H + h)) * HD + 2 * p]);
        const float c = cosT[l * 64 + p];
        const float s = sinT[l * 64 + p];
        xs[li][2 * p]     = xv.x * c - xv.y * s;
        xs[li][2 * p + 1] = xv.x * s + xv.y * c;
    }
    __syncthreads();
    const int row = tid >> 3;
    const int e0  = (tid & 7) * 4;
    float4 acc = *(const float4*)(bc + e0);
    #pragma unroll
    for (int d = 0; d < HD; d++) {
        const float xv = xs[row][d];
        const float4 w = *(const float4*)&Ws[d][e0];
        acc.x += xv * w.x; acc.y += xv * w.y;
        acc.z += xv * w.z; acc.w += xv * w.w;
    }
    __half2* dst = (__half2*)(Xc + ((size_t)bh * L + l0 + row) * LD + e0);
    dst[0] = __floats2half2_rn(acc.x, acc.y);
    dst[1] = __floats2half2_rn(acc.z, acc.w);
}

// ---------------- tensor-core causal flash attention ------------------------
__global__ void __launch_bounds__(128) attn_kernel(
    const __half* __restrict__ qc, const __half* __restrict__ kc,
    const __half* __restrict__ vc, __half* __restrict__ ao)
{
    __shared__ __half qs[64][40];
    __shared__ __half ks[64][40];
    __shared__ __half vs[64][40];
    constexpr float SCALE = 0.17677669529663687f;

    const int bh  = blockIdx.y;
    const int q0  = (gridDim.x - 1 - blockIdx.x) * 64;
    const int tid = threadIdx.x;
    const int w = tid >> 5, lane = tid & 31;

    const __half* bq = qc + ((size_t)bh * L + q0) * LD;
    const __half* bk = kc + (size_t)bh * L * LD;
    const __half* bv = vc + (size_t)bh * L * LD;

    for (int i = tid; i < 256; i += 128) {
        const int r = i >> 2, c = i & 3;
        *(uint4*)((char*)&qs[r][0] + c * 16) =
            *(const uint4*)((const char*)(bq + (size_t)r * LD) + c * 16);
    }
    __syncthreads();

    const uint32_t qs_b = smem_u32(qs);
    const uint32_t ks_b = smem_u32(ks);
    const uint32_t vs_b = smem_u32(vs);

    const int arow = ((lane >> 3) & 1) * 8 + (lane & 7);
    const int acol = (lane >> 4) * 16;
    const int brow = (lane >> 4) * 8 + (lane & 7);
    const int bcol = ((lane >> 3) & 1) * 16;

    uint32_t aq[2][4];
    #pragma unroll
    for (int ks2 = 0; ks2 < 2; ks2++)
        ldsm4(aq[ks2], qs_b + (w * 16 + arow) * 80 + ks2 * 32 + acol);

    float o[4][4];
    #pragma unroll
    for (int i = 0; i < 4; i++)
        #pragma unroll
        for (int j = 0; j < 4; j++) o[i][j] = 0.f;
    float m_lo = -INFINITY, m_hi = -INFINITY, l_lo = 0.f, l_hi = 0.f;

    const int nt = q0 / 64 + 1;
    const int row_lo = q0 + w * 16 + (lane >> 2);
    const int row_hi = row_lo + 8;

    for (int t = 0; t < nt; t++) {
        __syncthreads();
        for (int i = tid; i < 512; i += 128) {
            const int mtx = i >> 8;
            const int r = (i >> 2) & 63, c = i & 3;
            const __half* src = (mtx ? bv : bk) + ((size_t)(t * 64 + r)) * LD;
            __half* dst = mtx ? &vs[r][0] : &ks[r][0];
            *(uint4*)((char*)dst + c * 16) =
                *(const uint4*)((const char*)src + c * 16);
        }
        __syncthreads();

        float s[8][4];
        #pragma unroll
        for (int i = 0; i < 8; i++)
            #pragma unroll
            for (int j = 0; j < 4; j++) s[i][j] = 0.f;
        #pragma unroll
        for (int ks2 = 0; ks2 < 2; ks2++) {
            #pragma unroll
            for (int ng = 0; ng < 4; ng++) {
                uint32_t bkf[4];
                ldsm4(bkf, ks_b + (ng * 16 + brow) * 80 + ks2 * 32 + bcol);
                mma16816(s[ng * 2],     aq[ks2], bkf[0], bkf[1]);
                mma16816(s[ng * 2 + 1], aq[ks2], bkf[2], bkf[3]);
            }
        }

        const bool diag = (t == nt - 1);
        #pragma unroll
        for (int nf = 0; nf < 8; nf++) {
            const int col = t * 64 + nf * 8 + (lane & 3) * 2;
            #pragma unroll
            for (int j = 0; j < 4; j++) s[nf][j] *= SCALE;
            if (diag) {
                if (col     > row_lo) s[nf][0] = -INFINITY;
                if (col + 1 > row_lo) s[nf][1] = -INFINITY;
                if (col     > row_hi) s[nf][2] = -INFINITY;
                if (col + 1 > row_hi) s[nf][3] = -INFINITY;
            }
        }

        float tm_lo = -INFINITY, tm_hi = -INFINITY;
        #pragma unroll
        for (int nf = 0; nf < 8; nf++) {
            tm_lo = fmaxf(tm_lo, fmaxf(s[nf][0], s[nf][1]));
            tm_hi = fmaxf(tm_hi, fmaxf(s[nf][2], s[nf][3]));
        }
        #pragma unroll
        for (int off = 1; off <= 2; off <<= 1) {
            tm_lo = fmaxf(tm_lo, __shfl_xor_sync(0xffffffffu, tm_lo, off));
            tm_hi = fmaxf(tm_hi, __shfl_xor_sync(0xffffffffu, tm_hi, off));
        }
        const float mn_lo = fmaxf(m_lo, tm_lo);
        const float mn_hi = fmaxf(m_hi, tm_hi);
        const float al_lo = __expf(m_lo - mn_lo);
        const float al_hi = __expf(m_hi - mn_hi);
        m_lo = mn_lo; m_hi = mn_hi;

        float ps_lo = 0.f, ps_hi = 0.f;
        #pragma unroll
        for (int nf = 0; nf < 8; nf++) {
            s[nf][0] = __expf(s[nf][0] - mn_lo);
            s[nf][1] = __expf(s[nf][1] - mn_lo);
            s[nf][2] = __expf(s[nf][2] - mn_hi);
            s[nf][3] = __expf(s[nf][3] - mn_hi);
            ps_lo += s[nf][0] + s[nf][1];
            ps_hi += s[nf][2] + s[nf][3];
        }
        #pragma unroll
        for (int off = 1; off <= 2; off <<= 1) {
            ps_lo += __shfl_xor_sync(0xffffffffu, ps_lo, off);
            ps_hi += __shfl_xor_sync(0xffffffffu, ps_hi, off);
        }
        l_lo = l_lo * al_lo + ps_lo;
        l_hi = l_hi * al_hi + ps_hi;

        #pragma unroll
        for (int nf = 0; nf < 4; nf++) {
            o[nf][0] *= al_lo; o[nf][1] *= al_lo;
            o[nf][2] *= al_hi; o[nf][3] *= al_hi;
        }

        #pragma unroll
        for (int kc4 = 0; kc4 < 4; kc4++) {
            uint32_t ap[4];
            const int f0 = 2 * kc4, f1 = 2 * kc4 + 1;
            ap[0] = h2_u32(__floats2half2_rn(s[f0][0], s[f0][1]));
            ap[1] = h2_u32(__floats2half2_rn(s[f0][2], s[f0][3]));
            ap[2] = h2_u32(__floats2half2_rn(s[f1][0], s[f1][1]));
            ap[3] = h2_u32(__floats2half2_rn(s[f1][2], s[f1][3]));
            #pragma unroll
            for (int half = 0; half < 2; half++) {
                uint32_t bvf[4];
                ldsm4t(bvf, vs_b + (kc4 * 16 + arow) * 80 + half * 32 + acol);
                mma16816(o[half * 2],     ap, bvf[0], bvf[1]);
                mma16816(o[half * 2 + 1], ap, bvf[2], bvf[3]);
            }
        }
    }

    const int b = bh / H, h = bh % H;
    const float inv_lo = 1.f / l_lo, inv_hi = 1.f / l_hi;
    #pragma unroll
    for (int nf = 0; nf < 4; nf++) {
        const int e = nf * 8 + (lane & 3) * 2;
        __half* p_lo = ao + (size_t)(b * L + row_lo) * CD + h * LD + e;
        __half* p_hi = ao + (size_t)(b * L + row_hi) * CD + h * LD + e;
        *(__half2*)p_lo = __floats2half2_rn(o[nf][0] * inv_lo, o[nf][1] * inv_lo);
        *(__half2*)p_hi = __floats2half2_rn(o[nf][2] * inv_hi, o[nf][3] * inv_hi);
    }
}

// ---------------------------------------------------------------------------
extern "C" void kernel_launch(void* const* d_in, const int* in_sizes, int n_in,
                              void* d_out, int out_size)
{
    const float* x    = (const float*)d_in[0];
    const float* cosT = (const float*)d_in[1];
    const float* sinT = (const float*)d_in[2];
    const float* Wq   = (const float*)d_in[3];
    const float* bq   = (const float*)d_in[4];
    const float* Wk   = (const float*)d_in[5];
    const float* bk   = (const float*)d_in[6];
    const float* Wv   = (const float*)d_in[7];
    const float* bv   = (const float*)d_in[8];
    const float* Wqc  = (const float*)d_in[9];
    const float* bqc  = (const float*)d_in[10];
    const float* Wkc  = (const float*)d_in[11];
    const float* bkc  = (const float*)d_in[12];
    const float* Wvc  = (const float*)d_in[13];
    const float* bvc  = (const float*)d_in[14];
    const float* Wd   = (const float*)d_in[15];
    const float* bd   = (const float*)d_in[16];
    const float* Wo   = (const float*)d_in[17];
    const float* bo   = (const float*)d_in[18];
    float* out = (float*)d_out;

    float *bias_o, *bveff;
    __half *q16, *k16, *qch, *kch, *vch, *ao, *a16, *wB, *wo;
    cudaGetSymbolAddress((void**)&q16,    g_q16);
    cudaGetSymbolAddress((void**)&k16,    g_k16);
    cudaGetSymbolAddress((void**)&qch,    g_qch);
    cudaGetSymbolAddress((void**)&kch,    g_kch);
    cudaGetSymbolAddress((void**)&vch,    g_vch);
    cudaGetSymbolAddress((void**)&ao,     g_ao);
    cudaGetSymbolAddress((void**)&a16,    g_a16);
    cudaGetSymbolAddress((void**)&wB,     g_wB);
    cudaGetSymbolAddress((void**)&wo,     g_wo);
    cudaGetSymbolAddress((void**)&bias_o, g_bo);
    cudaGetSymbolAddress((void**)&bveff,  g_bv);

    cudaFuncSetAttribute(gemm_qkv_kernel,
                         cudaFuncAttributeMaxDynamicSharedMemorySize, SMEMB);
    cudaFuncSetAttribute(gemm_out_kernel,
                         cudaFuncAttributeMaxDynamicSharedMemorySize, SMEMB);
    cudaFuncSetAttribute(prep_wv_kernel,
                         cudaFuncAttributeMaxDynamicSharedMemorySize, SMEM_PREP);
    cudaFuncSetAttribute(prep_wo_kernel,
                         cudaFuncAttributeMaxDynamicSharedMemorySize, SMEM_PREP);

    // --- conversions + weight folding ---
    convert_a_kernel<<<(GM * D / 4) / 256, 256>>>(x, a16);
    convert_wqk_kernel<<<dim3(D / 32, D / 64, 2), dim3(32, 8)>>>(Wq, Wk, wB);
    prep_wv_kernel<<<dim3(D / 128, H), 256, SMEM_PREP>>>(
        Wv, Wvc, wB + (size_t)2 * D * D);
    prep_wo_kernel<<<dim3(D / 128, H), 256, SMEM_PREP>>>(Wd, Wo, wo);
    prep_bias_o_kernel<<<D / 32, 256>>>(bd, Wo, bo, bias_o);
    prep_bias_v_kernel<<<1, 256>>>(bv, Wvc, bvc, bveff);

    // --- unified Q,K,Vc GEMM (fp16 q/k out) ---
    gemm_qkv_kernel<<<dim3(NB / 128, GM / 256), 256, SMEMB>>>(
        a16, wB, bq, bk, bveff, q16, k16, vch);

    // --- compress + rope for q,k (single launch) ---
    compress_kernel<<<dim3(L / 32, B * H, 2), 256>>>(
        q16, k16, Wqc, Wkc, bqc, bkc, qch, kch, cosT, sinT);

    // --- attention ---
    attn_kernel<<<dim3(L / 64, B * H), 128>>>(qch, kch, vch, ao);

    // --- decompress+output projection folded ---
    gemm_out_kernel<<<dim3(D / 128, GM / 256), 256, SMEMB>>>(
        ao, wo, bias_o, out);
}

// round 15
// speedup vs baseline: 8.6883x; 1.0149x over previous
#include <cuda_runtime.h>
#include <cuda_fp16.h>
#include <math.h>
#include <cstdint>

namespace {
constexpr int B  = 2;
constexpr int L  = 2048;
constexpr int D  = 2048;
constexpr int H  = 16;
constexpr int HD = 128;
constexpr int LD = 32;
constexpr int BL = B * L;                 // 4096
constexpr int BHLLD = B * H * L * LD;     // 2097152
constexpr int CD = H * LD;                // 512
constexpr int GM = BL;                    // 4096
constexpr int NB = 2 * D + CD;            // 4608 B rows (Wq|Wk|Wveff)

constexpr int BK     = 32;
constexpr int STAGES = 3;
constexpr int ROWB   = 80;
constexpr int OFF_B  = 256 * ROWB;
constexpr int STAGEB = 384 * ROWB;        // 30720
constexpr int SMEMB  = STAGES * STAGEB;   // 92160

// prep kernels (dynamic smem)
constexpr int SMEM_WV = (32 * 130 + 128 * 130) * 2;        // 41600
constexpr int SMEM_WO = 128 * 36 * 4 + 128 * 132 * 2;      // 52224
}

// ---------------- scratch ----------------------------------------------------
__device__ __half g_q16[GM * D];     // q fp16 (b,l,h,hd)
__device__ __half g_k16[GM * D];
__device__ __half g_qch[BHLLD];      // (b,h,l,e)
__device__ __half g_kch[BHLLD];
__device__ __half g_vch[BHLLD];
__device__ __half g_ao[BL * CD];     // attn out fp16 (b*l, h*32+e)
__device__ __half g_a16[GM * D];     // x fp16 [M,K]
__device__ __half g_wB[(size_t)NB * D];  // Wq|Wk|Wveff fp16 [N,K]
__device__ __half g_wo[D * CD];      // Weffo fp16 [N=2048, K=512]
__device__ float  g_bo[D];
__device__ float  g_bv[CD];

// ================= PTX helpers ==============================================
__device__ __forceinline__ uint32_t smem_u32(const void* p) {
    uint32_t a;
    asm("{ .reg .u64 t; cvta.to.shared.u64 t, %1; cvt.u32.u64 %0, t; }"
        : "=r"(a) : "l"(p));
    return a;
}
__device__ __forceinline__ uint32_t h2_u32(__half2 h) {
    return *reinterpret_cast<uint32_t*>(&h);
}
__device__ __forceinline__ void cp_async16(uint32_t dst, const void* src) {
    asm volatile("cp.async.cg.shared.global [%0], [%1], 16;"
                 :: "r"(dst), "l"(src) : "memory");
}
__device__ __forceinline__ void cp_commit() {
    asm volatile("cp.async.commit_group;" ::: "memory");
}
template <int N>
__device__ __forceinline__ void cp_wait() {
    asm volatile("cp.async.wait_group %0;" :: "n"(N) : "memory");
}
__device__ __forceinline__ void ldsm4(uint32_t* r, uint32_t addr) {
    asm volatile("ldmatrix.sync.aligned.m8n8.x4.shared.b16 {%0,%1,%2,%3}, [%4];"
                 : "=r"(r[0]), "=r"(r[1]), "=r"(r[2]), "=r"(r[3]) : "r"(addr));
}
__device__ __forceinline__ void ldsm4t(uint32_t* r, uint32_t addr) {
    asm volatile("ldmatrix.sync.aligned.m8n8.x4.trans.shared.b16 {%0,%1,%2,%3}, [%4];"
                 : "=r"(r[0]), "=r"(r[1]), "=r"(r[2]), "=r"(r[3]) : "r"(addr));
}
__device__ __forceinline__ void mma16816(float* d, const uint32_t* a,
                                         uint32_t b0, uint32_t b1) {
    asm volatile(
        "mma.sync.aligned.m16n8k16.row.col.f32.f16.f16.f32 "
        "{%0,%1,%2,%3}, {%4,%5,%6,%7}, {%8,%9}, {%0,%1,%2,%3};"
        : "+f"(d[0]), "+f"(d[1]), "+f"(d[2]), "+f"(d[3])
        : "r"(a[0]), "r"(a[1]), "r"(a[2]), "r"(a[3]), "r"(b0), "r"(b1));
}

// ================= conversion / precompute ==================================
__global__ void __launch_bounds__(256) convert_a_kernel(
    const float* __restrict__ X, __half* __restrict__ out)
{
    long long i = ((long long)blockIdx.x * 256 + threadIdx.x) * 4;
    float4 v = *(const float4*)(X + i);
    *(__half2*)(out + i)     = __floats2half2_rn(v.x, v.y);
    *(__half2*)(out + i + 2) = __floats2half2_rn(v.z, v.w);
}

// Wq/Wk [K,N] -> transposed [N,K] fp16 into wB. grid (D/32, D/64, 2), blk (32,8)
__global__ void __launch_bounds__(256) convert_wqk_kernel(
    const float* __restrict__ Wq, const float* __restrict__ Wk,
    __half* __restrict__ wB)
{
    __shared__ float t[64][33];
    const float* W = blockIdx.z ? Wk : Wq;
    __half* dst = wB + (size_t)blockIdx.z * D * D;
    const int n0 = blockIdx.x * 32, k0 = blockIdx.y * 64;
    const int tx = threadIdx.x, ty = threadIdx.y;
    #pragma unroll
    for (int i = 0; i < 8; i++)
        t[ty + i * 8][tx] = W[(size_t)(k0 + ty + i * 8) * D + n0 + tx];
    __syncthreads();
    #pragma unroll
    for (int i = 0; i < 4; i++) {
        const int nr = ty + i * 8;
        *(__half2*)(dst + (size_t)(n0 + nr) * D + k0 + 2 * tx) =
            __floats2half2_rn(t[2 * tx][nr], t[2 * tx + 1][nr]);
    }
}

// Wveff[h*32+e][i] = sum_d Wvc[d][e]*Wv[i][h*128+d] -> wB rows 4096+.
// grid (D/128, H), 256 thr. fp16 smem, d-vectorized dot products.
__global__ void __launch_bounds__(256) prep_wv_kernel(
    const float* __restrict__ Wv, const float* __restrict__ Wvc,
    __half* __restrict__ w16v)
{
    extern __shared__ __half hsm[];
    __half (*a_s)[130] = (__half(*)[130])hsm;               // [e][d]
    __half (*b_s)[130] = (__half(*)[130])(hsm + 32 * 130);  // [il][d]
    const int h = blockIdx.y, i0 = blockIdx.x * 128;
    const int tid = threadIdx.x;
    for (int idx = tid; idx < HD * LD; idx += 256) {
        const int d = idx >> 5, e = idx & 31;
        a_s[e][d] = __float2half_rn(Wvc[idx]);
    }
    for (int idx = tid; idx < 128 * 32; idx += 256) {
        const int il = idx >> 5, dq = (idx & 31) * 4;
        float4 v = *(const float4*)(Wv + (size_t)(i0 + il) * D + h * HD + dq);
        *(__half2*)&b_s[il][dq]     = __floats2half2_rn(v.x, v.y);
        *(__half2*)&b_s[il][dq + 2] = __floats2half2_rn(v.z, v.w);
    }
    __syncthreads();
    const int e0  = (tid & 7) * 4;
    const int il0 = (tid >> 3) * 4;
    float acc[4][4] = {};
    #pragma unroll 8
    for (int d = 0; d < HD; d += 2) {
        float2 av[4], bv[4];
        #pragma unroll
        for (int j = 0; j < 4; j++)
            av[j] = __half22float2(*(const __half2*)&a_s[e0 + j][d]);
        #pragma unroll
        for (int i = 0; i < 4; i++)
            bv[i] = __half22float2(*(const __half2*)&b_s[il0 + i][d]);
        #pragma unroll
        for (int j = 0; j < 4; j++)
            #pragma unroll
            for (int i = 0; i < 4; i++)
                acc[j][i] += av[j].x * bv[i].x + av[j].y * bv[i].y;
    }
    #pragma unroll
    for (int j = 0; j < 4; j++) {
        __half2* dst = (__half2*)(w16v + (size_t)(h * LD + e0 + j) * D
                                  + i0 + il0);
        dst[0] = __floats2half2_rn(acc[j][0], acc[j][1]);
        dst[1] = __floats2half2_rn(acc[j][2], acc[j][3]);
    }
}

// Weffo[n][h*32+e] = sum_d Wd[e][d]*Wo[h*128+d][n]. grid (D/128, H), 256 thr.
// a fp32 [d][e], b fp16 [d][nl]; fully vectorized loads.
__global__ void __launch_bounds__(256) prep_wo_kernel(
    const float* __restrict__ Wd, const float* __restrict__ Wo,
    __half* __restrict__ w16o)
{
    extern __shared__ __half hsm[];
    float  (*a_s)[36]  = (float(*)[36])hsm;                    // [d][e]
    __half (*b_s)[132] = (__half(*)[132])(hsm + 128 * 36 * 2); // [d][nl]
    const int h = blockIdx.y, n0 = blockIdx.x * 128;
    const int tid = threadIdx.x;
    for (int idx = tid; idx < LD * HD; idx += 256) {
        const int e = idx >> 7, d = idx & 127;
        a_s[d][e] = Wd[idx];
    }
    for (int idx = tid; idx < 128 * 32; idx += 256) {
        const int d = idx >> 5, nlq = (idx & 31) * 4;
        float4 v = *(const float4*)(Wo + (size_t)(h * HD + d) * D + n0 + nlq);
        *(__half2*)&b_s[d][nlq]     = __floats2half2_rn(v.x, v.y);
        *(__half2*)&b_s[d][nlq + 2] = __floats2half2_rn(v.z, v.w);
    }
    __syncthreads();
    const int e0  = (tid & 7) * 4;
    const int nl0 = (tid >> 3) * 4;
    float acc[4][4] = {};
    #pragma unroll 4
    for (int d = 0; d < HD; d++) {
        const float4 a4 = *(const float4*)&a_s[d][e0];
        const float2 b01 = __half22float2(*(const __half2*)&b_s[d][nl0]);
        const float2 b23 = __half22float2(*(const __half2*)&b_s[d][nl0 + 2]);
        acc[0][0] += a4.x * b01.x; acc[0][1] += a4.x * b01.y;
        acc[0][2] += a4.x * b23.x; acc[0][3] += a4.x * b23.y;
        acc[1][0] += a4.y * b01.x; acc[1][1] += a4.y * b01.y;
        acc[1][2] += a4.y * b23.x; acc[1][3] += a4.y * b23.y;
        acc[2][0] += a4.z * b01.x; acc[2][1] += a4.z * b01.y;
        acc[2][2] += a4.z * b23.x; acc[2][3] += a4.z * b23.y;
        acc[3][0] += a4.w * b01.x; acc[3][1] += a4.w * b01.y;
        acc[3][2] += a4.w * b23.x; acc[3][3] += a4.w * b23.y;
    }
    #pragma unroll
    for (int i = 0; i < 4; i++) {
        __half2* dst = (__half2*)(w16o + (size_t)(n0 + nl0 + i) * CD
                                  + h * LD + e0);
        dst[0] = __floats2half2_rn(acc[0][i], acc[1][i]);
        dst[1] = __floats2half2_rn(acc[2][i], acc[3][i]);
    }
}

// bias_o[n] = sum_r bd[r%128]*Wo[r,n] + bo[n].  grid 64, block 256
__global__ void __launch_bounds__(256) prep_bias_o_kernel(
    const float* __restrict__ bd, const float* __restrict__ Wo,
    const float* __restrict__ bo, float* __restrict__ bias_o)
{
    __shared__ float part[8][32];
    const int tid = threadIdx.x;
    const int nl = tid & 31, rc = tid >> 5;
    const int n = blockIdx.x * 32 + nl;
    float acc = 0.f;
    for (int r = rc * 256; r < rc * 256 + 256; r++)
        acc += bd[r & 127] * Wo[(size_t)r * D + n];
    part[rc][nl] = acc;
    __syncthreads();
    if (tid < 32) {
        float s = bo[blockIdx.x * 32 + tid];
        #pragma unroll
        for (int j = 0; j < 8; j++) s += part[j][tid];
        bias_o[blockIdx.x * 32 + tid] = s;
    }
}

// bveff[h*32+e] = sum_d bv[h*128+d]*Wvc[d,e] + bvc[e]
__global__ void __launch_bounds__(256) prep_bias_v_kernel(
    const float* __restrict__ bv, const float* __restrict__ Wvc,
    const float* __restrict__ bvc, float* __restrict__ bveff)
{
    for (int o = threadIdx.x; o < CD; o += 256) {
        const int h = o >> 5, e = o & 31;
        float acc = bvc[e];
        for (int d = 0; d < HD; d++)
            acc += bv[h * HD + d] * Wvc[d * LD + e];
        bveff[o] = acc;
    }
}

// ================= unified QKV GEMM (K=2048, N=4608) ========================
__device__ __forceinline__ void load_stage_qkv(
    uint32_t sbase, const __half* pA, const __half* pB, int kc, int tid)
{
    const int r0 = tid >> 2, seg = tid & 3;
    const uint32_t so = sbase + r0 * ROWB + seg * 16;
    const size_t go = (size_t)r0 * D + kc + seg * 8;
    #pragma unroll
    for (int j = 0; j < 4; j++)
        cp_async16(so + j * 64 * ROWB, pA + go + (size_t)j * 64 * D);
    #pragma unroll
    for (int j = 0; j < 2; j++)
        cp_async16(so + (256 + j * 64) * ROWB, pB + go + (size_t)j * 64 * D);
}

__global__ void __launch_bounds__(256) gemm_qkv_kernel(
    const __half* __restrict__ A16, const __half* __restrict__ wB,
    const float* __restrict__ bq, const float* __restrict__ bk,
    const float* __restrict__ bveff,
    __half* __restrict__ q16, __half* __restrict__ k16,
    __half* __restrict__ vch)
{
    constexpr int NITL = D / BK;   // 64
    extern __shared__ char smem[];
    const uint32_t sb0 = smem_u32(smem);
    const int tid = threadIdx.x, wid = tid >> 5, lane = tid & 31;
    const int warp_m = (wid & 3) * 64;
    const int warp_n = (wid >> 2) * 64;
    const int m0 = blockIdx.y * 256;
    const int n0 = blockIdx.x * 128;

    const __half* pA = A16 + (size_t)m0 * D;
    const __half* pB = wB  + (size_t)n0 * D;

    float acc[4][8][4];
    #pragma unroll
    for (int i = 0; i < 4; i++)
        #pragma unroll
        for (int j = 0; j < 8; j++)
            #pragma unroll
            for (int t = 0; t < 4; t++) acc[i][j][t] = 0.f;

    const int arow = ((lane >> 3) & 1) * 8 + (lane & 7);
    const int acol = (lane >> 4) * 16;
    const int brow = (lane >> 4) * 8 + (lane & 7);
    const int bcol = ((lane >> 3) & 1) * 16;

    load_stage_qkv(sb0, pA, pB, 0, tid);
    cp_commit();
    load_stage_qkv(sb0 + STAGEB, pA, pB, BK, tid);
    cp_commit();

    #pragma unroll 1
    for (int kt = 0; kt < NITL; kt++) {
        cp_wait<1>();
        __syncthreads();
        if (kt + 2 < NITL)
            load_stage_qkv(sb0 + ((kt + 2) % STAGES) * STAGEB,
                           pA, pB, (kt + 2) * BK, tid);
        cp_commit();

        const uint32_t sb = sb0 + (kt % STAGES) * STAGEB;
        #pragma unroll
        for (int ks = 0; ks < 2; ks++) {
            uint32_t ah[4][4];
            #pragma unroll
            for (int mt = 0; mt < 4; mt++)
                ldsm4(ah[mt], sb + (warp_m + mt * 16 + arow) * ROWB
                              + ks * 32 + acol);
            uint32_t bh[4][4];
            #pragma unroll
            for (int np = 0; np < 4; np++)
                ldsm4(bh[np], sb + OFF_B + (warp_n + np * 16 + brow) * ROWB
                              + ks * 32 + bcol);
            #pragma unroll
            for (int mt = 0; mt < 4; mt++)
                #pragma unroll
                for (int nt = 0; nt < 8; nt++) {
                    const int np = nt >> 1, pp = (nt & 1) * 2;
                    mma16816(acc[mt][nt], ah[mt], bh[np][pp], bh[np][pp + 1]);
                }
        }
    }

    if (n0 < 2 * D) {
        __half* C = (n0 < D) ? q16 : k16;
        const float* bias = (n0 < D) ? bq : bk;
        const int nc0 = (n0 < D) ? n0 : n0 - D;
        #pragma unroll
        for (int mt = 0; mt < 4; mt++) {
            const int row = m0 + warp_m + mt * 16 + (lane >> 2);
            #pragma unroll
            for (int nt = 0; nt < 8; nt++) {
                const int col = nc0 + warp_n + nt * 8 + (lane & 3) * 2;
                const float b0 = bias[col], b1 = bias[col + 1];
                *(__half2*)(C + (size_t)row * D + col) =
                    __floats2half2_rn(acc[mt][nt][0] + b0, acc[mt][nt][1] + b1);
                *(__half2*)(C + (size_t)(row + 8) * D + col) =
                    __floats2half2_rn(acc[mt][nt][2] + b0, acc[mt][nt][3] + b1);
            }
        }
    } else {
        const int ncv = n0 - 2 * D;
        #pragma unroll
        for (int mt = 0; mt < 4; mt++) {
            const int row = m0 + warp_m + mt * 16 + (lane >> 2);
            const int b0i = row >> 11, l0i = row & (L - 1);
            const int b1i = (row + 8) >> 11, l1i = (row + 8) & (L - 1);
            #pragma unroll
            for (int nt = 0; nt < 8; nt++) {
                const int col = ncv + warp_n + nt * 8 + (lane & 3) * 2;
                const int h = col >> 5, e = col & 31;
                const float bb0 = bveff[col], bb1 = bveff[col + 1];
                *(__half2*)(vch + ((size_t)(b0i * H + h) * L + l0i) * LD + e) =
                    __floats2half2_rn(acc[mt][nt][0] + bb0,
                                      acc[mt][nt][1] + bb1);
                *(__half2*)(vch + ((size_t)(b1i * H + h) * L + l1i) * LD + e) =
                    __floats2half2_rn(acc[mt][nt][2] + bb0,
                                      acc[mt][nt][3] + bb1);
            }
        }
    }
}

// ================= output GEMM (K=512) ======================================
__device__ __forceinline__ void load_stage_out(
    uint32_t sbase, const __half* pA, const __half* pB, int kc, int tid)
{
    const int r0 = tid >> 2, seg = tid & 3;
    const uint32_t so = sbase + r0 * ROWB + seg * 16;
    const size_t go = (size_t)r0 * CD + kc + seg * 8;
    #pragma unroll
    for (int j = 0; j < 4; j++)
        cp_async16(so + j * 64 * ROWB, pA + go + (size_t)j * 64 * CD);
    #pragma unroll
    for (int j = 0; j < 2; j++)
        cp_async16(so + (256 + j * 64) * ROWB, pB + go + (size_t)j * 64 * CD);
}

__global__ void __launch_bounds__(256) gemm_out_kernel(
    const __half* __restrict__ A16, const __half* __restrict__ Bw,
    const float* __restrict__ bias, float* __restrict__ C)
{
    constexpr int NITL = CD / BK;  // 16
    extern __shared__ char smem[];
    const uint32_t sb0 = smem_u32(smem);
    const int tid = threadIdx.x, wid = tid >> 5, lane = tid & 31;
    const int warp_m = (wid & 3) * 64;
    const int warp_n = (wid >> 2) * 64;
    const int m0 = blockIdx.y * 256, n0 = blockIdx.x * 128;

    const __half* pA = A16 + (size_t)m0 * CD;
    const __half* pB = Bw  + (size_t)n0 * CD;

    float acc[4][8][4];
    #pragma unroll
    for (int i = 0; i < 4; i++)
        #pragma unroll
        for (int j = 0; j < 8; j++)
            #pragma unroll
            for (int t = 0; t < 4; t++) acc[i][j][t] = 0.f;

    const int arow = ((lane >> 3) & 1) * 8 + (lane & 7);
    const int acol = (lane >> 4) * 16;
    const int brow = (lane >> 4) * 8 + (lane & 7);
    const int bcol = ((lane >> 3) & 1) * 16;

    load_stage_out(sb0, pA, pB, 0, tid);
    cp_commit();
    load_stage_out(sb0 + STAGEB, pA, pB, BK, tid);
    cp_commit();

    #pragma unroll 1
    for (int kt = 0; kt < NITL; kt++) {
        cp_wait<1>();
        __syncthreads();
        if (kt + 2 < NITL)
            load_stage_out(sb0 + ((kt + 2) % STAGES) * STAGEB,
                           pA, pB, (kt + 2) * BK, tid);
        cp_commit();

        const uint32_t sb = sb0 + (kt % STAGES) * STAGEB;
        #pragma unroll
        for (int ks = 0; ks < 2; ks++) {
            uint32_t ah[4][4];
            #pragma unroll
            for (int mt = 0; mt < 4; mt++)
                ldsm4(ah[mt], sb + (warp_m + mt * 16 + arow) * ROWB
                              + ks * 32 + acol);
            uint32_t bh[4][4];
            #pragma unroll
            for (int np = 0; np < 4; np++)
                ldsm4(bh[np], sb + OFF_B + (warp_n + np * 16 + brow) * ROWB
                              + ks * 32 + bcol);
            #pragma unroll
            for (int mt = 0; mt < 4; mt++)
                #pragma unroll
                for (int nt = 0; nt < 8; nt++) {
                    const int np = nt >> 1, pp = (nt & 1) * 2;
                    mma16816(acc[mt][nt], ah[mt], bh[np][pp], bh[np][pp + 1]);
                }
        }
    }

    #pragma unroll
    for (int mt = 0; mt < 4; mt++) {
        const int row = m0 + warp_m + mt * 16 + (lane >> 2);
        #pragma unroll
        for (int nt = 0; nt < 8; nt++) {
            const int col = n0 + warp_n + nt * 8 + (lane & 3) * 2;
            const float b0 = bias[col], b1 = bias[col + 1];
            *(float2*)(C + (size_t)row * D + col) =
                make_float2(acc[mt][nt][0] + b0, acc[mt][nt][1] + b1);
            *(float2*)(C + (size_t)(row + 8) * D + col) =
                make_float2(acc[mt][nt][2] + b0, acc[mt][nt][3] + b1);
        }
    }
}

// ---------------- compress (+ fused RoPE), q & k in one launch, fp16 in -----
__global__ void __launch_bounds__(256) compress_kernel(
    const __half* __restrict__ Q, const __half* __restrict__ K,
    const float* __restrict__ Wqc, const float* __restrict__ Wkc,
    const float* __restrict__ bqc, const float* __restrict__ bkc,
    __half* __restrict__ qch, __half* __restrict__ kch,
    const float* __restrict__ cosT, const float* __restrict__ sinT)
{
    __shared__ float Ws[HD][LD];
    __shared__ float xs[32][HD];
    const int z = blockIdx.z;
    const __half* X = z ? K : Q;
    const float* Wc = z ? Wkc : Wqc;
    const float* bc = z ? bkc : bqc;
    __half* Xc = z ? kch : qch;
    const int bh = blockIdx.y;
    const int b = bh / H, h = bh % H;
    const int l0 = blockIdx.x * 32;
    const int tid = threadIdx.x;
    for (int i = tid; i < HD * LD; i += 256) Ws[i / LD][i % LD] = Wc[i];
    for (int i = tid; i < 32 * 64; i += 256) {
        const int li = i >> 6, p = i & 63;
        const int l = l0 + li;
        float2 xv = __half22float2(*(const __half2*)&X[
            ((size_t)((b * L + l) * H + h)) * HD + 2 * p]);
        const float c = cosT[l * 64 + p];
        const float s = sinT[l * 64 + p];
        xs[li][2 * p]     = xv.x * c - xv.y * s;
        xs[li][2 * p + 1] = xv.x * s + xv.y * c;
    }
    __syncthreads();
    const int row = tid >> 3;
    const int e0  = (tid & 7) * 4;
    float4 acc = *(const float4*)(bc + e0);
    #pragma unroll
    for (int d = 0; d < HD; d++) {
        const float xv = xs[row][d];
        const float4 w = *(const float4*)&Ws[d][e0];
        acc.x += xv * w.x; acc.y += xv * w.y;
        acc.z += xv * w.z; acc.w += xv * w.w;
    }
    __half2* dst = (__half2*)(Xc + ((size_t)bh * L + l0 + row) * LD + e0);
    dst[0] = __floats2half2_rn(acc.x, acc.y);
    dst[1] = __floats2half2_rn(acc.z, acc.w);
}

// ---------------- tensor-core causal flash attention ------------------------
// 128 queries/block (8 warps x 16 rows), 64-key tiles.
__global__ void __launch_bounds__(256) attn_kernel(
    const __half* __restrict__ qc, const __half* __restrict__ kc,
    const __half* __restrict__ vc, __half* __restrict__ ao)
{
    __shared__ __half qs[128][40];
    __shared__ __half ks[64][40];
    __shared__ __half vs[64][40];
    constexpr float SCALE = 0.17677669529663687f;

    const int bh  = blockIdx.y;
    const int q0  = (gridDim.x - 1 - blockIdx.x) * 128;
    const int tid = threadIdx.x;
    const int w = tid >> 5, lane = tid & 31;

    const __half* bq = qc + ((size_t)bh * L + q0) * LD;
    const __half* bk = kc + (size_t)bh * L * LD;
    const __half* bv = vc + (size_t)bh * L * LD;

    for (int i = tid; i < 512; i += 256) {
        const int r = i >> 2, c = i & 3;
        *(uint4*)((char*)&qs[r][0] + c * 16) =
            *(const uint4*)((const char*)(bq + (size_t)r * LD) + c * 16);
    }
    __syncthreads();

    const uint32_t qs_b = smem_u32(qs);
    const uint32_t ks_b = smem_u32(ks);
    const uint32_t vs_b = smem_u32(vs);

    const int arow = ((lane >> 3) & 1) * 8 + (lane & 7);
    const int acol = (lane >> 4) * 16;
    const int brow = (lane >> 4) * 8 + (lane & 7);
    const int bcol = ((lane >> 3) & 1) * 16;

    uint32_t aq[2][4];
    #pragma unroll
    for (int ks2 = 0; ks2 < 2; ks2++)
        ldsm4(aq[ks2], qs_b + (w * 16 + arow) * 80 + ks2 * 32 + acol);

    float o[4][4];
    #pragma unroll
    for (int i = 0; i < 4; i++)
        #pragma unroll
        for (int j = 0; j < 4; j++) o[i][j] = 0.f;
    float m_lo = -INFINITY, m_hi = -INFINITY, l_lo = 0.f, l_hi = 0.f;

    const int nt = q0 / 64 + 2;
    const int row_lo = q0 + w * 16 + (lane >> 2);
    const int row_hi = row_lo + 8;

    for (int t = 0; t < nt; t++) {
        __syncthreads();
        for (int i = tid; i < 512; i += 256) {
            const int mtx = i >> 8;
            const int r = (i >> 2) & 63, c = i & 3;
            const __half* src = (mtx ? bv : bk) + ((size_t)(t * 64 + r)) * LD;
            __half* dst = mtx ? &vs[r][0] : &ks[r][0];
            *(uint4*)((char*)dst + c * 16) =
                *(const uint4*)((const char*)src + c * 16);
        }
        __syncthreads();

        float s[8][4];
        #pragma unroll
        for (int i = 0; i < 8; i++)
            #pragma unroll
            for (int j = 0; j < 4; j++) s[i][j] = 0.f;
        #pragma unroll
        for (int ks2 = 0; ks2 < 2; ks2++) {
            #pragma unroll
            for (int ng = 0; ng < 4; ng++) {
                uint32_t bkf[4];
                ldsm4(bkf, ks_b + (ng * 16 + brow) * 80 + ks2 * 32 + bcol);
                mma16816(s[ng * 2],     aq[ks2], bkf[0], bkf[1]);
                mma16816(s[ng * 2 + 1], aq[ks2], bkf[2], bkf[3]);
            }
        }

        // mask needed for the last TWO tiles (rows span 128 > 64-key tile)
        const bool diag = (t >= nt - 2);
        #pragma unroll
        for (int nf = 0; nf < 8; nf++) {
            const int col = t * 64 + nf * 8 + (lane & 3) * 2;
            #pragma unroll
            for (int j = 0; j < 4; j++) s[nf][j] *= SCALE;
            if (diag) {
                if (col     > row_lo) s[nf][0] = -INFINITY;
                if (col + 1 > row_lo) s[nf][1] = -INFINITY;
                if (col     > row_hi) s[nf][2] = -INFINITY;
                if (col + 1 > row_hi) s[nf][3] = -INFINITY;
            }
        }

        float tm_lo = -INFINITY, tm_hi = -INFINITY;
        #pragma unroll
        for (int nf = 0; nf < 8; nf++) {
            tm_lo = fmaxf(tm_lo, fmaxf(s[nf][0], s[nf][1]));
            tm_hi = fmaxf(tm_hi, fmaxf(s[nf][2], s[nf][3]));
        }
        #pragma unroll
        for (int off = 1; off <= 2; off <<= 1) {
            tm_lo = fmaxf(tm_lo, __shfl_xor_sync(0xffffffffu, tm_lo, off));
            tm_hi = fmaxf(tm_hi, __shfl_xor_sync(0xffffffffu, tm_hi, off));
        }
        const float mn_lo = fmaxf(m_lo, tm_lo);
        const float mn_hi = fmaxf(m_hi, tm_hi);
        const float al_lo = __expf(m_lo - mn_lo);
        const float al_hi = __expf(m_hi - mn_hi);
        m_lo = mn_lo; m_hi = mn_hi;

        float ps_lo = 0.f, ps_hi = 0.f;
        #pragma unroll
        for (int nf = 0; nf < 8; nf++) {
            s[nf][0] = __expf(s[nf][0] - mn_lo);
            s[nf][1] = __expf(s[nf][1] - mn_lo);
            s[nf][2] = __expf(s[nf][2] - mn_hi);
            s[nf][3] = __expf(s[nf][3] - mn_hi);
            ps_lo += s[nf][0] + s[nf][1];
            ps_hi += s[nf][2] + s[nf][3];
        }
        #pragma unroll
        for (int off = 1; off <= 2; off <<= 1) {
            ps_lo += __shfl_xor_sync(0xffffffffu, ps_lo, off);
            ps_hi += __shfl_xor_sync(0xffffffffu, ps_hi, off);
        }
        l_lo = l_lo * al_lo + ps_lo;
        l_hi = l_hi * al_hi + ps_hi;

        #pragma unroll
        for (int nf = 0; nf < 4; nf++) {
            o[nf][0] *= al_lo; o[nf][1] *= al_lo;
            o[nf][2] *= al_hi; o[nf][3] *= al_hi;
        }

        #pragma unroll
        for (int kc4 = 0; kc4 < 4; kc4++) {
            uint32_t ap[4];
            const int f0 = 2 * kc4, f1 = 2 * kc4 + 1;
            ap[0] = h2_u32(__floats2half2_rn(s[f0][0], s[f0][1]));
            ap[1] = h2_u32(__floats2half2_rn(s[f0][2], s[f0][3]));
            ap[2] = h2_u32(__floats2half2_rn(s[f1][0], s[f1][1]));
            ap[3] = h2_u32(__floats2half2_rn(s[f1][2], s[f1][3]));
            #pragma unroll
            for (int half = 0; half < 2; half++) {
                uint32_t bvf[4];
                ldsm4t(bvf, vs_b + (kc4 * 16 + arow) * 80 + half * 32 + acol);
                mma16816(o[half * 2],     ap, bvf[0], bvf[1]);
                mma16816(o[half * 2 + 1], ap, bvf[2], bvf[3]);
            }
        }
    }

    const int b = bh / H, h = bh % H;
    const float inv_lo = 1.f / l_lo, inv_hi = 1.f / l_hi;
    #pragma unroll
    for (int nf = 0; nf < 4; nf++) {
        const int e = nf * 8 + (lane & 3) * 2;
        __half* p_lo = ao + (size_t)(b * L + row_lo) * CD + h * LD + e;
        __half* p_hi = ao + (size_t)(b * L + row_hi) * CD + h * LD + e;
        *(__half2*)p_lo = __floats2half2_rn(o[nf][0] * inv_lo, o[nf][1] * inv_lo);
        *(__half2*)p_hi = __floats2half2_rn(o[nf][2] * inv_hi, o[nf][3] * inv_hi);
    }
}

// ---------------------------------------------------------------------------
extern "C" void kernel_launch(void* const* d_in, const int* in_sizes, int n_in,
                              void* d_out, int out_size)
{
    const float* x    = (const float*)d_in[0];
    const float* cosT = (const float*)d_in[1];
    const float* sinT = (const float*)d_in[2];
    const float* Wq   = (const float*)d_in[3];
    const float* bq   = (const float*)d_in[4];
    const float* Wk   = (const float*)d_in[5];
    const float* bk   = (const float*)d_in[6];
    const float* Wv   = (const float*)d_in[7];
    const float* bv   = (const float*)d_in[8];
    const float* Wqc  = (const float*)d_in[9];
    const float* bqc  = (const float*)d_in[10];
    const float* Wkc  = (const float*)d_in[11];
    const float* bkc  = (const float*)d_in[12];
    const float* Wvc  = (const float*)d_in[13];
    const float* bvc  = (const float*)d_in[14];
    const float* Wd   = (const float*)d_in[15];
    const float* bd   = (const float*)d_in[16];
    const float* Wo   = (const float*)d_in[17];
    const float* bo   = (const float*)d_in[18];
    float* out = (float*)d_out;

    float *bias_o, *bveff;
    __half *q16, *k16, *qch, *kch, *vch, *ao, *a16, *wB, *wo;
    cudaGetSymbolAddress((void**)&q16,    g_q16);
    cudaGetSymbolAddress((void**)&k16,    g_k16);
    cudaGetSymbolAddress((void**)&qch,    g_qch);
    cudaGetSymbolAddress((void**)&kch,    g_kch);
    cudaGetSymbolAddress((void**)&vch,    g_vch);
    cudaGetSymbolAddress((void**)&ao,     g_ao);
    cudaGetSymbolAddress((void**)&a16,    g_a16);
    cudaGetSymbolAddress((void**)&wB,     g_wB);
    cudaGetSymbolAddress((void**)&wo,     g_wo);
    cudaGetSymbolAddress((void**)&bias_o, g_bo);
    cudaGetSymbolAddress((void**)&bveff,  g_bv);

    cudaFuncSetAttribute(gemm_qkv_kernel,
                         cudaFuncAttributeMaxDynamicSharedMemorySize, SMEMB);
    cudaFuncSetAttribute(gemm_out_kernel,
                         cudaFuncAttributeMaxDynamicSharedMemorySize, SMEMB);
    cudaFuncSetAttribute(prep_wv_kernel,
                         cudaFuncAttributeMaxDynamicSharedMemorySize, SMEM_WV);
    cudaFuncSetAttribute(prep_wo_kernel,
                         cudaFuncAttributeMaxDynamicSharedMemorySize, SMEM_WO);

    // --- conversions + weight folding ---
    convert_a_kernel<<<(GM * D / 4) / 256, 256>>>(x, a16);
    convert_wqk_kernel<<<dim3(D / 32, D / 64, 2), dim3(32, 8)>>>(Wq, Wk, wB);
    prep_wv_kernel<<<dim3(D / 128, H), 256, SMEM_WV>>>(
        Wv, Wvc, wB + (size_t)2 * D * D);
    prep_wo_kernel<<<dim3(D / 128, H), 256, SMEM_WO>>>(Wd, Wo, wo);
    prep_bias_o_kernel<<<D / 32, 256>>>(bd, Wo, bo, bias_o);
    prep_bias_v_kernel<<<1, 256>>>(bv, Wvc, bvc, bveff);

    // --- unified Q,K,Vc GEMM (fp16 q/k out) ---
    gemm_qkv_kernel<<<dim3(NB / 128, GM / 256), 256, SMEMB>>>(
        a16, wB, bq, bk, bveff, q16, k16, vch);

    // --- compress + rope for q,k (single launch) ---
    compress_kernel<<<dim3(L / 32, B * H, 2), 256>>>(
        q16, k16, Wqc, Wkc, bqc, bkc, qch, kch, cosT, sinT);

    // --- attention (128 queries/block) ---
    attn_kernel<<<dim3(L / 128, B * H), 256>>>(qch, kch, vch, ao);

    // --- decompress+output projection folded ---
    gemm_out_kernel<<<dim3(D / 128, GM / 256), 256, SMEMB>>>(
        ao, wo, bias_o, out);
}

// round 16
// speedup vs baseline: 9.5682x; 1.1013x over previous
#include <cuda_runtime.h>
#include <cuda_fp16.h>
#include <math.h>
#include <cstdint>

namespace {
constexpr int B  = 2;
constexpr int L  = 2048;
constexpr int D  = 2048;
constexpr int H  = 16;
constexpr int HD = 128;
constexpr int LD = 32;
constexpr int BL = B * L;                 // 4096
constexpr int BHLLD = B * H * L * LD;     // 2097152
constexpr int CD = H * LD;                // 512
constexpr int GM = BL;                    // 4096
constexpr int NB = 2 * D + CD;            // 4608 B rows (Wq|Wk|Wveff)

constexpr int BK     = 32;
constexpr int STAGES = 3;
constexpr int ROWB   = 80;
constexpr int OFF_B  = 256 * ROWB;
constexpr int STAGEB = 384 * ROWB;        // 30720
constexpr int SMEMB  = STAGES * STAGEB;   // 92160

// merged prep launch: dynamic smem = max over branches
constexpr int SMEM_PREP = 128 * 36 * 4 + 128 * 132 * 2;    // 52224 (wo branch)

// dispatch table (block ranges within the merged prep grid)
constexpr int NWV  = 256;                  // prep_wv   (16 x 16)
constexpr int NWO  = 256;                  // prep_wo   (16 x 16)
constexpr int NBO  = 64;                   // bias_o
constexpr int NBV  = 1;                    // bias_v
constexpr int NCW  = 4096;                 // convert_wqk (64 x 32 x 2)
constexpr int NCA  = GM * D / 4 / 256;     // 8192 convert_a
constexpr int NPREP = NWV + NWO + NBO + NBV + NCW + NCA;
}

// ---------------- scratch ----------------------------------------------------
__device__ __half g_q16[GM * D];     // q fp16 (b,l,h,hd)
__device__ __half g_k16[GM * D];
__device__ __half g_qch[BHLLD];      // (b,h,l,e)
__device__ __half g_kch[BHLLD];
__device__ __half g_vch[BHLLD];
__device__ __half g_ao[BL * CD];     // attn out fp16 (b*l, h*32+e)
__device__ __half g_a16[GM * D];     // x fp16 [M,K]
__device__ __half g_wB[(size_t)NB * D];  // Wq|Wk|Wveff fp16 [N,K]
__device__ __half g_wo[D * CD];      // Weffo fp16 [N=2048, K=512]
__device__ float  g_bo[D];
__device__ float  g_bv[CD];

// ================= PTX helpers ==============================================
__device__ __forceinline__ uint32_t smem_u32(const void* p) {
    uint32_t a;
    asm("{ .reg .u64 t; cvta.to.shared.u64 t, %1; cvt.u32.u64 %0, t; }"
        : "=r"(a) : "l"(p));
    return a;
}
__device__ __forceinline__ uint32_t h2_u32(__half2 h) {
    return *reinterpret_cast<uint32_t*>(&h);
}
__device__ __forceinline__ void cp_async16(uint32_t dst, const void* src) {
    asm volatile("cp.async.cg.shared.global [%0], [%1], 16;"
                 :: "r"(dst), "l"(src) : "memory");
}
__device__ __forceinline__ void cp_commit() {
    asm volatile("cp.async.commit_group;" ::: "memory");
}
template <int N>
__device__ __forceinline__ void cp_wait() {
    asm volatile("cp.async.wait_group %0;" :: "n"(N) : "memory");
}
__device__ __forceinline__ void ldsm4(uint32_t* r, uint32_t addr) {
    asm volatile("ldmatrix.sync.aligned.m8n8.x4.shared.b16 {%0,%1,%2,%3}, [%4];"
                 : "=r"(r[0]), "=r"(r[1]), "=r"(r[2]), "=r"(r[3]) : "r"(addr));
}
__device__ __forceinline__ void ldsm4t(uint32_t* r, uint32_t addr) {
    asm volatile("ldmatrix.sync.aligned.m8n8.x4.trans.shared.b16 {%0,%1,%2,%3}, [%4];"
                 : "=r"(r[0]), "=r"(r[1]), "=r"(r[2]), "=r"(r[3]) : "r"(addr));
}
__device__ __forceinline__ void mma16816(float* d, const uint32_t* a,
                                         uint32_t b0, uint32_t b1) {
    asm volatile(
        "mma.sync.aligned.m16n8k16.row.col.f32.f16.f16.f32 "
        "{%0,%1,%2,%3}, {%4,%5,%6,%7}, {%8,%9}, {%0,%1,%2,%3};"
        : "+f"(d[0]), "+f"(d[1]), "+f"(d[2]), "+f"(d[3])
        : "r"(a[0]), "r"(a[1]), "r"(a[2]), "r"(a[3]), "r"(b0), "r"(b1));
}

// ================= merged prep kernel =======================================
// One launch; blockIdx.x dispatches: [wv | wo | bias_o | bias_v | conv_wqk | conv_a]
__global__ void __launch_bounds__(256) prep_merged_kernel(
    const float* __restrict__ x,   __half* __restrict__ a16,
    const float* __restrict__ Wq,  const float* __restrict__ Wk,
    __half* __restrict__ wB,
    const float* __restrict__ Wv,  const float* __restrict__ Wvc,
    const float* __restrict__ Wd,  const float* __restrict__ Wo,
    __half* __restrict__ w16o,
    const float* __restrict__ bd,  const float* __restrict__ bo,
    float* __restrict__ bias_o,
    const float* __restrict__ bv,  const float* __restrict__ bvc,
    float* __restrict__ bveff)
{
    extern __shared__ char dsm[];
    const int tid = threadIdx.x;
    int bx = blockIdx.x;

    // ---- branch 1: prep_wv (256 blocks; launched first to hide latency) ----
    if (bx < NWV) {
        __half* w16v = wB + (size_t)2 * D * D;
        __half (*a_s)[130] = (__half(*)[130])dsm;                       // [e][d]
        __half (*b_s)[130] = (__half(*)[130])(dsm + 32 * 130 * 2);      // [il][d]
        const int h = bx >> 4, i0 = (bx & 15) * 128;
        for (int idx = tid; idx < HD * LD; idx += 256) {
            const int d = idx >> 5, e = idx & 31;
            a_s[e][d] = __float2half_rn(Wvc[idx]);
        }
        for (int idx = tid; idx < 128 * 32; idx += 256) {
            const int il = idx >> 5, dq = (idx & 31) * 4;
            float4 v = *(const float4*)(Wv + (size_t)(i0 + il) * D
                                        + h * HD + dq);
            *(__half2*)&b_s[il][dq]     = __floats2half2_rn(v.x, v.y);
            *(__half2*)&b_s[il][dq + 2] = __floats2half2_rn(v.z, v.w);
        }
        __syncthreads();
        const int e0  = (tid & 7) * 4;
        const int il0 = (tid >> 3) * 4;
        float acc[4][4] = {};
        #pragma unroll 8
        for (int d = 0; d < HD; d += 2) {
            float2 av[4], bvv[4];
            #pragma unroll
            for (int j = 0; j < 4; j++)
                av[j] = __half22float2(*(const __half2*)&a_s[e0 + j][d]);
            #pragma unroll
            for (int i = 0; i < 4; i++)
                bvv[i] = __half22float2(*(const __half2*)&b_s[il0 + i][d]);
            #pragma unroll
            for (int j = 0; j < 4; j++)
                #pragma unroll
                for (int i = 0; i < 4; i++)
                    acc[j][i] += av[j].x * bvv[i].x + av[j].y * bvv[i].y;
        }
        #pragma unroll
        for (int j = 0; j < 4; j++) {
            __half2* dst = (__half2*)(w16v + (size_t)(h * LD + e0 + j) * D
                                      + i0 + il0);
            dst[0] = __floats2half2_rn(acc[j][0], acc[j][1]);
            dst[1] = __floats2half2_rn(acc[j][2], acc[j][3]);
        }
        return;
    }
    bx -= NWV;

    // ---- branch 2: prep_wo (256 blocks) ------------------------------------
    if (bx < NWO) {
        float  (*a_s)[36]  = (float(*)[36])dsm;                         // [d][e]
        __half (*b_s)[132] = (__half(*)[132])(dsm + 128 * 36 * 4);      // [d][nl]
        const int h = bx >> 4, n0 = (bx & 15) * 128;
        for (int idx = tid; idx < LD * HD; idx += 256) {
            const int e = idx >> 7, d = idx & 127;
            a_s[d][e] = Wd[idx];
        }
        for (int idx = tid; idx < 128 * 32; idx += 256) {
            const int d = idx >> 5, nlq = (idx & 31) * 4;
            float4 v = *(const float4*)(Wo + (size_t)(h * HD + d) * D
                                        + n0 + nlq);
            *(__half2*)&b_s[d][nlq]     = __floats2half2_rn(v.x, v.y);
            *(__half2*)&b_s[d][nlq + 2] = __floats2half2_rn(v.z, v.w);
        }
        __syncthreads();
        const int e0  = (tid & 7) * 4;
        const int nl0 = (tid >> 3) * 4;
        float acc[4][4] = {};
        #pragma unroll 4
        for (int d = 0; d < HD; d++) {
            const float4 a4 = *(const float4*)&a_s[d][e0];
            const float2 b01 = __half22float2(*(const __half2*)&b_s[d][nl0]);
            const float2 b23 = __half22float2(*(const __half2*)&b_s[d][nl0 + 2]);
            acc[0][0] += a4.x * b01.x; acc[0][1] += a4.x * b01.y;
            acc[0][2] += a4.x * b23.x; acc[0][3] += a4.x * b23.y;
            acc[1][0] += a4.y * b01.x; acc[1][1] += a4.y * b01.y;
            acc[1][2] += a4.y * b23.x; acc[1][3] += a4.y * b23.y;
            acc[2][0] += a4.z * b01.x; acc[2][1] += a4.z * b01.y;
            acc[2][2] += a4.z * b23.x; acc[2][3] += a4.z * b23.y;
            acc[3][0] += a4.w * b01.x; acc[3][1] += a4.w * b01.y;
            acc[3][2] += a4.w * b23.x; acc[3][3] += a4.w * b23.y;
        }
        #pragma unroll
        for (int i = 0; i < 4; i++) {
            __half2* dst = (__half2*)(w16o + (size_t)(n0 + nl0 + i) * CD
                                      + h * LD + e0);
            dst[0] = __floats2half2_rn(acc[0][i], acc[1][i]);
            dst[1] = __floats2half2_rn(acc[2][i], acc[3][i]);
        }
        return;
    }
    bx -= NWO;

    // ---- branch 3: bias_o (64 blocks) ---------------------------------------
    if (bx < NBO) {
        float (*part)[32] = (float(*)[32])dsm;
        const int nl = tid & 31, rc = tid >> 5;
        const int n = bx * 32 + nl;
        float acc = 0.f;
        for (int r = rc * 256; r < rc * 256 + 256; r++)
            acc += bd[r & 127] * Wo[(size_t)r * D + n];
        part[rc][nl] = acc;
        __syncthreads();
        if (tid < 32) {
            float s = bo[bx * 32 + tid];
            #pragma unroll
            for (int j = 0; j < 8; j++) s += part[j][tid];
            bias_o[bx * 32 + tid] = s;
        }
        return;
    }
    bx -= NBO;

    // ---- branch 4: bias_v (1 block) -----------------------------------------
    if (bx < NBV) {
        for (int o = tid; o < CD; o += 256) {
            const int h = o >> 5, e = o & 31;
            float acc = bvc[e];
            for (int d = 0; d < HD; d++)
                acc += bv[h * HD + d] * Wvc[d * LD + e];
            bveff[o] = acc;
        }
        return;
    }
    bx -= NBV;

    // ---- branch 5: convert_wqk (4096 blocks) --------------------------------
    if (bx < NCW) {
        float (*t)[33] = (float(*)[33])dsm;     // [64][33]
        const int z = bx >> 11;                 // 0:Wq 1:Wk
        const int rem = bx & 2047;
        const int n0 = (rem & 63) * 32, k0 = (rem >> 6) * 64;
        const float* W = z ? Wk : Wq;
        __half* dst = wB + (size_t)z * D * D;
        const int tx = tid & 31, ty = tid >> 5;
        #pragma unroll
        for (int i = 0; i < 8; i++)
            t[ty + i * 8][tx] = W[(size_t)(k0 + ty + i * 8) * D + n0 + tx];
        __syncthreads();
        #pragma unroll
        for (int i = 0; i < 4; i++) {
            const int nr = ty + i * 8;
            *(__half2*)(dst + (size_t)(n0 + nr) * D + k0 + 2 * tx) =
                __floats2half2_rn(t[2 * tx][nr], t[2 * tx + 1][nr]);
        }
        return;
    }
    bx -= NCW;

    // ---- branch 6: convert_a (8192 blocks) ----------------------------------
    {
        long long i = ((long long)bx * 256 + tid) * 4;
        float4 v = *(const float4*)(x + i);
        *(__half2*)(a16 + i)     = __floats2half2_rn(v.x, v.y);
        *(__half2*)(a16 + i + 2) = __floats2half2_rn(v.z, v.w);
    }
}

// ================= unified QKV GEMM (K=2048, N=4608) ========================
__device__ __forceinline__ void load_stage_qkv(
    uint32_t sbase, const __half* pA, const __half* pB, int kc, int tid)
{
    const int r0 = tid >> 2, seg = tid & 3;
    const uint32_t so = sbase + r0 * ROWB + seg * 16;
    const size_t go = (size_t)r0 * D + kc + seg * 8;
    #pragma unroll
    for (int j = 0; j < 4; j++)
        cp_async16(so + j * 64 * ROWB, pA + go + (size_t)j * 64 * D);
    #pragma unroll
    for (int j = 0; j < 2; j++)
        cp_async16(so + (256 + j * 64) * ROWB, pB + go + (size_t)j * 64 * D);
}

__global__ void __launch_bounds__(256) gemm_qkv_kernel(
    const __half* __restrict__ A16, const __half* __restrict__ wB,
    const float* __restrict__ bq, const float* __restrict__ bk,
    const float* __restrict__ bveff,
    __half* __restrict__ q16, __half* __restrict__ k16,
    __half* __restrict__ vch)
{
    constexpr int NITL = D / BK;   // 64
    extern __shared__ char smem[];
    const uint32_t sb0 = smem_u32(smem);
    const int tid = threadIdx.x, wid = tid >> 5, lane = tid & 31;
    const int warp_m = (wid & 3) * 64;
    const int warp_n = (wid >> 2) * 64;
    const int m0 = blockIdx.y * 256;
    const int n0 = blockIdx.x * 128;

    const __half* pA = A16 + (size_t)m0 * D;
    const __half* pB = wB  + (size_t)n0 * D;

    float acc[4][8][4];
    #pragma unroll
    for (int i = 0; i < 4; i++)
        #pragma unroll
        for (int j = 0; j < 8; j++)
            #pragma unroll
            for (int t = 0; t < 4; t++) acc[i][j][t] = 0.f;

    const int arow = ((lane >> 3) & 1) * 8 + (lane & 7);
    const int acol = (lane >> 4) * 16;
    const int brow = (lane >> 4) * 8 + (lane & 7);
    const int bcol = ((lane >> 3) & 1) * 16;

    load_stage_qkv(sb0, pA, pB, 0, tid);
    cp_commit();
    load_stage_qkv(sb0 + STAGEB, pA, pB, BK, tid);
    cp_commit();

    #pragma unroll 1
    for (int kt = 0; kt < NITL; kt++) {
        cp_wait<1>();
        __syncthreads();
        if (kt + 2 < NITL)
            load_stage_qkv(sb0 + ((kt + 2) % STAGES) * STAGEB,
                           pA, pB, (kt + 2) * BK, tid);
        cp_commit();

        const uint32_t sb = sb0 + (kt % STAGES) * STAGEB;
        #pragma unroll
        for (int ks = 0; ks < 2; ks++) {
            uint32_t ah[4][4];
            #pragma unroll
            for (int mt = 0; mt < 4; mt++)
                ldsm4(ah[mt], sb + (warp_m + mt * 16 + arow) * ROWB
                              + ks * 32 + acol);
            uint32_t bh[4][4];
            #pragma unroll
            for (int np = 0; np < 4; np++)
                ldsm4(bh[np], sb + OFF_B + (warp_n + np * 16 + brow) * ROWB
                              + ks * 32 + bcol);
            #pragma unroll
            for (int mt = 0; mt < 4; mt++)
                #pragma unroll
                for (int nt = 0; nt < 8; nt++) {
                    const int np = nt >> 1, pp = (nt & 1) * 2;
                    mma16816(acc[mt][nt], ah[mt], bh[np][pp], bh[np][pp + 1]);
                }
        }
    }

    if (n0 < 2 * D) {
        __half* C = (n0 < D) ? q16 : k16;
        const float* bias = (n0 < D) ? bq : bk;
        const int nc0 = (n0 < D) ? n0 : n0 - D;
        #pragma unroll
        for (int mt = 0; mt < 4; mt++) {
            const int row = m0 + warp_m + mt * 16 + (lane >> 2);
            #pragma unroll
            for (int nt = 0; nt < 8; nt++) {
                const int col = nc0 + warp_n + nt * 8 + (lane & 3) * 2;
                const float b0 = bias[col], b1 = bias[col + 1];
                *(__half2*)(C + (size_t)row * D + col) =
                    __floats2half2_rn(acc[mt][nt][0] + b0, acc[mt][nt][1] + b1);
                *(__half2*)(C + (size_t)(row + 8) * D + col) =
                    __floats2half2_rn(acc[mt][nt][2] + b0, acc[mt][nt][3] + b1);
            }
        }
    } else {
        const int ncv = n0 - 2 * D;
        #pragma unroll
        for (int mt = 0; mt < 4; mt++) {
            const int row = m0 + warp_m + mt * 16 + (lane >> 2);
            const int b0i = row >> 11, l0i = row & (L - 1);
            const int b1i = (row + 8) >> 11, l1i = (row + 8) & (L - 1);
            #pragma unroll
            for (int nt = 0; nt < 8; nt++) {
                const int col = ncv + warp_n + nt * 8 + (lane & 3) * 2;
                const int h = col >> 5, e = col & 31;
                const float bb0 = bveff[col], bb1 = bveff[col + 1];
                *(__half2*)(vch + ((size_t)(b0i * H + h) * L + l0i) * LD + e) =
                    __floats2half2_rn(acc[mt][nt][0] + bb0,
                                      acc[mt][nt][1] + bb1);
                *(__half2*)(vch + ((size_t)(b1i * H + h) * L + l1i) * LD + e) =
                    __floats2half2_rn(acc[mt][nt][2] + bb0,
                                      acc[mt][nt][3] + bb1);
            }
        }
    }
}

// ================= output GEMM (K=512) ======================================
__device__ __forceinline__ void load_stage_out(
    uint32_t sbase, const __half* pA, const __half* pB, int kc, int tid)
{
    const int r0 = tid >> 2, seg = tid & 3;
    const uint32_t so = sbase + r0 * ROWB + seg * 16;
    const size_t go = (size_t)r0 * CD + kc + seg * 8;
    #pragma unroll
    for (int j = 0; j < 4; j++)
        cp_async16(so + j * 64 * ROWB, pA + go + (size_t)j * 64 * CD);
    #pragma unroll
    for (int j = 0; j < 2; j++)
        cp_async16(so + (256 + j * 64) * ROWB, pB + go + (size_t)j * 64 * CD);
}

__global__ void __launch_bounds__(256) gemm_out_kernel(
    const __half* __restrict__ A16, const __half* __restrict__ Bw,
    const float* __restrict__ bias, float* __restrict__ C)
{
    constexpr int NITL = CD / BK;  // 16
    extern __shared__ char smem[];
    const uint32_t sb0 = smem_u32(smem);
    const int tid = threadIdx.x, wid = tid >> 5, lane = tid & 31;
    const int warp_m = (wid & 3) * 64;
    const int warp_n = (wid >> 2) * 64;
    const int m0 = blockIdx.y * 256, n0 = blockIdx.x * 128;

    const __half* pA = A16 + (size_t)m0 * CD;
    const __half* pB = Bw  + (size_t)n0 * CD;

    float acc[4][8][4];
    #pragma unroll
    for (int i = 0; i < 4; i++)
        #pragma unroll
        for (int j = 0; j < 8; j++)
            #pragma unroll
            for (int t = 0; t < 4; t++) acc[i][j][t] = 0.f;

    const int arow = ((lane >> 3) & 1) * 8 + (lane & 7);
    const int acol = (lane >> 4) * 16;
    const int brow = (lane >> 4) * 8 + (lane & 7);
    const int bcol = ((lane >> 3) & 1) * 16;

    load_stage_out(sb0, pA, pB, 0, tid);
    cp_commit();
    load_stage_out(sb0 + STAGEB, pA, pB, BK, tid);
    cp_commit();

    #pragma unroll 1
    for (int kt = 0; kt < NITL; kt++) {
        cp_wait<1>();
        __syncthreads();
        if (kt + 2 < NITL)
            load_stage_out(sb0 + ((kt + 2) % STAGES) * STAGEB,
                           pA, pB, (kt + 2) * BK, tid);
        cp_commit();

        const uint32_t sb = sb0 + (kt % STAGES) * STAGEB;
        #pragma unroll
        for (int ks = 0; ks < 2; ks++) {
            uint32_t ah[4][4];
            #pragma unroll
            for (int mt = 0; mt < 4; mt++)
                ldsm4(ah[mt], sb + (warp_m + mt * 16 + arow) * ROWB
                              + ks * 32 + acol);
            uint32_t bh[4][4];
            #pragma unroll
            for (int np = 0; np < 4; np++)
                ldsm4(bh[np], sb + OFF_B + (warp_n + np * 16 + brow) * ROWB
                              + ks * 32 + bcol);
            #pragma unroll
            for (int mt = 0; mt < 4; mt++)
                #pragma unroll
                for (int nt = 0; nt < 8; nt++) {
                    const int np = nt >> 1, pp = (nt & 1) * 2;
                    mma16816(acc[mt][nt], ah[mt], bh[np][pp], bh[np][pp + 1]);
                }
        }
    }

    #pragma unroll
    for (int mt = 0; mt < 4; mt++) {
        const int row = m0 + warp_m + mt * 16 + (lane >> 2);
        #pragma unroll
        for (int nt = 0; nt < 8; nt++) {
            const int col = n0 + warp_n + nt * 8 + (lane & 3) * 2;
            const float b0 = bias[col], b1 = bias[col + 1];
            *(float2*)(C + (size_t)row * D + col) =
                make_float2(acc[mt][nt][0] + b0, acc[mt][nt][1] + b1);
            *(float2*)(C + (size_t)(row + 8) * D + col) =
                make_float2(acc[mt][nt][2] + b0, acc[mt][nt][3] + b1);
        }
    }
}

// ---------------- compress (+ fused RoPE), q & k in one launch, fp16 in -----
__global__ void __launch_bounds__(256) compress_kernel(
    const __half* __restrict__ Q, const __half* __restrict__ K,
    const float* __restrict__ Wqc, const float* __restrict__ Wkc,
    const float* __restrict__ bqc, const float* __restrict__ bkc,
    __half* __restrict__ qch, __half* __restrict__ kch,
    const float* __restrict__ cosT, const float* __restrict__ sinT)
{
    __shared__ float Ws[HD][LD];
    __shared__ float xs[32][HD];
    const int z = blockIdx.z;
    const __half* X = z ? K : Q;
    const float* Wc = z ? Wkc : Wqc;
    const float* bc = z ? bkc : bqc;
    __half* Xc = z ? kch : qch;
    const int bh = blockIdx.y;
    const int b = bh / H, h = bh % H;
    const int l0 = blockIdx.x * 32;
    const int tid = threadIdx.x;
    for (int i = tid; i < HD * LD; i += 256) Ws[i / LD][i % LD] = Wc[i];
    for (int i = tid; i < 32 * 64; i += 256) {
        const int li = i >> 6, p = i & 63;
        const int l = l0 + li;
        float2 xv = __half22float2(*(const __half2*)&X[
            ((size_t)((b * L + l) * H + h)) * HD + 2 * p]);
        const float c = cosT[l * 64 + p];
        const float s = sinT[l * 64 + p];
        xs[li][2 * p]     = xv.x * c - xv.y * s;
        xs[li][2 * p + 1] = xv.x * s + xv.y * c;
    }
    __syncthreads();
    const int row = tid >> 3;
    const int e0  = (tid & 7) * 4;
    float4 acc = *(const float4*)(bc + e0);
    #pragma unroll
    for (int d = 0; d < HD; d++) {
        const float xv = xs[row][d];
        const float4 w = *(const float4*)&Ws[d][e0];
        acc.x += xv * w.x; acc.y += xv * w.y;
        acc.z += xv * w.z; acc.w += xv * w.w;
    }
    __half2* dst = (__half2*)(Xc + ((size_t)bh * L + l0 + row) * LD + e0);
    dst[0] = __floats2half2_rn(acc.x, acc.y);
    dst[1] = __floats2half2_rn(acc.z, acc.w);
}

// ---------------- tensor-core causal flash attention ------------------------
// 128 queries/block (8 warps x 16 rows), 64-key tiles.
__global__ void __launch_bounds__(256) attn_kernel(
    const __half* __restrict__ qc, const __half* __restrict__ kc,
    const __half* __restrict__ vc, __half* __restrict__ ao)
{
    __shared__ __half qs[128][40];
    __shared__ __half ks[64][40];
    __shared__ __half vs[64][40];
    constexpr float SCALE = 0.17677669529663687f;

    const int bh  = blockIdx.y;
    const int q0  = (gridDim.x - 1 - blockIdx.x) * 128;
    const int tid = threadIdx.x;
    const int w = tid >> 5, lane = tid & 31;

    const __half* bq = qc + ((size_t)bh * L + q0) * LD;
    const __half* bk = kc + (size_t)bh * L * LD;
    const __half* bv = vc + (size_t)bh * L * LD;

    for (int i = tid; i < 512; i += 256) {
        const int r = i >> 2, c = i & 3;
        *(uint4*)((char*)&qs[r][0] + c * 16) =
            *(const uint4*)((const char*)(bq + (size_t)r * LD) + c * 16);
    }
    __syncthreads();

    const uint32_t qs_b = smem_u32(qs);
    const uint32_t ks_b = smem_u32(ks);
    const uint32_t vs_b = smem_u32(vs);

    const int arow = ((lane >> 3) & 1) * 8 + (lane & 7);
    const int acol = (lane >> 4) * 16;
    const int brow = (lane >> 4) * 8 + (lane & 7);
    const int bcol = ((lane >> 3) & 1) * 16;

    uint32_t aq[2][4];
    #pragma unroll
    for (int ks2 = 0; ks2 < 2; ks2++)
        ldsm4(aq[ks2], qs_b + (w * 16 + arow) * 80 + ks2 * 32 + acol);

    float o[4][4];
    #pragma unroll
    for (int i = 0; i < 4; i++)
        #pragma unroll
        for (int j = 0; j < 4; j++) o[i][j] = 0.f;
    float m_lo = -INFINITY, m_hi = -INFINITY, l_lo = 0.f, l_hi = 0.f;

    const int nt = q0 / 64 + 2;
    const int row_lo = q0 + w * 16 + (lane >> 2);
    const int row_hi = row_lo + 8;

    for (int t = 0; t < nt; t++) {
        __syncthreads();
        for (int i = tid; i < 512; i += 256) {
            const int mtx = i >> 8;
            const int r = (i >> 2) & 63, c = i & 3;
            const __half* src = (mtx ? bv : bk) + ((size_t)(t * 64 + r)) * LD;
            __half* dst = mtx ? &vs[r][0] : &ks[r][0];
            *(uint4*)((char*)dst + c * 16) =
                *(const uint4*)((const char*)src + c * 16);
        }
        __syncthreads();

        float s[8][4];
        #pragma unroll
        for (int i = 0; i < 8; i++)
            #pragma unroll
            for (int j = 0; j < 4; j++) s[i][j] = 0.f;
        #pragma unroll
        for (int ks2 = 0; ks2 < 2; ks2++) {
            #pragma unroll
            for (int ng = 0; ng < 4; ng++) {
                uint32_t bkf[4];
                ldsm4(bkf, ks_b + (ng * 16 + brow) * 80 + ks2 * 32 + bcol);
                mma16816(s[ng * 2],     aq[ks2], bkf[0], bkf[1]);
                mma16816(s[ng * 2 + 1], aq[ks2], bkf[2], bkf[3]);
            }
        }

        // mask needed for the last TWO tiles (rows span 128 > 64-key tile)
        const bool diag = (t >= nt - 2);
        #pragma unroll
        for (int nf = 0; nf < 8; nf++) {
            const int col = t * 64 + nf * 8 + (lane & 3) * 2;
            #pragma unroll
            for (int j = 0; j < 4; j++) s[nf][j] *= SCALE;
            if (diag) {
                if (col     > row_lo) s[nf][0] = -INFINITY;
                if (col + 1 > row_lo) s[nf][1] = -INFINITY;
                if (col     > row_hi) s[nf][2] = -INFINITY;
                if (col + 1 > row_hi) s[nf][3] = -INFINITY;
            }
        }

        float tm_lo = -INFINITY, tm_hi = -INFINITY;
        #pragma unroll
        for (int nf = 0; nf < 8; nf++) {
            tm_lo = fmaxf(tm_lo, fmaxf(s[nf][0], s[nf][1]));
            tm_hi = fmaxf(tm_hi, fmaxf(s[nf][2], s[nf][3]));
        }
        #pragma unroll
        for (int off = 1; off <= 2; off <<= 1) {
            tm_lo = fmaxf(tm_lo, __shfl_xor_sync(0xffffffffu, tm_lo, off));
            tm_hi = fmaxf(tm_hi, __shfl_xor_sync(0xffffffffu, tm_hi, off));
        }
        const float mn_lo = fmaxf(m_lo, tm_lo);
        const float mn_hi = fmaxf(m_hi, tm_hi);
        const float al_lo = __expf(m_lo - mn_lo);
        const float al_hi = __expf(m_hi - mn_hi);
        m_lo = mn_lo; m_hi = mn_hi;

        float ps_lo = 0.f, ps_hi = 0.f;
        #pragma unroll
        for (int nf = 0; nf < 8; nf++) {
            s[nf][0] = __expf(s[nf][0] - mn_lo);
            s[nf][1] = __expf(s[nf][1] - mn_lo);
            s[nf][2] = __expf(s[nf][2] - mn_hi);
            s[nf][3] = __expf(s[nf][3] - mn_hi);
            ps_lo += s[nf][0] + s[nf][1];
            ps_hi += s[nf][2] + s[nf][3];
        }
        #pragma unroll
        for (int off = 1; off <= 2; off <<= 1) {
            ps_lo += __shfl_xor_sync(0xffffffffu, ps_lo, off);
            ps_hi += __shfl_xor_sync(0xffffffffu, ps_hi, off);
        }
        l_lo = l_lo * al_lo + ps_lo;
        l_hi = l_hi * al_hi + ps_hi;

        #pragma unroll
        for (int nf = 0; nf < 4; nf++) {
            o[nf][0] *= al_lo; o[nf][1] *= al_lo;
            o[nf][2] *= al_hi; o[nf][3] *= al_hi;
        }

        #pragma unroll
        for (int kc4 = 0; kc4 < 4; kc4++) {
            uint32_t ap[4];
            const int f0 = 2 * kc4, f1 = 2 * kc4 + 1;
            ap[0] = h2_u32(__floats2half2_rn(s[f0][0], s[f0][1]));
            ap[1] = h2_u32(__floats2half2_rn(s[f0][2], s[f0][3]));
            ap[2] = h2_u32(__floats2half2_rn(s[f1][0], s[f1][1]));
            ap[3] = h2_u32(__floats2half2_rn(s[f1][2], s[f1][3]));
            #pragma unroll
            for (int half = 0; half < 2; half++) {
                uint32_t bvf[4];
                ldsm4t(bvf, vs_b + (kc4 * 16 + arow) * 80 + half * 32 + acol);
                mma16816(o[half * 2],     ap, bvf[0], bvf[1]);
                mma16816(o[half * 2 + 1], ap, bvf[2], bvf[3]);
            }
        }
    }

    const int b = bh / H, h = bh % H;
    const float inv_lo = 1.f / l_lo, inv_hi = 1.f / l_hi;
    #pragma unroll
    for (int nf = 0; nf < 4; nf++) {
        const int e = nf * 8 + (lane & 3) * 2;
        __half* p_lo = ao + (size_t)(b * L + row_lo) * CD + h * LD + e;
        __half* p_hi = ao + (size_t)(b * L + row_hi) * CD + h * LD + e;
        *(__half2*)p_lo = __floats2half2_rn(o[nf][0] * inv_lo, o[nf][1] * inv_lo);
        *(__half2*)p_hi = __floats2half2_rn(o[nf][2] * inv_hi, o[nf][3] * inv_hi);
    }
}

// ---------------------------------------------------------------------------
extern "C" void kernel_launch(void* const* d_in, const int* in_sizes, int n_in,
                              void* d_out, int out_size)
{
    const float* x    = (const float*)d_in[0];
    const float* cosT = (const float*)d_in[1];
    const float* sinT = (const float*)d_in[2];
    const float* Wq   = (const float*)d_in[3];
    const float* bq   = (const float*)d_in[4];
    const float* Wk   = (const float*)d_in[5];
    const float* bk   = (const float*)d_in[6];
    const float* Wv   = (const float*)d_in[7];
    const float* bv   = (const float*)d_in[8];
    const float* Wqc  = (const float*)d_in[9];
    const float* bqc  = (const float*)d_in[10];
    const float* Wkc  = (const float*)d_in[11];
    const float* bkc  = (const float*)d_in[12];
    const float* Wvc  = (const float*)d_in[13];
    const float* bvc  = (const float*)d_in[14];
    const float* Wd   = (const float*)d_in[15];
    const float* bd   = (const float*)d_in[16];
    const float* Wo   = (const float*)d_in[17];
    const float* bo   = (const float*)d_in[18];
    float* out = (float*)d_out;

    float *bias_o, *bveff;
    __half *q16, *k16, *qch, *kch, *vch, *ao, *a16, *wB, *wo;
    cudaGetSymbolAddress((void**)&q16,    g_q16);
    cudaGetSymbolAddress((void**)&k16,    g_k16);
    cudaGetSymbolAddress((void**)&qch,    g_qch);
    cudaGetSymbolAddress((void**)&kch,    g_kch);
    cudaGetSymbolAddress((void**)&vch,    g_vch);
    cudaGetSymbolAddress((void**)&ao,     g_ao);
    cudaGetSymbolAddress((void**)&a16,    g_a16);
    cudaGetSymbolAddress((void**)&wB,     g_wB);
    cudaGetSymbolAddress((void**)&wo,     g_wo);
    cudaGetSymbolAddress((void**)&bias_o, g_bo);
    cudaGetSymbolAddress((void**)&bveff,  g_bv);

    cudaFuncSetAttribute(gemm_qkv_kernel,
                         cudaFuncAttributeMaxDynamicSharedMemorySize, SMEMB);
    cudaFuncSetAttribute(gemm_out_kernel,
                         cudaFuncAttributeMaxDynamicSharedMemorySize, SMEMB);
    cudaFuncSetAttribute(prep_merged_kernel,
                         cudaFuncAttributeMaxDynamicSharedMemorySize, SMEM_PREP);

    // --- merged conversions + weight folding (one launch) ---
    prep_merged_kernel<<<NPREP, 256, SMEM_PREP>>>(
        x, a16, Wq, Wk, wB, Wv, Wvc, Wd, Wo, wo,
        bd, bo, bias_o, bv, bvc, bveff);

    // --- unified Q,K,Vc GEMM (fp16 q/k out) ---
    gemm_qkv_kernel<<<dim3(NB / 128, GM / 256), 256, SMEMB>>>(
        a16, wB, bq, bk, bveff, q16, k16, vch);

    // --- compress + rope for q,k (single launch) ---
    compress_kernel<<<dim3(L / 32, B * H, 2), 256>>>(
        q16, k16, Wqc, Wkc, bqc, bkc, qch, kch, cosT, sinT);

    // --- attention (128 queries/block) ---
    attn_kernel<<<dim3(L / 128, B * H), 256>>>(qch, kch, vch, ao);

    // --- decompress+output projection folded ---
    gemm_out_kernel<<<dim3(D / 128, GM / 256), 256, SMEMB>>>(
        ao, wo, bias_o, out);
}

// round 17
// speedup vs baseline: 9.7902x; 1.0232x over previous
#include <cuda_runtime.h>
#include <cuda_fp16.h>
#include <math.h>
#include <cstdint>

namespace {
constexpr int B  = 2;
constexpr int L  = 2048;
constexpr int D  = 2048;
constexpr int H  = 16;
constexpr int HD = 128;
constexpr int LD = 32;
constexpr int BL = B * L;                 // 4096
constexpr int BHLLD = B * H * L * LD;     // 2097152
constexpr int CD = H * LD;                // 512
constexpr int GM = BL;                    // 4096
constexpr int NB = 2 * D + CD;            // 4608 B rows (Wq|Wk|Wveff)

constexpr int BK     = 32;
constexpr int STAGES = 3;
constexpr int ROWB   = 80;
constexpr int OFF_B  = 256 * ROWB;
constexpr int STAGEB = 384 * ROWB;        // 30720
constexpr int SMEMB  = STAGES * STAGEB;   // 92160

// merged prep launch: dynamic smem = max over branches
constexpr int SMEM_PREP = 128 * 36 * 4 + 128 * 132 * 2;    // 52224 (wo branch)

// dispatch table (block ranges within the merged prep grid)
constexpr int NWV  = 256;
constexpr int NWO  = 256;
constexpr int NBO  = 64;
constexpr int NBV  = 1;
constexpr int NCW  = 4096;
constexpr int NCA  = GM * D / 4 / 256;     // 8192
constexpr int NPREP = NWV + NWO + NBO + NBV + NCW + NCA;

// qc pre-scale: 1/sqrt(32) * log2(e)
constexpr float QSCALE = 0.17677669529663687f * 1.4426950408889634f;
}

// ---------------- scratch ----------------------------------------------------
__device__ __half g_q16[GM * D];     // q fp16 (b,l,h,hd)
__device__ __half g_k16[GM * D];
__device__ __half g_qch[BHLLD];      // (b,h,l,e)  [pre-scaled by QSCALE]
__device__ __half g_kch[BHLLD];
__device__ __half g_vch[BHLLD];
__device__ __half g_ao[BL * CD];     // attn out fp16 (b*l, h*32+e)
__device__ __half g_a16[GM * D];     // x fp16 [M,K]
__device__ __half g_wB[(size_t)NB * D];  // Wq|Wk|Wveff fp16 [N,K]
__device__ __half g_wo[D * CD];      // Weffo fp16 [N=2048, K=512]
__device__ float  g_bo[D];
__device__ float  g_bv[CD];

// ================= PTX helpers ==============================================
__device__ __forceinline__ uint32_t smem_u32(const void* p) {
    uint32_t a;
    asm("{ .reg .u64 t; cvta.to.shared.u64 t, %1; cvt.u32.u64 %0, t; }"
        : "=r"(a) : "l"(p));
    return a;
}
__device__ __forceinline__ uint32_t h2_u32(__half2 h) {
    return *reinterpret_cast<uint32_t*>(&h);
}
__device__ __forceinline__ float ex2(float x) {
    float r; asm("ex2.approx.f32 %0, %1;" : "=f"(r) : "f"(x)); return r;
}
__device__ __forceinline__ void cp_async16(uint32_t dst, const void* src) {
    asm volatile("cp.async.cg.shared.global [%0], [%1], 16;"
                 :: "r"(dst), "l"(src) : "memory");
}
__device__ __forceinline__ void cp_commit() {
    asm volatile("cp.async.commit_group;" ::: "memory");
}
template <int N>
__device__ __forceinline__ void cp_wait() {
    asm volatile("cp.async.wait_group %0;" :: "n"(N) : "memory");
}
__device__ __forceinline__ void ldsm4(uint32_t* r, uint32_t addr) {
    asm volatile("ldmatrix.sync.aligned.m8n8.x4.shared.b16 {%0,%1,%2,%3}, [%4];"
                 : "=r"(r[0]), "=r"(r[1]), "=r"(r[2]), "=r"(r[3]) : "r"(addr));
}
__device__ __forceinline__ void ldsm4t(uint32_t* r, uint32_t addr) {
    asm volatile("ldmatrix.sync.aligned.m8n8.x4.trans.shared.b16 {%0,%1,%2,%3}, [%4];"
                 : "=r"(r[0]), "=r"(r[1]), "=r"(r[2]), "=r"(r[3]) : "r"(addr));
}
__device__ __forceinline__ void mma16816(float* d, const uint32_t* a,
                                         uint32_t b0, uint32_t b1) {
    asm volatile(
        "mma.sync.aligned.m16n8k16.row.col.f32.f16.f16.f32 "
        "{%0,%1,%2,%3}, {%4,%5,%6,%7}, {%8,%9}, {%0,%1,%2,%3};"
        : "+f"(d[0]), "+f"(d[1]), "+f"(d[2]), "+f"(d[3])
        : "r"(a[0]), "r"(a[1]), "r"(a[2]), "r"(a[3]), "r"(b0), "r"(b1));
}

// ================= merged prep kernel =======================================
__global__ void __launch_bounds__(256) prep_merged_kernel(
    const float* __restrict__ x,   __half* __restrict__ a16,
    const float* __restrict__ Wq,  const float* __restrict__ Wk,
    __half* __restrict__ wB,
    const float* __restrict__ Wv,  const float* __restrict__ Wvc,
    const float* __restrict__ Wd,  const float* __restrict__ Wo,
    __half* __restrict__ w16o,
    const float* __restrict__ bd,  const float* __restrict__ bo,
    float* __restrict__ bias_o,
    const float* __restrict__ bv,  const float* __restrict__ bvc,
    float* __restrict__ bveff)
{
    extern __shared__ char dsm[];
    const int tid = threadIdx.x;
    int bx = blockIdx.x;

    if (bx < NWV) {
        __half* w16v = wB + (size_t)2 * D * D;
        __half (*a_s)[130] = (__half(*)[130])dsm;
        __half (*b_s)[130] = (__half(*)[130])(dsm + 32 * 130 * 2);
        const int h = bx >> 4, i0 = (bx & 15) * 128;
        for (int idx = tid; idx < HD * LD; idx += 256) {
            const int d = idx >> 5, e = idx & 31;
            a_s[e][d] = __float2half_rn(Wvc[idx]);
        }
        for (int idx = tid; idx < 128 * 32; idx += 256) {
            const int il = idx >> 5, dq = (idx & 31) * 4;
            float4 v = *(const float4*)(Wv + (size_t)(i0 + il) * D
                                        + h * HD + dq);
            *(__half2*)&b_s[il][dq]     = __floats2half2_rn(v.x, v.y);
            *(__half2*)&b_s[il][dq + 2] = __floats2half2_rn(v.z, v.w);
        }
        __syncthreads();
        const int e0  = (tid & 7) * 4;
        const int il0 = (tid >> 3) * 4;
        float acc[4][4] = {};
        #pragma unroll 8
        for (int d = 0; d < HD; d += 2) {
            float2 av[4], bvv[4];
            #pragma unroll
            for (int j = 0; j < 4; j++)
                av[j] = __half22float2(*(const __half2*)&a_s[e0 + j][d]);
            #pragma unroll
            for (int i = 0; i < 4; i++)
                bvv[i] = __half22float2(*(const __half2*)&b_s[il0 + i][d]);
            #pragma unroll
            for (int j = 0; j < 4; j++)
                #pragma unroll
                for (int i = 0; i < 4; i++)
                    acc[j][i] += av[j].x * bvv[i].x + av[j].y * bvv[i].y;
        }
        #pragma unroll
        for (int j = 0; j < 4; j++) {
            __half2* dst = (__half2*)(w16v + (size_t)(h * LD + e0 + j) * D
                                      + i0 + il0);
            dst[0] = __floats2half2_rn(acc[j][0], acc[j][1]);
            dst[1] = __floats2half2_rn(acc[j][2], acc[j][3]);
        }
        return;
    }
    bx -= NWV;

    if (bx < NWO) {
        float  (*a_s)[36]  = (float(*)[36])dsm;
        __half (*b_s)[132] = (__half(*)[132])(dsm + 128 * 36 * 4);
        const int h = bx >> 4, n0 = (bx & 15) * 128;
        for (int idx = tid; idx < LD * HD; idx += 256) {
            const int e = idx >> 7, d = idx & 127;
            a_s[d][e] = Wd[idx];
        }
        for (int idx = tid; idx < 128 * 32; idx += 256) {
            const int d = idx >> 5, nlq = (idx & 31) * 4;
            float4 v = *(const float4*)(Wo + (size_t)(h * HD + d) * D
                                        + n0 + nlq);
            *(__half2*)&b_s[d][nlq]     = __floats2half2_rn(v.x, v.y);
            *(__half2*)&b_s[d][nlq + 2] = __floats2half2_rn(v.z, v.w);
        }
        __syncthreads();
        const int e0  = (tid & 7) * 4;
        const int nl0 = (tid >> 3) * 4;
        float acc[4][4] = {};
        #pragma unroll 4
        for (int d = 0; d < HD; d++) {
            const float4 a4 = *(const float4*)&a_s[d][e0];
            const float2 b01 = __half22float2(*(const __half2*)&b_s[d][nl0]);
            const float2 b23 = __half22float2(*(const __half2*)&b_s[d][nl0 + 2]);
            acc[0][0] += a4.x * b01.x; acc[0][1] += a4.x * b01.y;
            acc[0][2] += a4.x * b23.x; acc[0][3] += a4.x * b23.y;
            acc[1][0] += a4.y * b01.x; acc[1][1] += a4.y * b01.y;
            acc[1][2] += a4.y * b23.x; acc[1][3] += a4.y * b23.y;
            acc[2][0] += a4.z * b01.x; acc[2][1] += a4.z * b01.y;
            acc[2][2] += a4.z * b23.x; acc[2][3] += a4.z * b23.y;
            acc[3][0] += a4.w * b01.x; acc[3][1] += a4.w * b01.y;
            acc[3][2] += a4.w * b23.x; acc[3][3] += a4.w * b23.y;
        }
        #pragma unroll
        for (int i = 0; i < 4; i++) {
            __half2* dst = (__half2*)(w16o + (size_t)(n0 + nl0 + i) * CD
                                      + h * LD + e0);
            dst[0] = __floats2half2_rn(acc[0][i], acc[1][i]);
            dst[1] = __floats2half2_rn(acc[2][i], acc[3][i]);
        }
        return;
    }
    bx -= NWO;

    if (bx < NBO) {
        float (*part)[32] = (float(*)[32])dsm;
        const int nl = tid & 31, rc = tid >> 5;
        const int n = bx * 32 + nl;
        float acc = 0.f;
        for (int r = rc * 256; r < rc * 256 + 256; r++)
            acc += bd[r & 127] * Wo[(size_t)r * D + n];
        part[rc][nl] = acc;
        __syncthreads();
        if (tid < 32) {
            float s = bo[bx * 32 + tid];
            #pragma unroll
            for (int j = 0; j < 8; j++) s += part[j][tid];
            bias_o[bx * 32 + tid] = s;
        }
        return;
    }
    bx -= NBO;

    if (bx < NBV) {
        for (int o = tid; o < CD; o += 256) {
            const int h = o >> 5, e = o & 31;
            float acc = bvc[e];
            for (int d = 0; d < HD; d++)
                acc += bv[h * HD + d] * Wvc[d * LD + e];
            bveff[o] = acc;
        }
        return;
    }
    bx -= NBV;

    if (bx < NCW) {
        float (*t)[33] = (float(*)[33])dsm;
        const int z = bx >> 11;
        const int rem = bx & 2047;
        const int n0 = (rem & 63) * 32, k0 = (rem >> 6) * 64;
        const float* W = z ? Wk : Wq;
        __half* dst = wB + (size_t)z * D * D;
        const int tx = tid & 31, ty = tid >> 5;
        #pragma unroll
        for (int i = 0; i < 8; i++)
            t[ty + i * 8][tx] = W[(size_t)(k0 + ty + i * 8) * D + n0 + tx];
        __syncthreads();
        #pragma unroll
        for (int i = 0; i < 4; i++) {
            const int nr = ty + i * 8;
            *(__half2*)(dst + (size_t)(n0 + nr) * D + k0 + 2 * tx) =
                __floats2half2_rn(t[2 * tx][nr], t[2 * tx + 1][nr]);
        }
        return;
    }
    bx -= NCW;

    {
        long long i = ((long long)bx * 256 + tid) * 4;
        float4 v = *(const float4*)(x + i);
        *(__half2*)(a16 + i)     = __floats2half2_rn(v.x, v.y);
        *(__half2*)(a16 + i + 2) = __floats2half2_rn(v.z, v.w);
    }
}

// ================= unified QKV GEMM (K=2048, N=4608) ========================
__device__ __forceinline__ void load_stage_qkv(
    uint32_t sbase, const __half* pA, const __half* pB, int kc, int tid)
{
    const int r0 = tid >> 2, seg = tid & 3;
    const uint32_t so = sbase + r0 * ROWB + seg * 16;
    const size_t go = (size_t)r0 * D + kc + seg * 8;
    #pragma unroll
    for (int j = 0; j < 4; j++)
        cp_async16(so + j * 64 * ROWB, pA + go + (size_t)j * 64 * D);
    #pragma unroll
    for (int j = 0; j < 2; j++)
        cp_async16(so + (256 + j * 64) * ROWB, pB + go + (size_t)j * 64 * D);
}

__global__ void __launch_bounds__(256) gemm_qkv_kernel(
    const __half* __restrict__ A16, const __half* __restrict__ wB,
    const float* __restrict__ bq, const float* __restrict__ bk,
    const float* __restrict__ bveff,
    __half* __restrict__ q16, __half* __restrict__ k16,
    __half* __restrict__ vch)
{
    constexpr int NITL = D / BK;   // 64
    extern __shared__ char smem[];
    const uint32_t sb0 = smem_u32(smem);
    const int tid = threadIdx.x, wid = tid >> 5, lane = tid & 31;
    const int warp_m = (wid & 3) * 64;
    const int warp_n = (wid >> 2) * 64;
    const int m0 = blockIdx.y * 256;
    const int n0 = blockIdx.x * 128;

    const __half* pA = A16 + (size_t)m0 * D;
    const __half* pB = wB  + (size_t)n0 * D;

    float acc[4][8][4];
    #pragma unroll
    for (int i = 0; i < 4; i++)
        #pragma unroll
        for (int j = 0; j < 8; j++)
            #pragma unroll
            for (int t = 0; t < 4; t++) acc[i][j][t] = 0.f;

    const int arow = ((lane >> 3) & 1) * 8 + (lane & 7);
    const int acol = (lane >> 4) * 16;
    const int brow = (lane >> 4) * 8 + (lane & 7);
    const int bcol = ((lane >> 3) & 1) * 16;

    load_stage_qkv(sb0, pA, pB, 0, tid);
    cp_commit();
    load_stage_qkv(sb0 + STAGEB, pA, pB, BK, tid);
    cp_commit();

    #pragma unroll 1
    for (int kt = 0; kt < NITL; kt++) {
        cp_wait<1>();
        __syncthreads();
        if (kt + 2 < NITL)
            load_stage_qkv(sb0 + ((kt + 2) % STAGES) * STAGEB,
                           pA, pB, (kt + 2) * BK, tid);
        cp_commit();

        const uint32_t sb = sb0 + (kt % STAGES) * STAGEB;
        #pragma unroll
        for (int ks = 0; ks < 2; ks++) {
            uint32_t ah[4][4];
            #pragma unroll
            for (int mt = 0; mt < 4; mt++)
                ldsm4(ah[mt], sb + (warp_m + mt * 16 + arow) * ROWB
                              + ks * 32 + acol);
            uint32_t bh[4][4];
            #pragma unroll
            for (int np = 0; np < 4; np++)
                ldsm4(bh[np], sb + OFF_B + (warp_n + np * 16 + brow) * ROWB
                              + ks * 32 + bcol);
            #pragma unroll
            for (int mt = 0; mt < 4; mt++)
                #pragma unroll
                for (int nt = 0; nt < 8; nt++) {
                    const int np = nt >> 1, pp = (nt & 1) * 2;
                    mma16816(acc[mt][nt], ah[mt], bh[np][pp], bh[np][pp + 1]);
                }
        }
    }

    if (n0 < 2 * D) {
        __half* C = (n0 < D) ? q16 : k16;
        const float* bias = (n0 < D) ? bq : bk;
        const int nc0 = (n0 < D) ? n0 : n0 - D;
        #pragma unroll
        for (int mt = 0; mt < 4; mt++) {
            const int row = m0 + warp_m + mt * 16 + (lane >> 2);
            #pragma unroll
            for (int nt = 0; nt < 8; nt++) {
                const int col = nc0 + warp_n + nt * 8 + (lane & 3) * 2;
                const float b0 = bias[col], b1 = bias[col + 1];
                *(__half2*)(C + (size_t)row * D + col) =
                    __floats2half2_rn(acc[mt][nt][0] + b0, acc[mt][nt][1] + b1);
                *(__half2*)(C + (size_t)(row + 8) * D + col) =
                    __floats2half2_rn(acc[mt][nt][2] + b0, acc[mt][nt][3] + b1);
            }
        }
    } else {
        const int ncv = n0 - 2 * D;
        #pragma unroll
        for (int mt = 0; mt < 4; mt++) {
            const int row = m0 + warp_m + mt * 16 + (lane >> 2);
            const int b0i = row >> 11, l0i = row & (L - 1);
            const int b1i = (row + 8) >> 11, l1i = (row + 8) & (L - 1);
            #pragma unroll
            for (int nt = 0; nt < 8; nt++) {
                const int col = ncv + warp_n + nt * 8 + (lane & 3) * 2;
                const int h = col >> 5, e = col & 31;
                const float bb0 = bveff[col], bb1 = bveff[col + 1];
                *(__half2*)(vch + ((size_t)(b0i * H + h) * L + l0i) * LD + e) =
                    __floats2half2_rn(acc[mt][nt][0] + bb0,
                                      acc[mt][nt][1] + bb1);
                *(__half2*)(vch + ((size_t)(b1i * H + h) * L + l1i) * LD + e) =
                    __floats2half2_rn(acc[mt][nt][2] + bb0,
                                      acc[mt][nt][3] + bb1);
            }
        }
    }
}

// ================= output GEMM (K=512) ======================================
__device__ __forceinline__ void load_stage_out(
    uint32_t sbase, const __half* pA, const __half* pB, int kc, int tid)
{
    const int r0 = tid >> 2, seg = tid & 3;
    const uint32_t so = sbase + r0 * ROWB + seg * 16;
    const size_t go = (size_t)r0 * CD + kc + seg * 8;
    #pragma unroll
    for (int j = 0; j < 4; j++)
        cp_async16(so + j * 64 * ROWB, pA + go + (size_t)j * 64 * CD);
    #pragma unroll
    for (int j = 0; j < 2; j++)
        cp_async16(so + (256 + j * 64) * ROWB, pB + go + (size_t)j * 64 * CD);
}

__global__ void __launch_bounds__(256) gemm_out_kernel(
    const __half* __restrict__ A16, const __half* __restrict__ Bw,
    const float* __restrict__ bias, float* __restrict__ C)
{
    constexpr int NITL = CD / BK;  // 16
    extern __shared__ char smem[];
    const uint32_t sb0 = smem_u32(smem);
    const int tid = threadIdx.x, wid = tid >> 5, lane = tid & 31;
    const int warp_m = (wid & 3) * 64;
    const int warp_n = (wid >> 2) * 64;
    const int m0 = blockIdx.y * 256, n0 = blockIdx.x * 128;

    const __half* pA = A16 + (size_t)m0 * CD;
    const __half* pB = Bw  + (size_t)n0 * CD;

    float acc[4][8][4];
    #pragma unroll
    for (int i = 0; i < 4; i++)
        #pragma unroll
        for (int j = 0; j < 8; j++)
            #pragma unroll
            for (int t = 0; t < 4; t++) acc[i][j][t] = 0.f;

    const int arow = ((lane >> 3) & 1) * 8 + (lane & 7);
    const int acol = (lane >> 4) * 16;
    const int brow = (lane >> 4) * 8 + (lane & 7);
    const int bcol = ((lane >> 3) & 1) * 16;

    load_stage_out(sb0, pA, pB, 0, tid);
    cp_commit();
    load_stage_out(sb0 + STAGEB, pA, pB, BK, tid);
    cp_commit();

    #pragma unroll 1
    for (int kt = 0; kt < NITL; kt++) {
        cp_wait<1>();
        __syncthreads();
        if (kt + 2 < NITL)
            load_stage_out(sb0 + ((kt + 2) % STAGES) * STAGEB,
                           pA, pB, (kt + 2) * BK, tid);
        cp_commit();

        const uint32_t sb = sb0 + (kt % STAGES) * STAGEB;
        #pragma unroll
        for (int ks = 0; ks < 2; ks++) {
            uint32_t ah[4][4];
            #pragma unroll
            for (int mt = 0; mt < 4; mt++)
                ldsm4(ah[mt], sb + (warp_m + mt * 16 + arow) * ROWB
                              + ks * 32 + acol);
            uint32_t bh[4][4];
            #pragma unroll
            for (int np = 0; np < 4; np++)
                ldsm4(bh[np], sb + OFF_B + (warp_n + np * 16 + brow) * ROWB
                              + ks * 32 + bcol);
            #pragma unroll
            for (int mt = 0; mt < 4; mt++)
                #pragma unroll
                for (int nt = 0; nt < 8; nt++) {
                    const int np = nt >> 1, pp = (nt & 1) * 2;
                    mma16816(acc[mt][nt], ah[mt], bh[np][pp], bh[np][pp + 1]);
                }
        }
    }

    #pragma unroll
    for (int mt = 0; mt < 4; mt++) {
        const int row = m0 + warp_m + mt * 16 + (lane >> 2);
        #pragma unroll
        for (int nt = 0; nt < 8; nt++) {
            const int col = n0 + warp_n + nt * 8 + (lane & 3) * 2;
            const float b0 = bias[col], b1 = bias[col + 1];
            *(float2*)(C + (size_t)row * D + col) =
                make_float2(acc[mt][nt][0] + b0, acc[mt][nt][1] + b1);
            *(float2*)(C + (size_t)(row + 8) * D + col) =
                make_float2(acc[mt][nt][2] + b0, acc[mt][nt][3] + b1);
        }
    }
}

// ---------------- compress (+ fused RoPE), q pre-scaled by QSCALE -----------
__global__ void __launch_bounds__(256) compress_kernel(
    const __half* __restrict__ Q, const __half* __restrict__ K,
    const float* __restrict__ Wqc, const float* __restrict__ Wkc,
    const float* __restrict__ bqc, const float* __restrict__ bkc,
    __half* __restrict__ qch, __half* __restrict__ kch,
    const float* __restrict__ cosT, const float* __restrict__ sinT)
{
    __shared__ float Ws[HD][LD];
    __shared__ float xs[32][HD];
    const int z = blockIdx.z;
    const __half* X = z ? K : Q;
    const float* Wc = z ? Wkc : Wqc;
    const float* bc = z ? bkc : bqc;
    __half* Xc = z ? kch : qch;
    const float sc = z ? 1.0f : QSCALE;
    const int bh = blockIdx.y;
    const int b = bh / H, h = bh % H;
    const int l0 = blockIdx.x * 32;
    const int tid = threadIdx.x;
    for (int i = tid; i < HD * LD; i += 256) Ws[i / LD][i % LD] = Wc[i];
    for (int i = tid; i < 32 * 64; i += 256) {
        const int li = i >> 6, p = i & 63;
        const int l = l0 + li;
        float2 xv = __half22float2(*(const __half2*)&X[
            ((size_t)((b * L + l) * H + h)) * HD + 2 * p]);
        const float c = cosT[l * 64 + p];
        const float s = sinT[l * 64 + p];
        xs[li][2 * p]     = xv.x * c - xv.y * s;
        xs[li][2 * p + 1] = xv.x * s + xv.y * c;
    }
    __syncthreads();
    const int row = tid >> 3;
    const int e0  = (tid & 7) * 4;
    float4 acc = *(const float4*)(bc + e0);
    #pragma unroll
    for (int d = 0; d < HD; d++) {
        const float xv = xs[row][d];
        const float4 w = *(const float4*)&Ws[d][e0];
        acc.x += xv * w.x; acc.y += xv * w.y;
        acc.z += xv * w.z; acc.w += xv * w.w;
    }
    __half2* dst = (__half2*)(Xc + ((size_t)bh * L + l0 + row) * LD + e0);
    dst[0] = __floats2half2_rn(acc.x * sc, acc.y * sc);
    dst[1] = __floats2half2_rn(acc.z * sc, acc.w * sc);
}

// ---------------- tensor-core causal flash attention ------------------------
// 128 queries/block (8 warps x 16 rows), 64-key tiles, double-buffered K/V.
// qc pre-scaled so MMA emits log2-domain scores; softmax uses ex2.
__global__ void __launch_bounds__(256) attn_kernel(
    const __half* __restrict__ qc, const __half* __restrict__ kc,
    const __half* __restrict__ vc, __half* __restrict__ ao)
{
    __shared__ __half qs[128][40];
    __shared__ __half ks[2][64][40];
    __shared__ __half vs[2][64][40];

    const int bh  = blockIdx.y;
    const int q0  = (gridDim.x - 1 - blockIdx.x) * 128;
    const int tid = threadIdx.x;
    const int w = tid >> 5, lane = tid & 31;

    const __half* bq = qc + ((size_t)bh * L + q0) * LD;
    const __half* bk = kc + (size_t)bh * L * LD;
    const __half* bv = vc + (size_t)bh * L * LD;

    const uint32_t qs_b = smem_u32(qs);
    const uint32_t ks_b = smem_u32(ks);
    const uint32_t vs_b = smem_u32(vs);
    constexpr uint32_t TILEB = 64 * 80;   // bytes per K or V tile buffer

    // async K/V tile loader: 512 16B chunks (K then V) -> buffer `buf`
    auto load_kv = [&](int t, int buf) {
        #pragma unroll
        for (int j = 0; j < 2; j++) {
            const int i = tid + j * 256;
            const int mtx = i >> 8;
            const int r = (i >> 2) & 63, c = i & 3;
            const __half* src = (mtx ? bv : bk) + ((size_t)(t * 64 + r)) * LD
                                + c * 8;
            const uint32_t dst = (mtx ? vs_b : ks_b) + buf * TILEB
                               + r * 80 + c * 16;
            cp_async16(dst, src);
        }
    };

    // load Q tile (plain) + prefetch K/V tile 0 (async)
    for (int i = tid; i < 512; i += 256) {
        const int r = i >> 2, c = i & 3;
        *(uint4*)((char*)&qs[r][0] + c * 16) =
            *(const uint4*)((const char*)(bq + (size_t)r * LD) + c * 16);
    }
    load_kv(0, 0);
    cp_commit();
    __syncthreads();

    const int arow = ((lane >> 3) & 1) * 8 + (lane & 7);
    const int acol = (lane >> 4) * 16;
    const int brow = (lane >> 4) * 8 + (lane & 7);
    const int bcol = ((lane >> 3) & 1) * 16;

    uint32_t aq[2][4];
    #pragma unroll
    for (int ks2 = 0; ks2 < 2; ks2++)
        ldsm4(aq[ks2], qs_b + (w * 16 + arow) * 80 + ks2 * 32 + acol);

    float o[4][4];
    #pragma unroll
    for (int i = 0; i < 4; i++)
        #pragma unroll
        for (int j = 0; j < 4; j++) o[i][j] = 0.f;
    float m_lo = -INFINITY, m_hi = -INFINITY, l_lo = 0.f, l_hi = 0.f;

    const int nt = q0 / 64 + 2;
    const int row_lo = q0 + w * 16 + (lane >> 2);
    const int row_hi = row_lo + 8;

    for (int t = 0; t < nt; t++) {
        cp_wait<0>();
        __syncthreads();
        if (t + 1 < nt) {
            load_kv(t + 1, (t + 1) & 1);
            cp_commit();
        }
        const int buf = t & 1;
        const uint32_t kb = ks_b + buf * TILEB;
        const uint32_t vb = vs_b + buf * TILEB;

        float s[8][4];
        #pragma unroll
        for (int i = 0; i < 8; i++)
            #pragma unroll
            for (int j = 0; j < 4; j++) s[i][j] = 0.f;
        #pragma unroll
        for (int ks2 = 0; ks2 < 2; ks2++) {
            #pragma unroll
            for (int ng = 0; ng < 4; ng++) {
                uint32_t bkf[4];
                ldsm4(bkf, kb + (ng * 16 + brow) * 80 + ks2 * 32 + bcol);
                mma16816(s[ng * 2],     aq[ks2], bkf[0], bkf[1]);
                mma16816(s[ng * 2 + 1], aq[ks2], bkf[2], bkf[3]);
            }
        }

        // causal mask (scores already scaled into log2 domain by qc prescale)
        if (t >= nt - 2) {
            #pragma unroll
            for (int nf = 0; nf < 8; nf++) {
                const int col = t * 64 + nf * 8 + (lane & 3) * 2;
                if (col     > row_lo) s[nf][0] = -INFINITY;
                if (col + 1 > row_lo) s[nf][1] = -INFINITY;
                if (col     > row_hi) s[nf][2] = -INFINITY;
                if (col + 1 > row_hi) s[nf][3] = -INFINITY;
            }
        }

        float tm_lo = -INFINITY, tm_hi = -INFINITY;
        #pragma unroll
        for (int nf = 0; nf < 8; nf++) {
            tm_lo = fmaxf(tm_lo, fmaxf(s[nf][0], s[nf][1]));
            tm_hi = fmaxf(tm_hi, fmaxf(s[nf][2], s[nf][3]));
        }
        #pragma unroll
        for (int off = 1; off <= 2; off <<= 1) {
            tm_lo = fmaxf(tm_lo, __shfl_xor_sync(0xffffffffu, tm_lo, off));
            tm_hi = fmaxf(tm_hi, __shfl_xor_sync(0xffffffffu, tm_hi, off));
        }
        const float mn_lo = fmaxf(m_lo, tm_lo);
        const float mn_hi = fmaxf(m_hi, tm_hi);
        const float al_lo = ex2(m_lo - mn_lo);
        const float al_hi = ex2(m_hi - mn_hi);
        m_lo = mn_lo; m_hi = mn_hi;

        float ps_lo = 0.f, ps_hi = 0.f;
        #pragma unroll
        for (int nf = 0; nf < 8; nf++) {
            s[nf][0] = ex2(s[nf][0] - mn_lo);
            s[nf][1] = ex2(s[nf][1] - mn_lo);
            s[nf][2] = ex2(s[nf][2] - mn_hi);
            s[nf][3] = ex2(s[nf][3] - mn_hi);
            ps_lo += s[nf][0] + s[nf][1];
            ps_hi += s[nf][2] + s[nf][3];
        }
        #pragma unroll
        for (int off = 1; off <= 2; off <<= 1) {
            ps_lo += __shfl_xor_sync(0xffffffffu, ps_lo, off);
            ps_hi += __shfl_xor_sync(0xffffffffu, ps_hi, off);
        }
        l_lo = l_lo * al_lo + ps_lo;
        l_hi = l_hi * al_hi + ps_hi;

        #pragma unroll
        for (int nf = 0; nf < 4; nf++) {
            o[nf][0] *= al_lo; o[nf][1] *= al_lo;
            o[nf][2] *= al_hi; o[nf][3] *= al_hi;
        }

        #pragma unroll
        for (int kc4 = 0; kc4 < 4; kc4++) {
            uint32_t ap[4];
            const int f0 = 2 * kc4, f1 = 2 * kc4 + 1;
            ap[0] = h2_u32(__floats2half2_rn(s[f0][0], s[f0][1]));
            ap[1] = h2_u32(__floats2half2_rn(s[f0][2], s[f0][3]));
            ap[2] = h2_u32(__floats2half2_rn(s[f1][0], s[f1][1]));
            ap[3] = h2_u32(__floats2half2_rn(s[f1][2], s[f1][3]));
            #pragma unroll
            for (int half = 0; half < 2; half++) {
                uint32_t bvf[4];
                ldsm4t(bvf, vb + (kc4 * 16 + arow) * 80 + half * 32 + acol);
                mma16816(o[half * 2],     ap, bvf[0], bvf[1]);
                mma16816(o[half * 2 + 1], ap, bvf[2], bvf[3]);
            }
        }
    }

    const int b = bh / H, h = bh % H;
    const float inv_lo = 1.f / l_lo, inv_hi = 1.f / l_hi;
    #pragma unroll
    for (int nf = 0; nf < 4; nf++) {
        const int e = nf * 8 + (lane & 3) * 2;
        __half* p_lo = ao + (size_t)(b * L + row_lo) * CD + h * LD + e;
        __half* p_hi = ao + (size_t)(b * L + row_hi) * CD + h * LD + e;
        *(__half2*)p_lo = __floats2half2_rn(o[nf][0] * inv_lo, o[nf][1] * inv_lo);
        *(__half2*)p_hi = __floats2half2_rn(o[nf][2] * inv_hi, o[nf][3] * inv_hi);
    }
}

// ---------------------------------------------------------------------------
extern "C" void kernel_launch(void* const* d_in, const int* in_sizes, int n_in,
                              void* d_out, int out_size)
{
    const float* x    = (const float*)d_in[0];
    const float* cosT = (const float*)d_in[1];
    const float* sinT = (const float*)d_in[2];
    const float* Wq   = (const float*)d_in[3];
    const float* bq   = (const float*)d_in[4];
    const float* Wk   = (const float*)d_in[5];
    const float* bk   = (const float*)d_in[6];
    const float* Wv   = (const float*)d_in[7];
    const float* bv   = (const float*)d_in[8];
    const float* Wqc  = (const float*)d_in[9];
    const float* bqc  = (const float*)d_in[10];
    const float* Wkc  = (const float*)d_in[11];
    const float* bkc  = (const float*)d_in[12];
    const float* Wvc  = (const float*)d_in[13];
    const float* bvc  = (const float*)d_in[14];
    const float* Wd   = (const float*)d_in[15];
    const float* bd   = (const float*)d_in[16];
    const float* Wo   = (const float*)d_in[17];
    const float* bo   = (const float*)d_in[18];
    float* out = (float*)d_out;

    float *bias_o, *bveff;
    __half *q16, *k16, *qch, *kch, *vch, *ao, *a16, *wB, *wo;
    cudaGetSymbolAddress((void**)&q16,    g_q16);
    cudaGetSymbolAddress((void**)&k16,    g_k16);
    cudaGetSymbolAddress((void**)&qch,    g_qch);
    cudaGetSymbolAddress((void**)&kch,    g_kch);
    cudaGetSymbolAddress((void**)&vch,    g_vch);
    cudaGetSymbolAddress((void**)&ao,     g_ao);
    cudaGetSymbolAddress((void**)&a16,    g_a16);
    cudaGetSymbolAddress((void**)&wB,     g_wB);
    cudaGetSymbolAddress((void**)&wo,     g_wo);
    cudaGetSymbolAddress((void**)&bias_o, g_bo);
    cudaGetSymbolAddress((void**)&bveff,  g_bv);

    cudaFuncSetAttribute(gemm_qkv_kernel,
                         cudaFuncAttributeMaxDynamicSharedMemorySize, SMEMB);
    cudaFuncSetAttribute(gemm_out_kernel,
                         cudaFuncAttributeMaxDynamicSharedMemorySize, SMEMB);
    cudaFuncSetAttribute(prep_merged_kernel,
                         cudaFuncAttributeMaxDynamicSharedMemorySize, SMEM_PREP);

    // --- merged conversions + weight folding (one launch) ---
    prep_merged_kernel<<<NPREP, 256, SMEM_PREP>>>(
        x, a16, Wq, Wk, wB, Wv, Wvc, Wd, Wo, wo,
        bd, bo, bias_o, bv, bvc, bveff);

    // --- unified Q,K,Vc GEMM (fp16 q/k out) ---
    gemm_qkv_kernel<<<dim3(NB / 128, GM / 256), 256, SMEMB>>>(
        a16, wB, bq, bk, bveff, q16, k16, vch);

    // --- compress + rope for q,k (single launch; q pre-scaled) ---
    compress_kernel<<<dim3(L / 32, B * H, 2), 256>>>(
        q16, k16, Wqc, Wkc, bqc, bkc, qch, kch, cosT, sinT);

    // --- attention (128 queries/block, double-buffered) ---
    attn_kernel<<<dim3(L / 128, B * H), 256>>>(qch, kch, vch, ao);

    // --- decompress+output projection folded ---
    gemm_out_kernel<<<dim3(D / 128, GM / 256), 256, SMEMB>>>(
        ao, wo, bias_o, out);
}